// round 7
// baseline (speedup 1.0000x reference)
#include <cuda_runtime.h>
#include <math.h>
#include <stdint.h>

#define NROWS 4096
#define DIMH  1024
#define DIN2  2048

// ---------------- helpers ----------------
__device__ __forceinline__ float srelu(float x){
    float r = fmaxf(x, 0.0f);
    if (r < 0.1f){ float r2 = r*r; return (0.2f*r*r2 - r2*r2) * 500.0f; }
    return x - 0.05f;
}
__device__ __forceinline__ float softplusf(float x){
    return fmaxf(x, 0.0f) + log1pf(expf(-fabsf(x)));
}
__device__ __forceinline__ void tf32split(float x, float& h, float& l){
    uint32_t hb; asm("cvt.rna.tf32.f32 %0, %1;" : "=r"(hb) : "f"(x));
    h = __uint_as_float(hb);
    uint32_t lb; asm("cvt.rna.tf32.f32 %0, %1;" : "=r"(lb) : "f"(x - h));
    l = __uint_as_float(lb);
}

// ---------------- scratch (device globals) ----------------
__device__ float g_Pt_h  [DIMH*DIMH],  g_Pt_l  [DIMH*DIMH];
__device__ float g_PtSc_h[DIMH*DIMH],  g_PtSc_l[DIMH*DIMH];
__device__ float g_Lm_h  [DIMH*DIMH],  g_Lm_l  [DIMH*DIMH];
__device__ float g_Hu_h  [NROWS*DIMH], g_Hu_l  [NROWS*DIMH];
__device__ float g_st_h  [NROWS*DIN2], g_st_l  [NROWS*DIN2];
__device__ float g_sx_h  [NROWS*DIN2];
__device__ float g_W1_h  [512*DIN2],   g_W1_l  [512*DIN2];
__device__ float g_W2_h  [512*512],    g_W2_l  [512*512];
__device__ float g_W3_h  [DIN2*512],   g_W3_l  [DIN2*512];
__device__ float g_icW_h [128*DIN2];
__device__ float g_H1_h  [NROWS*512],  g_H1_l  [NROWS*512];
__device__ float g_H2_h  [NROWS*512],  g_H2_l  [NROWS*512];
__device__ float g_G1    [NROWS*DIMH];
__device__ float g_CT    [NROWS*DIN2];
__device__ float g_Z01   [NROWS*128];
__device__ float g_Z2    [NROWS*64];
__device__ float g_spU0  [64*64];
__device__ float g_spU1  [64];
__device__ float g_cb01  [128];
__device__ float g_z0    [1];

// ---------------- P transpose + eig scale + tf32 split ----------------
__global__ void transposePK(const float* __restrict__ P, const float* __restrict__ t){
    __shared__ float tile[32][33];
    int c0 = blockIdx.x*32, r0 = blockIdx.y*32;
    int x = threadIdx.x, y = threadIdx.y;
    float s = 2.0f * sinf(t[0]);
    #pragma unroll
    for (int i=0;i<32;i+=8)
        tile[y+i][x] = P[(size_t)(r0+y+i)*DIMH + c0 + x];
    __syncthreads();
    #pragma unroll
    for (int i=0;i<32;i+=8){
        int c = c0 + y + i;
        int r = r0 + x;
        float v = tile[x][y+i];
        float e = (r == 0) ? 0.0f : ((r <= 511) ? (1.0f + s) : (1.0f - s));
        float ev = e * v;
        size_t o = (size_t)c*DIMH + r;
        float h, l;
        tf32split(v,  h, l); g_Pt_h[o]   = h; g_Pt_l[o]   = l;
        tf32split(ev, h, l); g_PtSc_h[o] = h; g_PtSc_l[o] = l;
    }
}

// ---------------- concat icW0/icW1 (tf32-rounded, 1x path) ----------------
__global__ void catIcWK(const float* __restrict__ w0, const float* __restrict__ w1){
    int i = blockIdx.x*256 + threadIdx.x;
    float h, l;
    tf32split(w0[i], h, l); g_icW_h[i] = h;
    tf32split(w1[i], h, l); g_icW_h[64*DIN2+i] = h;
}

// ---------------- generic weight split ----------------
__global__ void splitWK(const float* __restrict__ in, float* __restrict__ hi,
                        float* __restrict__ lo, int n4){
    int i = blockIdx.x*256 + threadIdx.x;
    if (i >= n4) return;
    float4 x = reinterpret_cast<const float4*>(in)[i];
    float4 h, l;
    tf32split(x.x, h.x, l.x); tf32split(x.y, h.y, l.y);
    tf32split(x.z, h.z, l.z); tf32split(x.w, h.w, l.w);
    reinterpret_cast<float4*>(hi)[i] = h;
    reinterpret_cast<float4*>(lo)[i] = l;
}

// ---------------- Hu / st / state splits ----------------
__global__ void huStK(const float* __restrict__ state){
    int idx = blockIdx.x*blockDim.x + threadIdx.x;   // NROWS*512 float4s
    int n = idx >> 9, q = idx & 511;
    const float4* s4 = reinterpret_cast<const float4*>(state);
    float4 x = s4[idx];
    float x0 = state[(n<<11) + (q < 256 ? 0 : DIMH)];
    float4 h, l;
    tf32split(x.x, h.x, l.x); tf32split(x.y, h.y, l.y);
    tf32split(x.z, h.z, l.z); tf32split(x.w, h.w, l.w);
    reinterpret_cast<float4*>(g_sx_h)[idx] = h;
    tf32split(x.x-x0, h.x, l.x); tf32split(x.y-x0, h.y, l.y);
    tf32split(x.z-x0, h.z, l.z); tf32split(x.w-x0, h.w, l.w);
    reinterpret_cast<float4*>(g_st_h)[idx] = h;
    reinterpret_cast<float4*>(g_st_l)[idx] = l;
    if (q < 256){
        float4 u;
        u.x = 1.0f/(1.0f + expf(-10.0f*x.x));
        u.y = 1.0f/(1.0f + expf(-10.0f*x.y));
        u.z = 1.0f/(1.0f + expf(-10.0f*x.z));
        u.w = 1.0f/(1.0f + expf(-10.0f*x.w));
        tf32split(u.x, h.x, l.x); tf32split(u.y, h.y, l.y);
        tf32split(u.z, h.z, l.z); tf32split(u.w, h.w, l.w);
        reinterpret_cast<float4*>(g_Hu_h)[n*256 + q] = h;
        reinterpret_cast<float4*>(g_Hu_l)[n*256 + q] = l;
    }
}

// ---------------- softplus(U), biases, z0 constant ----------------
__global__ void prepIcnnK(const float* __restrict__ icU0, const float* __restrict__ icU1,
                          const float* __restrict__ icb0, const float* __restrict__ icb1,
                          const float* __restrict__ icb2){
    int tid = threadIdx.x;
    for (int i = tid; i < 64*64; i += blockDim.x) g_spU0[i] = softplusf(icU0[i]);
    if (tid < 64){
        g_spU1[tid]     = softplusf(icU1[tid]);
        g_cb01[tid]     = icb0[tid];
        g_cb01[64+tid]  = icb1[tid];
    }
    __syncthreads();
    __shared__ float z0a[64], z0b[64];
    if (tid < 64) z0a[tid] = srelu(icb0[tid]);
    __syncthreads();
    if (tid < 64){
        float s = icb1[tid];
        #pragma unroll 8
        for (int j=0;j<64;j++) s += g_spU0[tid*64+j]*z0a[j];
        z0b[tid] = srelu(s);
    }
    __syncthreads();
    if (tid == 0){
        float s = icb2[0];
        for (int j=0;j<64;j++) s += g_spU1[j]*z0b[j];
        g_z0[0] = srelu(s);
    }
}

// ---------------- z2 ----------------
__global__ void z2K(){
    __shared__ float sUT[64*64];
    __shared__ float z1s[4][64];
    int t = threadIdx.x;
    for (int i = t; i < 4096; i += 256){
        int j = i >> 6, k = i & 63;
        sUT[i] = g_spU0[k*64 + j];
    }
    int r = t >> 6, k = t & 63;
    int n = blockIdx.x*4 + r;
    z1s[r][k] = srelu(g_Z01[n*128 + k]);
    __syncthreads();
    float s = g_Z01[n*128 + 64 + k];
    #pragma unroll 8
    for (int j=0;j<64;j++) s += sUT[j*64 + k]*z1s[r][j];
    g_Z2[n*64 + k] = srelu(s);
}

// ---------------- final assembly ----------------
__global__ void finalK(const float* __restrict__ state, const float* __restrict__ icW2,
                       const float* __restrict__ icb2, float* __restrict__ out){
    int n = blockIdx.x;
    int tid = threadIdx.x;
    const float* srow = state + (size_t)n*DIN2;
    const float4* srow4 = reinterpret_cast<const float4*>(srow);
    const float4* icW24 = reinterpret_cast<const float4*>(icW2);
    const float4* CT4   = reinterpret_cast<const float4*>(g_CT + (size_t)n*DIN2);

    float x0u = srow[0], x0v = srow[DIMH];

    float dot = 0.0f, ss = 0.0f;
    #pragma unroll
    for (int it=0; it<2; it++){
        int q = tid + it*256;
        float4 x = srow4[q], w = icW24[q];
        dot += w.x*x.x + w.y*x.y + w.z*x.z + w.w*x.w;
        ss  += x.x*x.x + x.y*x.y + x.z*x.z + x.w*x.w;
    }
    #pragma unroll
    for (int o=16;o>0;o>>=1){
        dot += __shfl_down_sync(0xffffffffu, dot, o);
        ss  += __shfl_down_sync(0xffffffffu, ss,  o);
    }
    __shared__ float sd[8], sq[8];
    if ((tid & 31) == 0){ sd[tid>>5] = dot; sq[tid>>5] = ss; }
    __syncthreads();
    if (tid == 0){
        float D = 0.0f, S = 0.0f;
        #pragma unroll
        for (int w=0;w<8;w++){ D += sd[w]; S += sq[w]; }
        float z = icb2[0] + D;
        for (int k=0;k<64;k++) z = fmaf(g_spU1[k], g_Z2[n*64+k], z);
        float z3 = srelu(z);
        out[(size_t)n*2049 + 2048] = srelu(z3 - g_z0[0]) + 0.001f*S;
    }

    #pragma unroll
    for (int it=0; it<2; it++){
        int q = tid + it*256;
        int d = q*4;
        float4 x  = srow4[q];
        float4 ct = CT4[q];
        float x0 = (d < DIMH) ? x0u : x0v;
        float r[4];
        float xv[4] = {x.x, x.y, x.z, x.w};
        float cv[4] = {ct.x, ct.y, ct.z, ct.w};
        if (d < DIMH){
            const float4 v4 = srow4[q + 256];
            const float4 gg = reinterpret_cast<const float4*>(g_G1 + (size_t)n*DIMH)[q];
            float vv[4] = {v4.x, v4.y, v4.z, v4.w};
            float gv[4] = {gg.x, gg.y, gg.z, gg.w};
            #pragma unroll
            for (int e=0;e<4;e++){
                float ux = cv[e]*(xv[e]-x0);
                float ctrl = (ux < 10.0f && ux > -10.0f) ? ux : 0.0f;
                float uu = xv[e];
                r[e] = uu - uu*uu*uu*(1.0f/3.0f) - vv[e] + 1.0f + gv[e] + ctrl;
            }
        } else {
            const float4 u4 = srow4[q - 256];
            float uv[4] = {u4.x, u4.y, u4.z, u4.w};
            #pragma unroll
            for (int e=0;e<4;e++){
                float ux = cv[e]*(xv[e]-x0);
                float ctrl = (ux < 10.0f && ux > -10.0f) ? ux : 0.0f;
                r[e] = 0.2f*(uv[e] + 0.7f - 0.8f*xv[e]) + ctrl;
            }
        }
        float* o = out + (size_t)n*2049 + d;
        o[0]=r[0]; o[1]=r[1]; o[2]=r[2]; o[3]=r[3];
    }
}

// ======== mma.sync TF32 GEMM, splits precomputed in GMEM (no cvt in loop) ========
#define CPASYNC(dst, src) asm volatile("cp.async.cg.shared.global [%0], [%1], 16;\n" :: "r"(dst), "l"(src))
#define CPCOMMIT()        asm volatile("cp.async.commit_group;\n" ::: "memory")
#define CPWAIT(n)         asm volatile("cp.async.wait_group %0;\n" :: "n"(n) : "memory")

__device__ __forceinline__ void ldsm4(uint32_t addr, uint32_t& r0, uint32_t& r1,
                                      uint32_t& r2, uint32_t& r3){
    asm volatile("ldmatrix.sync.aligned.m8n8.x4.shared.b16 {%0,%1,%2,%3}, [%4];"
                 : "=r"(r0), "=r"(r1), "=r"(r2), "=r"(r3) : "r"(addr));
}
__device__ __forceinline__ void mma_tf32(float* d, const uint32_t* a4,
                                         uint32_t b0, uint32_t b1){
    asm volatile("mma.sync.aligned.m16n8k8.row.col.f32.tf32.tf32.f32 "
                 "{%0,%1,%2,%3}, {%4,%5,%6,%7}, {%8,%9}, {%0,%1,%2,%3};"
                 : "+f"(d[0]), "+f"(d[1]), "+f"(d[2]), "+f"(d[3])
                 : "r"(a4[0]), "r"(a4[2]), "r"(a4[1]), "r"(a4[3]),
                   "r"(b0), "r"(b1));
}

// C[M,N] = A@Bt^T. NSPL=3: 3xTF32 from (Ah,Al,Bh,Bl). NSPL=1: plain tf32 (Ah,Bh).
// TANH: tanh epilogue. SOUT: also write tf32-split (C=hi, Cl=lo).
template<int BM, int BN, int STAGES, int NSPL, int TANH, int SOUT>
__global__ __launch_bounds__(256)
void mmaGemm(int M, int N, int K,
             const float* __restrict__ Ah, const float* __restrict__ Al,
             const float* __restrict__ Bh, const float* __restrict__ Bl,
             const float* __restrict__ bias,
             float* __restrict__ C, float* __restrict__ Cl){
    constexpr int BK  = 16;
    constexpr int LDS = BK + 4;          // 80B row stride
    constexpr int TPS = (NSPL == 3) ? 2 : 1;
    constexpr int WARPS_M = BM/32;
    constexpr int WARPS_N = 8/WARPS_M;
    constexpr int WN = BN/WARPS_N;
    constexpr int NP = WN/16;
    constexpr int STG_BYTES = (BM + BN)*TPS*LDS*4;
    constexpr int offAl = BM*LDS*4;
    constexpr int offBh = BM*LDS*4*TPS;
    constexpr int offBl = offBh + BN*LDS*4;

    extern __shared__ __align__(16) float smem[];

    const int tid  = threadIdx.x;
    const int warp = tid >> 5, lane = tid & 31;
    const int wm = (warp % WARPS_M)*32;
    const int wn = (warp / WARPS_M)*WN;
    const int bm = blockIdx.y*BM, bn = blockIdx.x*BN;

    const int lrow   = ((lane>>4)&1)*8 + (lane&7);
    const int lcol16 = ((lane>>3)&1)*16;

    float acc[2][2*NP][4];
    #pragma unroll
    for (int i=0;i<2;i++)
        #pragma unroll
        for (int j=0;j<2*NP;j++)
            #pragma unroll
            for (int q=0;q<4;q++) acc[i][j][q] = 0.0f;

    uint32_t sBase = (uint32_t)__cvta_generic_to_shared(smem);

    auto loadTile = [&](int buf, int k0){
        uint32_t st = sBase + buf*STG_BYTES;
        #pragma unroll
        for (int i=0;i<(BM*4)/256;i++){
            int L = tid + i*256;
            int r = L>>2, s = L&3;
            CPASYNC(st + (r*LDS + s*4)*4, Ah + (size_t)(bm+r)*K + k0 + s*4);
            if (NSPL == 3)
                CPASYNC(st + offAl + (r*LDS + s*4)*4, Al + (size_t)(bm+r)*K + k0 + s*4);
        }
        #pragma unroll
        for (int i=0;i<(BN*4)/256;i++){
            int L = tid + i*256;
            int r = L>>2, s = L&3;
            CPASYNC(st + offBh + (r*LDS + s*4)*4, Bh + (size_t)(bn+r)*K + k0 + s*4);
            if (NSPL == 3)
                CPASYNC(st + offBl + (r*LDS + s*4)*4, Bl + (size_t)(bn+r)*K + k0 + s*4);
        }
        CPCOMMIT();
    };

    const int nk = K / BK;
    #pragma unroll
    for (int p=0; p<STAGES-1; p++){
        if (p < nk) loadTile(p, p*BK); else CPCOMMIT();
    }

    for (int ck = 0; ck < nk; ck++){
        CPWAIT(STAGES-2);
        __syncthreads();

        int nxt = ck + STAGES - 1;
        if (nxt < nk) loadTile(nxt % STAGES, nxt*BK); else CPCOMMIT();

        uint32_t st = sBase + (ck % STAGES)*STG_BYTES;
        #pragma unroll
        for (int s=0; s<2; s++){
            uint32_t bhi[NP][4], blo[NP][4];
            #pragma unroll
            for (int p=0; p<NP; p++){
                uint32_t boff = (uint32_t)((wn + p*16 + lrow)*LDS*4) + lcol16 + s*32;
                ldsm4(st + offBh + boff, bhi[p][0], bhi[p][1], bhi[p][2], bhi[p][3]);
                if (NSPL == 3)
                    ldsm4(st + offBl + boff, blo[p][0], blo[p][1], blo[p][2], blo[p][3]);
            }
            #pragma unroll
            for (int mt=0; mt<2; mt++){
                uint32_t aoff = (uint32_t)((wm + mt*16 + lrow)*LDS*4) + lcol16 + s*32;
                uint32_t ahi[4], alo[4];
                ldsm4(st + aoff, ahi[0], ahi[1], ahi[2], ahi[3]);
                if (NSPL == 3)
                    ldsm4(st + offAl + aoff, alo[0], alo[1], alo[2], alo[3]);
                #pragma unroll
                for (int p=0; p<NP; p++){
                    mma_tf32(acc[mt][2*p+0], ahi, bhi[p][0], bhi[p][1]);
                    mma_tf32(acc[mt][2*p+1], ahi, bhi[p][2], bhi[p][3]);
                    if (NSPL == 3){
                        mma_tf32(acc[mt][2*p+0], alo, bhi[p][0], bhi[p][1]);
                        mma_tf32(acc[mt][2*p+1], alo, bhi[p][2], bhi[p][3]);
                        mma_tf32(acc[mt][2*p+0], ahi, blo[p][0], blo[p][1]);
                        mma_tf32(acc[mt][2*p+1], ahi, blo[p][2], blo[p][3]);
                    }
                }
            }
        }
        __syncthreads();
    }

    const int tg = lane & 3, g = lane >> 2;
    #pragma unroll
    for (int mt=0; mt<2; mt++){
        #pragma unroll
        for (int nt=0; nt<2*NP; nt++){
            int row = bm + wm + mt*16 + g;
            int col = bn + wn + nt*8 + tg*2;
            float v0 = acc[mt][nt][0], v1 = acc[mt][nt][1];
            float v2 = acc[mt][nt][2], v3 = acc[mt][nt][3];
            if (bias){
                float b0v = bias[col], b1v = bias[col+1];
                v0 += b0v; v1 += b1v; v2 += b0v; v3 += b1v;
            }
            if (TANH){ v0 = tanhf(v0); v1 = tanhf(v1); v2 = tanhf(v2); v3 = tanhf(v3); }
            if (SOUT){
                float h0,l0,h1,l1,h2,l2,h3,l3;
                tf32split(v0,h0,l0); tf32split(v1,h1,l1);
                tf32split(v2,h2,l2); tf32split(v3,h3,l3);
                *reinterpret_cast<float2*>(C  + (size_t)row*N + col)     = make_float2(h0, h1);
                *reinterpret_cast<float2*>(C  + (size_t)(row+8)*N + col) = make_float2(h2, h3);
                *reinterpret_cast<float2*>(Cl + (size_t)row*N + col)     = make_float2(l0, l1);
                *reinterpret_cast<float2*>(Cl + (size_t)(row+8)*N + col) = make_float2(l2, l3);
            } else {
                *reinterpret_cast<float2*>(C + (size_t)row*N + col)     = make_float2(v0, v1);
                *reinterpret_cast<float2*>(C + (size_t)(row+8)*N + col) = make_float2(v2, v3);
            }
        }
    }
}

// ---------------- host ----------------
extern "C" void kernel_launch(void* const* d_in, const int* in_sizes, int n_in,
                              void* d_out, int out_size){
    const float* state = (const float*)d_in[0];
    const float* t     = (const float*)d_in[1];
    const float* P     = (const float*)d_in[2];
    const float* W1    = (const float*)d_in[3];
    const float* b1    = (const float*)d_in[4];
    const float* W2    = (const float*)d_in[5];
    const float* b2    = (const float*)d_in[6];
    const float* W3    = (const float*)d_in[7];
    const float* b3    = (const float*)d_in[8];
    const float* icW0  = (const float*)d_in[9];
    const float* icb0  = (const float*)d_in[10];
    const float* icW1  = (const float*)d_in[11];
    const float* icb1  = (const float*)d_in[12];
    const float* icW2  = (const float*)d_in[13];
    const float* icb2  = (const float*)d_in[14];
    const float* icU0  = (const float*)d_in[15];
    const float* icU1  = (const float*)d_in[16];
    float* out = (float*)d_out;

    float *Pt_h,*Pt_l,*PtSc_h,*PtSc_l,*Lm_h,*Lm_l,*Hu_h,*Hu_l,*st_h,*st_l,*sx_h;
    float *W1_h,*W1_l,*W2_h,*W2_l,*W3_h,*W3_l,*icW_h,*H1_h,*H1_l,*H2_h,*H2_l;
    float *G1,*CT,*Z01,*cb01;
    cudaGetSymbolAddress((void**)&Pt_h,   g_Pt_h);   cudaGetSymbolAddress((void**)&Pt_l,   g_Pt_l);
    cudaGetSymbolAddress((void**)&PtSc_h, g_PtSc_h); cudaGetSymbolAddress((void**)&PtSc_l, g_PtSc_l);
    cudaGetSymbolAddress((void**)&Lm_h,   g_Lm_h);   cudaGetSymbolAddress((void**)&Lm_l,   g_Lm_l);
    cudaGetSymbolAddress((void**)&Hu_h,   g_Hu_h);   cudaGetSymbolAddress((void**)&Hu_l,   g_Hu_l);
    cudaGetSymbolAddress((void**)&st_h,   g_st_h);   cudaGetSymbolAddress((void**)&st_l,   g_st_l);
    cudaGetSymbolAddress((void**)&sx_h,   g_sx_h);
    cudaGetSymbolAddress((void**)&W1_h,   g_W1_h);   cudaGetSymbolAddress((void**)&W1_l,   g_W1_l);
    cudaGetSymbolAddress((void**)&W2_h,   g_W2_h);   cudaGetSymbolAddress((void**)&W2_l,   g_W2_l);
    cudaGetSymbolAddress((void**)&W3_h,   g_W3_h);   cudaGetSymbolAddress((void**)&W3_l,   g_W3_l);
    cudaGetSymbolAddress((void**)&icW_h,  g_icW_h);
    cudaGetSymbolAddress((void**)&H1_h,   g_H1_h);   cudaGetSymbolAddress((void**)&H1_l,   g_H1_l);
    cudaGetSymbolAddress((void**)&H2_h,   g_H2_h);   cudaGetSymbolAddress((void**)&H2_l,   g_H2_l);
    cudaGetSymbolAddress((void**)&G1,  g_G1);
    cudaGetSymbolAddress((void**)&CT,  g_CT);
    cudaGetSymbolAddress((void**)&Z01, g_Z01);
    cudaGetSymbolAddress((void**)&cb01,g_cb01);

    constexpr int LDS = 20;
    const int smLm  = 3*(64 +128)*2*LDS*4;    // 92160
    const int sm128 = 3*(128+128)*2*LDS*4;    // 122880
    const int smZ   = 4*(64 + 64)*1*LDS*4;    // 40960
    cudaFuncSetAttribute((const void*)mmaGemm<64,128,3,3,0,1>, cudaFuncAttributeMaxDynamicSharedMemorySize, smLm);
    cudaFuncSetAttribute((const void*)mmaGemm<128,128,3,3,0,0>, cudaFuncAttributeMaxDynamicSharedMemorySize, sm128);
    cudaFuncSetAttribute((const void*)mmaGemm<128,128,3,3,1,1>, cudaFuncAttributeMaxDynamicSharedMemorySize, sm128);
    cudaFuncSetAttribute((const void*)mmaGemm<64,64,4,1,0,0>,  cudaFuncAttributeMaxDynamicSharedMemorySize, smZ);

    transposePK<<<dim3(32,32), dim3(32,8)>>>(P, t);
    catIcWK<<<(64*DIN2)/256, 256>>>(icW0, icW1);
    splitWK<<<(512*DIN2/4+255)/256, 256>>>(W1, W1_h, W1_l, 512*DIN2/4);
    splitWK<<<(512*512 /4+255)/256, 256>>>(W2, W2_h, W2_l, 512*512/4);
    splitWK<<<(DIN2*512/4+255)/256, 256>>>(W3, W3_h, W3_l, DIN2*512/4);
    prepIcnnK<<<1, 256>>>(icU0, icU1, icb0, icb1, icb2);
    huStK<<<(NROWS*512)/256, 256>>>(state);

    // Lm = PtSc @ Pt^T  (1024x1024x1024) -> split output
    mmaGemm<64,128,3,3,0,1><<<dim3(8,16), 256, smLm>>>(1024, 1024, 1024, PtSc_h, PtSc_l, Pt_h, Pt_l, nullptr, Lm_h, Lm_l);
    // G1 = Hu @ Lm (symmetric)  (4096x1024x1024)
    mmaGemm<128,128,3,3,0,0><<<dim3(8,32), 256, sm128>>>(NROWS, 1024, 1024, Hu_h, Hu_l, Lm_h, Lm_l, nullptr, G1, nullptr);
    // H1 = tanh(st @ W1^T + b1) (4096x512x2048) -> split
    mmaGemm<128,128,3,3,1,1><<<dim3(4,32), 256, sm128>>>(NROWS, 512, 2048, st_h, st_l, W1_h, W1_l, b1, H1_h, H1_l);
    // H2 = tanh(H1 @ W2^T + b2) (4096x512x512) -> split
    mmaGemm<128,128,3,3,1,1><<<dim3(4,32), 256, sm128>>>(NROWS, 512, 512, H1_h, H1_l, W2_h, W2_l, b2, H2_h, H2_l);
    // CT = H2 @ W3^T + b3       (4096x2048x512)
    mmaGemm<128,128,3,3,0,0><<<dim3(16,32), 256, sm128>>>(NROWS, 2048, 512, H2_h, H2_l, W3_h, W3_l, b3, CT, nullptr);
    // Z01 = state @ icW^T + cb01 (4096x128x2048), 1x tf32 (error only touches V column)
    mmaGemm<64,64,4,1,0,0><<<dim3(2,64), 256, smZ>>>(NROWS, 128, 2048, sx_h, nullptr, icW_h, nullptr, cb01, Z01, nullptr);

    z2K<<<NROWS/4, 256>>>();
    finalK<<<NROWS, 256>>>(state, icW2, icb2, out);
}

// round 9
// speedup vs baseline: 1.7031x; 1.7031x over previous
#include <cuda_runtime.h>
#include <cuda_bf16.h>
#include <math.h>
#include <stdint.h>

#define NROWS 4096
#define DIMH  1024
#define DIN2  2048

typedef __nv_bfloat16 bf16;

// ---------------- helpers ----------------
__device__ __forceinline__ float srelu(float x){
    float r = fmaxf(x, 0.0f);
    if (r < 0.1f){ float r2 = r*r; return (0.2f*r*r2 - r2*r2) * 500.0f; }
    return x - 0.05f;
}
__device__ __forceinline__ float softplusf(float x){
    return fmaxf(x, 0.0f) + log1pf(expf(-fabsf(x)));
}
__device__ __forceinline__ void bfsplit(float x, bf16& h, bf16& l){
    h = __float2bfloat16_rn(x);
    l = __float2bfloat16_rn(x - __bfloat162float(h));
}

// ---------------- scratch (device globals) ----------------
__device__ bf16  g_Pt_h  [DIMH*DIMH],  g_Pt_l  [DIMH*DIMH];
__device__ bf16  g_PtSc_h[DIMH*DIMH],  g_PtSc_l[DIMH*DIMH];
__device__ bf16  g_Lm_h  [DIMH*DIMH],  g_Lm_l  [DIMH*DIMH];
__device__ bf16  g_Hu_h  [NROWS*DIMH], g_Hu_l  [NROWS*DIMH];
__device__ bf16  g_st_h  [NROWS*DIN2], g_st_l  [NROWS*DIN2];
__device__ bf16  g_sx_h  [NROWS*DIN2], g_sx_l  [NROWS*DIN2];
__device__ bf16  g_W1_h  [512*DIN2],   g_W1_l  [512*DIN2];
__device__ bf16  g_W2_h  [512*512],    g_W2_l  [512*512];
__device__ bf16  g_W3_h  [DIN2*512],   g_W3_l  [DIN2*512];
__device__ bf16  g_icW_h [128*DIN2],   g_icW_l [128*DIN2];
__device__ bf16  g_H1_h  [NROWS*512],  g_H1_l  [NROWS*512];
__device__ bf16  g_H2_h  [NROWS*512],  g_H2_l  [NROWS*512];
__device__ float g_G1    [NROWS*DIMH];
__device__ float g_CT    [NROWS*DIN2];
__device__ float g_Z01   [NROWS*128];
__device__ float g_Z2    [NROWS*64];
__device__ float g_spU0  [64*64];
__device__ float g_spU1  [64];
__device__ float g_cb01  [128];
__device__ float g_z0    [1];

// ---------------- P transpose + eig scale + bf16 split ----------------
__global__ void transposePK(const float* __restrict__ P, const float* __restrict__ t){
    __shared__ float tile[32][33];
    int c0 = blockIdx.x*32, r0 = blockIdx.y*32;
    int x = threadIdx.x, y = threadIdx.y;
    float s = 2.0f * sinf(t[0]);
    #pragma unroll
    for (int i=0;i<32;i+=8)
        tile[y+i][x] = P[(size_t)(r0+y+i)*DIMH + c0 + x];
    __syncthreads();
    #pragma unroll
    for (int i=0;i<32;i+=8){
        int c = c0 + y + i;
        int r = r0 + x;
        float v = tile[x][y+i];
        float e = (r == 0) ? 0.0f : ((r <= 511) ? (1.0f + s) : (1.0f - s));
        float ev = e * v;
        size_t o = (size_t)c*DIMH + r;
        bf16 h, l;
        bfsplit(v,  h, l); g_Pt_h[o]   = h; g_Pt_l[o]   = l;
        bfsplit(ev, h, l); g_PtSc_h[o] = h; g_PtSc_l[o] = l;
    }
}

// ---------------- concat icW0/icW1 + split ----------------
__global__ void catIcWK(const float* __restrict__ w0, const float* __restrict__ w1){
    int i = blockIdx.x*256 + threadIdx.x;
    bf16 h, l;
    bfsplit(w0[i], h, l); g_icW_h[i] = h; g_icW_l[i] = l;
    bfsplit(w1[i], h, l); g_icW_h[64*DIN2+i] = h; g_icW_l[64*DIN2+i] = l;
}

// ---------------- generic weight split ----------------
__global__ void splitWK(const float* __restrict__ in, bf16* __restrict__ hi,
                        bf16* __restrict__ lo, int n4){
    int i = blockIdx.x*256 + threadIdx.x;
    if (i >= n4) return;
    float4 x = reinterpret_cast<const float4*>(in)[i];
    bf16 h0,l0,h1,l1,h2,l2,h3,l3;
    bfsplit(x.x,h0,l0); bfsplit(x.y,h1,l1); bfsplit(x.z,h2,l2); bfsplit(x.w,h3,l3);
    reinterpret_cast<__nv_bfloat162*>(hi)[i*2+0] = __halves2bfloat162(h0,h1);
    reinterpret_cast<__nv_bfloat162*>(hi)[i*2+1] = __halves2bfloat162(h2,h3);
    reinterpret_cast<__nv_bfloat162*>(lo)[i*2+0] = __halves2bfloat162(l0,l1);
    reinterpret_cast<__nv_bfloat162*>(lo)[i*2+1] = __halves2bfloat162(l2,l3);
}

// ---------------- Hu / st / state splits ----------------
__global__ void huStK(const float* __restrict__ state){
    int idx = blockIdx.x*blockDim.x + threadIdx.x;   // NROWS*512 float4s
    int n = idx >> 9, q = idx & 511;
    const float4* s4 = reinterpret_cast<const float4*>(state);
    float4 x = s4[idx];
    float x0 = state[(n<<11) + (q < 256 ? 0 : DIMH)];
    bf16 h0,l0,h1,l1,h2,l2,h3,l3;

    bfsplit(x.x,h0,l0); bfsplit(x.y,h1,l1); bfsplit(x.z,h2,l2); bfsplit(x.w,h3,l3);
    reinterpret_cast<__nv_bfloat162*>(g_sx_h)[idx*2+0] = __halves2bfloat162(h0,h1);
    reinterpret_cast<__nv_bfloat162*>(g_sx_h)[idx*2+1] = __halves2bfloat162(h2,h3);
    reinterpret_cast<__nv_bfloat162*>(g_sx_l)[idx*2+0] = __halves2bfloat162(l0,l1);
    reinterpret_cast<__nv_bfloat162*>(g_sx_l)[idx*2+1] = __halves2bfloat162(l2,l3);

    bfsplit(x.x-x0,h0,l0); bfsplit(x.y-x0,h1,l1); bfsplit(x.z-x0,h2,l2); bfsplit(x.w-x0,h3,l3);
    reinterpret_cast<__nv_bfloat162*>(g_st_h)[idx*2+0] = __halves2bfloat162(h0,h1);
    reinterpret_cast<__nv_bfloat162*>(g_st_h)[idx*2+1] = __halves2bfloat162(h2,h3);
    reinterpret_cast<__nv_bfloat162*>(g_st_l)[idx*2+0] = __halves2bfloat162(l0,l1);
    reinterpret_cast<__nv_bfloat162*>(g_st_l)[idx*2+1] = __halves2bfloat162(l2,l3);

    if (q < 256){
        float ux = 1.0f/(1.0f + expf(-10.0f*x.x));
        float uy = 1.0f/(1.0f + expf(-10.0f*x.y));
        float uz = 1.0f/(1.0f + expf(-10.0f*x.z));
        float uw = 1.0f/(1.0f + expf(-10.0f*x.w));
        bfsplit(ux,h0,l0); bfsplit(uy,h1,l1); bfsplit(uz,h2,l2); bfsplit(uw,h3,l3);
        int o = n*256 + q;
        reinterpret_cast<__nv_bfloat162*>(g_Hu_h)[o*2+0] = __halves2bfloat162(h0,h1);
        reinterpret_cast<__nv_bfloat162*>(g_Hu_h)[o*2+1] = __halves2bfloat162(h2,h3);
        reinterpret_cast<__nv_bfloat162*>(g_Hu_l)[o*2+0] = __halves2bfloat162(l0,l1);
        reinterpret_cast<__nv_bfloat162*>(g_Hu_l)[o*2+1] = __halves2bfloat162(l2,l3);
    }
}

// ---------------- softplus(U), biases, z0 constant ----------------
__global__ void prepIcnnK(const float* __restrict__ icU0, const float* __restrict__ icU1,
                          const float* __restrict__ icb0, const float* __restrict__ icb1,
                          const float* __restrict__ icb2){
    int tid = threadIdx.x;
    for (int i = tid; i < 64*64; i += blockDim.x) g_spU0[i] = softplusf(icU0[i]);
    if (tid < 64){
        g_spU1[tid]     = softplusf(icU1[tid]);
        g_cb01[tid]     = icb0[tid];
        g_cb01[64+tid]  = icb1[tid];
    }
    __syncthreads();
    __shared__ float z0a[64], z0b[64];
    if (tid < 64) z0a[tid] = srelu(icb0[tid]);
    __syncthreads();
    if (tid < 64){
        float s = icb1[tid];
        #pragma unroll 8
        for (int j=0;j<64;j++) s += g_spU0[tid*64+j]*z0a[j];
        z0b[tid] = srelu(s);
    }
    __syncthreads();
    if (tid == 0){
        float s = icb2[0];
        for (int j=0;j<64;j++) s += g_spU1[j]*z0b[j];
        g_z0[0] = srelu(s);
    }
}

// ---------------- z2 ----------------
__global__ void z2K(){
    __shared__ float sUT[64*64];
    __shared__ float z1s[4][64];
    int t = threadIdx.x;
    for (int i = t; i < 4096; i += 256){
        int j = i >> 6, k = i & 63;
        sUT[i] = g_spU0[k*64 + j];
    }
    int r = t >> 6, k = t & 63;
    int n = blockIdx.x*4 + r;
    z1s[r][k] = srelu(g_Z01[n*128 + k]);
    __syncthreads();
    float s = g_Z01[n*128 + 64 + k];
    #pragma unroll 8
    for (int j=0;j<64;j++) s += sUT[j*64 + k]*z1s[r][j];
    g_Z2[n*64 + k] = srelu(s);
}

// ---------------- final assembly ----------------
__global__ void finalK(const float* __restrict__ state, const float* __restrict__ icW2,
                       const float* __restrict__ icb2, float* __restrict__ out){
    int n = blockIdx.x;
    int tid = threadIdx.x;
    const float* srow = state + (size_t)n*DIN2;
    const float4* srow4 = reinterpret_cast<const float4*>(srow);
    const float4* icW24 = reinterpret_cast<const float4*>(icW2);
    const float4* CT4   = reinterpret_cast<const float4*>(g_CT + (size_t)n*DIN2);

    float x0u = srow[0], x0v = srow[DIMH];

    float dot = 0.0f, ss = 0.0f;
    #pragma unroll
    for (int it=0; it<2; it++){
        int q = tid + it*256;
        float4 x = srow4[q], w = icW24[q];
        dot += w.x*x.x + w.y*x.y + w.z*x.z + w.w*x.w;
        ss  += x.x*x.x + x.y*x.y + x.z*x.z + x.w*x.w;
    }
    #pragma unroll
    for (int o=16;o>0;o>>=1){
        dot += __shfl_down_sync(0xffffffffu, dot, o);
        ss  += __shfl_down_sync(0xffffffffu, ss,  o);
    }
    __shared__ float sd[8], sq[8];
    if ((tid & 31) == 0){ sd[tid>>5] = dot; sq[tid>>5] = ss; }
    __syncthreads();
    if (tid == 0){
        float D = 0.0f, S = 0.0f;
        #pragma unroll
        for (int w=0;w<8;w++){ D += sd[w]; S += sq[w]; }
        float z = icb2[0] + D;
        for (int k=0;k<64;k++) z = fmaf(g_spU1[k], g_Z2[n*64+k], z);
        float z3 = srelu(z);
        out[(size_t)n*2049 + 2048] = srelu(z3 - g_z0[0]) + 0.001f*S;
    }

    #pragma unroll
    for (int it=0; it<2; it++){
        int q = tid + it*256;
        int d = q*4;
        float4 x  = srow4[q];
        float4 ct = CT4[q];
        float x0 = (d < DIMH) ? x0u : x0v;
        float r[4];
        float xv[4] = {x.x, x.y, x.z, x.w};
        float cv[4] = {ct.x, ct.y, ct.z, ct.w};
        if (d < DIMH){
            const float4 v4 = srow4[q + 256];
            const float4 gg = reinterpret_cast<const float4*>(g_G1 + (size_t)n*DIMH)[q];
            float vv[4] = {v4.x, v4.y, v4.z, v4.w};
            float gv[4] = {gg.x, gg.y, gg.z, gg.w};
            #pragma unroll
            for (int e=0;e<4;e++){
                float ux = cv[e]*(xv[e]-x0);
                float ctrl = (ux < 10.0f && ux > -10.0f) ? ux : 0.0f;
                float uu = xv[e];
                r[e] = uu - uu*uu*uu*(1.0f/3.0f) - vv[e] + 1.0f + gv[e] + ctrl;
            }
        } else {
            const float4 u4 = srow4[q - 256];
            float uv[4] = {u4.x, u4.y, u4.z, u4.w};
            #pragma unroll
            for (int e=0;e<4;e++){
                float ux = cv[e]*(xv[e]-x0);
                float ctrl = (ux < 10.0f && ux > -10.0f) ? ux : 0.0f;
                r[e] = 0.2f*(uv[e] + 0.7f - 0.8f*xv[e]) + ctrl;
            }
        }
        float* o = out + (size_t)n*2049 + d;
        o[0]=r[0]; o[1]=r[1]; o[2]=r[2]; o[3]=r[3];
    }
}

// ======== 3xBF16 mma.sync GEMM (split-2 bf16 operands, fp32 accum) ========
#define CPASYNC(dst, src) asm volatile("cp.async.cg.shared.global [%0], [%1], 16;\n" :: "r"(dst), "l"(src))
#define CPCOMMIT()        asm volatile("cp.async.commit_group;\n" ::: "memory")
#define CPWAIT(n)         asm volatile("cp.async.wait_group %0;\n" :: "n"(n) : "memory")

__device__ __forceinline__ void ldsm4(uint32_t addr, uint32_t& r0, uint32_t& r1,
                                      uint32_t& r2, uint32_t& r3){
    asm volatile("ldmatrix.sync.aligned.m8n8.x4.shared.b16 {%0,%1,%2,%3}, [%4];"
                 : "=r"(r0), "=r"(r1), "=r"(r2), "=r"(r3) : "r"(addr));
}
__device__ __forceinline__ void mma_bf16(float* d, const uint32_t* a, uint32_t b0, uint32_t b1){
    asm volatile("mma.sync.aligned.m16n8k16.row.col.f32.bf16.bf16.f32 "
                 "{%0,%1,%2,%3}, {%4,%5,%6,%7}, {%8,%9}, {%0,%1,%2,%3};"
                 : "+f"(d[0]), "+f"(d[1]), "+f"(d[2]), "+f"(d[3])
                 : "r"(a[0]), "r"(a[1]), "r"(a[2]), "r"(a[3]), "r"(b0), "r"(b1));
}

// C[M,N] = (Ah+Al)@(Bh+Bl)^T via hh+lh+hl. BK=32. TANH: tanh epi.
// SOUT=1: write bf16 split (Ch,Cl). SOUT=0: write fp32 Cf.
template<int BM, int BN, int STAGES, int TANH, int SOUT>
__global__ __launch_bounds__(256)
void mmaGemmBF(int M, int N, int K,
               const bf16* __restrict__ Ah, const bf16* __restrict__ Al,
               const bf16* __restrict__ Bh, const bf16* __restrict__ Bl,
               const float* __restrict__ bias,
               float* __restrict__ Cf, bf16* __restrict__ Ch, bf16* __restrict__ Cl){
    constexpr int ROWB = 80;                 // 32 bf16 (64B) + 16B pad
    constexpr int offAl = BM*ROWB;
    constexpr int offBh = 2*BM*ROWB;
    constexpr int offBl = offBh + BN*ROWB;
    constexpr int STG   = 2*(BM+BN)*ROWB;
    constexpr int WARPS_M = BM/32;
    constexpr int WARPS_N = 8/WARPS_M;
    constexpr int WN = BN/WARPS_N;
    constexpr int NP = WN/16;

    extern __shared__ __align__(16) char smem[];

    const int tid  = threadIdx.x;
    const int warp = tid >> 5, lane = tid & 31;
    const int wm = (warp % WARPS_M)*32;
    const int wn = (warp / WARPS_M)*WN;
    const int bm = blockIdx.y*BM, bn = blockIdx.x*BN;

    const int lr  = lane & 15;               // ldmatrix row within 16
    const int lcb = (lane >> 4)*16;          // 16B column half

    float acc[2][2*NP][4];
    #pragma unroll
    for (int i=0;i<2;i++)
        #pragma unroll
        for (int j=0;j<2*NP;j++)
            #pragma unroll
            for (int q=0;q<4;q++) acc[i][j][q] = 0.0f;

    uint32_t sBase = (uint32_t)__cvta_generic_to_shared(smem);

    auto loadTile = [&](int buf, int k0){
        uint32_t st = sBase + buf*STG;
        #pragma unroll
        for (int i=0;i<(BM*4)/256;i++){
            int L = tid + i*256;
            int r = L>>2, c = L&3;
            CPASYNC(st + r*ROWB + c*16,         Ah + (size_t)(bm+r)*K + k0 + c*8);
            CPASYNC(st + offAl + r*ROWB + c*16, Al + (size_t)(bm+r)*K + k0 + c*8);
        }
        #pragma unroll
        for (int i=0;i<(BN*4)/256;i++){
            int L = tid + i*256;
            int r = L>>2, c = L&3;
            CPASYNC(st + offBh + r*ROWB + c*16, Bh + (size_t)(bn+r)*K + k0 + c*8);
            CPASYNC(st + offBl + r*ROWB + c*16, Bl + (size_t)(bn+r)*K + k0 + c*8);
        }
        CPCOMMIT();
    };

    const int nk = K / 32;
    #pragma unroll
    for (int p=0; p<STAGES-1; p++){
        if (p < nk) loadTile(p, p*32); else CPCOMMIT();
    }

    for (int ck = 0; ck < nk; ck++){
        CPWAIT(STAGES-2);
        __syncthreads();

        int nxt = ck + STAGES - 1;
        if (nxt < nk) loadTile(nxt % STAGES, nxt*32); else CPCOMMIT();

        uint32_t st = sBase + (ck % STAGES)*STG;
        #pragma unroll
        for (int ks=0; ks<2; ks++){                      // two k16 steps
            uint32_t bh[NP][4], bl[NP][4];
            #pragma unroll
            for (int p=0; p<NP; p++){
                uint32_t boff = (uint32_t)((wn + p*16 + lr)*ROWB) + ks*32 + lcb;
                ldsm4(st + offBh + boff, bh[p][0], bh[p][1], bh[p][2], bh[p][3]);
                ldsm4(st + offBl + boff, bl[p][0], bl[p][1], bl[p][2], bl[p][3]);
            }
            #pragma unroll
            for (int mt=0; mt<2; mt++){
                uint32_t aoff = (uint32_t)((wm + mt*16 + lr)*ROWB) + ks*32 + lcb;
                uint32_t ah[4], al[4];
                ldsm4(st + aoff,        ah[0], ah[1], ah[2], ah[3]);
                ldsm4(st + offAl + aoff, al[0], al[1], al[2], al[3]);
                #pragma unroll
                for (int p=0; p<NP; p++){
                    // n-subtile 0: B regs {r0, r2}; subtile 1: {r1, r3}
                    mma_bf16(acc[mt][2*p+0], ah, bh[p][0], bh[p][2]);
                    mma_bf16(acc[mt][2*p+0], al, bh[p][0], bh[p][2]);
                    mma_bf16(acc[mt][2*p+0], ah, bl[p][0], bl[p][2]);
                    mma_bf16(acc[mt][2*p+1], ah, bh[p][1], bh[p][3]);
                    mma_bf16(acc[mt][2*p+1], al, bh[p][1], bh[p][3]);
                    mma_bf16(acc[mt][2*p+1], ah, bl[p][1], bl[p][3]);
                }
            }
        }
        __syncthreads();
    }

    const int tg = lane & 3, g = lane >> 2;
    #pragma unroll
    for (int mt=0; mt<2; mt++){
        #pragma unroll
        for (int nt=0; nt<2*NP; nt++){
            int p = nt >> 1, nsub = nt & 1;
            int row = bm + wm + mt*16 + g;
            int col = bn + wn + p*16 + nsub*8 + tg*2;
            float v0 = acc[mt][nt][0], v1 = acc[mt][nt][1];
            float v2 = acc[mt][nt][2], v3 = acc[mt][nt][3];
            if (bias){
                float b0v = bias[col], b1v = bias[col+1];
                v0 += b0v; v1 += b1v; v2 += b0v; v3 += b1v;
            }
            if (TANH){ v0 = tanhf(v0); v1 = tanhf(v1); v2 = tanhf(v2); v3 = tanhf(v3); }
            if (SOUT){
                bf16 h0,l0,h1,l1,h2,l2,h3,l3;
                bfsplit(v0,h0,l0); bfsplit(v1,h1,l1);
                bfsplit(v2,h2,l2); bfsplit(v3,h3,l3);
                *reinterpret_cast<__nv_bfloat162*>(Ch + (size_t)row*N + col)     = __halves2bfloat162(h0,h1);
                *reinterpret_cast<__nv_bfloat162*>(Ch + (size_t)(row+8)*N + col) = __halves2bfloat162(h2,h3);
                *reinterpret_cast<__nv_bfloat162*>(Cl + (size_t)row*N + col)     = __halves2bfloat162(l0,l1);
                *reinterpret_cast<__nv_bfloat162*>(Cl + (size_t)(row+8)*N + col) = __halves2bfloat162(l2,l3);
            } else {
                *reinterpret_cast<float2*>(Cf + (size_t)row*N + col)     = make_float2(v0, v1);
                *reinterpret_cast<float2*>(Cf + (size_t)(row+8)*N + col) = make_float2(v2, v3);
            }
        }
    }
}

// ---------------- host ----------------
extern "C" void kernel_launch(void* const* d_in, const int* in_sizes, int n_in,
                              void* d_out, int out_size){
    const float* state = (const float*)d_in[0];
    const float* t     = (const float*)d_in[1];
    const float* P     = (const float*)d_in[2];
    const float* W1    = (const float*)d_in[3];
    const float* b1    = (const float*)d_in[4];
    const float* W2    = (const float*)d_in[5];
    const float* b2    = (const float*)d_in[6];
    const float* W3    = (const float*)d_in[7];
    const float* b3    = (const float*)d_in[8];
    const float* icW0  = (const float*)d_in[9];
    const float* icb0  = (const float*)d_in[10];
    const float* icW1  = (const float*)d_in[11];
    const float* icb1  = (const float*)d_in[12];
    const float* icW2  = (const float*)d_in[13];
    const float* icb2  = (const float*)d_in[14];
    const float* icU0  = (const float*)d_in[15];
    const float* icU1  = (const float*)d_in[16];
    float* out = (float*)d_out;

    bf16 *Pt_h,*Pt_l,*PtSc_h,*PtSc_l,*Lm_h,*Lm_l,*Hu_h,*Hu_l,*st_h,*st_l,*sx_h,*sx_l;
    bf16 *W1_h,*W1_l,*W2_h,*W2_l,*W3_h,*W3_l,*icW_h,*icW_l,*H1_h,*H1_l,*H2_h,*H2_l;
    float *G1,*CT,*Z01,*cb01;
    cudaGetSymbolAddress((void**)&Pt_h,   g_Pt_h);   cudaGetSymbolAddress((void**)&Pt_l,   g_Pt_l);
    cudaGetSymbolAddress((void**)&PtSc_h, g_PtSc_h); cudaGetSymbolAddress((void**)&PtSc_l, g_PtSc_l);
    cudaGetSymbolAddress((void**)&Lm_h,   g_Lm_h);   cudaGetSymbolAddress((void**)&Lm_l,   g_Lm_l);
    cudaGetSymbolAddress((void**)&Hu_h,   g_Hu_h);   cudaGetSymbolAddress((void**)&Hu_l,   g_Hu_l);
    cudaGetSymbolAddress((void**)&st_h,   g_st_h);   cudaGetSymbolAddress((void**)&st_l,   g_st_l);
    cudaGetSymbolAddress((void**)&sx_h,   g_sx_h);   cudaGetSymbolAddress((void**)&sx_l,   g_sx_l);
    cudaGetSymbolAddress((void**)&W1_h,   g_W1_h);   cudaGetSymbolAddress((void**)&W1_l,   g_W1_l);
    cudaGetSymbolAddress((void**)&W2_h,   g_W2_h);   cudaGetSymbolAddress((void**)&W2_l,   g_W2_l);
    cudaGetSymbolAddress((void**)&W3_h,   g_W3_h);   cudaGetSymbolAddress((void**)&W3_l,   g_W3_l);
    cudaGetSymbolAddress((void**)&icW_h,  g_icW_h);  cudaGetSymbolAddress((void**)&icW_l,  g_icW_l);
    cudaGetSymbolAddress((void**)&H1_h,   g_H1_h);   cudaGetSymbolAddress((void**)&H1_l,   g_H1_l);
    cudaGetSymbolAddress((void**)&H2_h,   g_H2_h);   cudaGetSymbolAddress((void**)&H2_l,   g_H2_l);
    cudaGetSymbolAddress((void**)&G1,  g_G1);
    cudaGetSymbolAddress((void**)&CT,  g_CT);
    cudaGetSymbolAddress((void**)&Z01, g_Z01);
    cudaGetSymbolAddress((void**)&cb01,g_cb01);

    const int sm128 = 4*2*(128+128)*80;   // 163840
    const int smLm  = 4*2*( 64+128)*80;   // 122880
    const int smZ   = 4*2*( 64+ 64)*80;   //  81920
    cudaFuncSetAttribute((const void*)mmaGemmBF<64,128,4,0,1>,  cudaFuncAttributeMaxDynamicSharedMemorySize, smLm);
    cudaFuncSetAttribute((const void*)mmaGemmBF<128,128,4,0,0>, cudaFuncAttributeMaxDynamicSharedMemorySize, sm128);
    cudaFuncSetAttribute((const void*)mmaGemmBF<128,128,4,1,1>, cudaFuncAttributeMaxDynamicSharedMemorySize, sm128);
    cudaFuncSetAttribute((const void*)mmaGemmBF<64,64,4,0,0>,   cudaFuncAttributeMaxDynamicSharedMemorySize, smZ);

    transposePK<<<dim3(32,32), dim3(32,8)>>>(P, t);
    catIcWK<<<(64*DIN2)/256, 256>>>(icW0, icW1);
    splitWK<<<(512*DIN2/4+255)/256, 256>>>(W1, W1_h, W1_l, 512*DIN2/4);
    splitWK<<<(512*512 /4+255)/256, 256>>>(W2, W2_h, W2_l, 512*512/4);
    splitWK<<<(DIN2*512/4+255)/256, 256>>>(W3, W3_h, W3_l, DIN2*512/4);
    prepIcnnK<<<1, 256>>>(icU0, icU1, icb0, icb1, icb2);
    huStK<<<(NROWS*512)/256, 256>>>(state);

    // Lm = PtSc @ Pt^T  (1024x1024x1024) -> bf16 split output
    mmaGemmBF<64,128,4,0,1><<<dim3(8,16), 256, smLm>>>(1024, 1024, 1024,
        PtSc_h, PtSc_l, Pt_h, Pt_l, nullptr, nullptr, Lm_h, Lm_l);
    // G1 = Hu @ Lm (symmetric)  (4096x1024x1024) -> fp32
    mmaGemmBF<128,128,4,0,0><<<dim3(8,32), 256, sm128>>>(NROWS, 1024, 1024,
        Hu_h, Hu_l, Lm_h, Lm_l, nullptr, G1, nullptr, nullptr);
    // H1 = tanh(st @ W1^T + b1) (4096x512x2048) -> bf16 split
    mmaGemmBF<128,128,4,1,1><<<dim3(4,32), 256, sm128>>>(NROWS, 512, 2048,
        st_h, st_l, W1_h, W1_l, b1, nullptr, H1_h, H1_l);
    // H2 = tanh(H1 @ W2^T + b2) (4096x512x512) -> bf16 split
    mmaGemmBF<128,128,4,1,1><<<dim3(4,32), 256, sm128>>>(NROWS, 512, 512,
        H1_h, H1_l, W2_h, W2_l, b2, nullptr, H2_h, H2_l);
    // CT = H2 @ W3^T + b3       (4096x2048x512) -> fp32
    mmaGemmBF<128,128,4,0,0><<<dim3(16,32), 256, sm128>>>(NROWS, 2048, 512,
        H2_h, H2_l, W3_h, W3_l, b3, CT, nullptr, nullptr);
    // Z01 = state @ icW^T + cb01 (4096x128x2048) -> fp32
    mmaGemmBF<64,64,4,0,0><<<dim3(2,64), 256, smZ>>>(NROWS, 128, 2048,
        sx_h, sx_l, icW_h, icW_l, cb01, Z01, nullptr, nullptr);

    z2K<<<NROWS/4, 256>>>();
    finalK<<<NROWS, 256>>>(state, icW2, icb2, out);
}

// round 11
// speedup vs baseline: 1.7829x; 1.0468x over previous
#include <cuda_runtime.h>
#include <cuda_bf16.h>
#include <math.h>
#include <stdint.h>

#define NROWS 4096
#define DIMH  1024
#define DIN2  2048

typedef __nv_bfloat16 bf16;

// ---------------- helpers ----------------
__device__ __forceinline__ float srelu(float x){
    float r = fmaxf(x, 0.0f);
    if (r < 0.1f){ float r2 = r*r; return (0.2f*r*r2 - r2*r2) * 500.0f; }
    return x - 0.05f;
}
__device__ __forceinline__ float softplusf(float x){
    return fmaxf(x, 0.0f) + log1pf(expf(-fabsf(x)));
}
__device__ __forceinline__ void bfsplit(float x, bf16& h, bf16& l){
    h = __float2bfloat16_rn(x);
    l = __float2bfloat16_rn(x - __bfloat162float(h));
}

// ---------------- scratch (device globals) ----------------
__device__ bf16  g_Pt_h  [DIMH*DIMH],  g_Pt_l  [DIMH*DIMH];
__device__ bf16  g_PtSc_h[DIMH*DIMH],  g_PtSc_l[DIMH*DIMH];
__device__ bf16  g_Lm_h  [DIMH*DIMH],  g_Lm_l  [DIMH*DIMH];
__device__ bf16  g_Hu_h  [NROWS*DIMH], g_Hu_l  [NROWS*DIMH];
__device__ bf16  g_st_h  [NROWS*DIN2], g_st_l  [NROWS*DIN2];
__device__ bf16  g_sx_h  [NROWS*DIN2], g_sx_l  [NROWS*DIN2];
__device__ bf16  g_W1_h  [512*DIN2],   g_W1_l  [512*DIN2];
__device__ bf16  g_W2_h  [512*512],    g_W2_l  [512*512];
__device__ bf16  g_W3_h  [DIN2*512],   g_W3_l  [DIN2*512];
__device__ bf16  g_icW_h [128*DIN2],   g_icW_l [128*DIN2];
__device__ bf16  g_H1_h  [NROWS*512],  g_H1_l  [NROWS*512];
__device__ bf16  g_H2_h  [NROWS*512],  g_H2_l  [NROWS*512];
__device__ float g_G1    [NROWS*DIMH];
__device__ float g_CT    [NROWS*DIN2];
__device__ float g_Z01   [NROWS*128];
__device__ float g_Z2    [NROWS*64];
__device__ float g_spU0  [64*64];
__device__ float g_spU1  [64];
__device__ float g_cb01  [128];
__device__ float g_z0    [1];

// ---------------- P transpose + eig scale + bf16 split ----------------
__global__ void transposePK(const float* __restrict__ P, const float* __restrict__ t){
    __shared__ float tile[32][33];
    int c0 = blockIdx.x*32, r0 = blockIdx.y*32;
    int x = threadIdx.x, y = threadIdx.y;
    float s = 2.0f * sinf(t[0]);
    #pragma unroll
    for (int i=0;i<32;i+=8)
        tile[y+i][x] = P[(size_t)(r0+y+i)*DIMH + c0 + x];
    __syncthreads();
    #pragma unroll
    for (int i=0;i<32;i+=8){
        int c = c0 + y + i;
        int r = r0 + x;
        float v = tile[x][y+i];
        float e = (r == 0) ? 0.0f : ((r <= 511) ? (1.0f + s) : (1.0f - s));
        float ev = e * v;
        size_t o = (size_t)c*DIMH + r;
        bf16 h, l;
        bfsplit(v,  h, l); g_Pt_h[o]   = h; g_Pt_l[o]   = l;
        bfsplit(ev, h, l); g_PtSc_h[o] = h; g_PtSc_l[o] = l;
    }
}

// ---------------- concat icW0/icW1 + split ----------------
__global__ void catIcWK(const float* __restrict__ w0, const float* __restrict__ w1){
    int i = blockIdx.x*256 + threadIdx.x;
    bf16 h, l;
    bfsplit(w0[i], h, l); g_icW_h[i] = h; g_icW_l[i] = l;
    bfsplit(w1[i], h, l); g_icW_h[64*DIN2+i] = h; g_icW_l[64*DIN2+i] = l;
}

// ---------------- generic weight split ----------------
__global__ void splitWK(const float* __restrict__ in, bf16* __restrict__ hi,
                        bf16* __restrict__ lo, int n4){
    int i = blockIdx.x*256 + threadIdx.x;
    if (i >= n4) return;
    float4 x = reinterpret_cast<const float4*>(in)[i];
    bf16 h0,l0,h1,l1,h2,l2,h3,l3;
    bfsplit(x.x,h0,l0); bfsplit(x.y,h1,l1); bfsplit(x.z,h2,l2); bfsplit(x.w,h3,l3);
    reinterpret_cast<__nv_bfloat162*>(hi)[i*2+0] = __halves2bfloat162(h0,h1);
    reinterpret_cast<__nv_bfloat162*>(hi)[i*2+1] = __halves2bfloat162(h2,h3);
    reinterpret_cast<__nv_bfloat162*>(lo)[i*2+0] = __halves2bfloat162(l0,l1);
    reinterpret_cast<__nv_bfloat162*>(lo)[i*2+1] = __halves2bfloat162(l2,l3);
}

// ---------------- Hu / st / state splits ----------------
__global__ void huStK(const float* __restrict__ state){
    int idx = blockIdx.x*blockDim.x + threadIdx.x;   // NROWS*512 float4s
    int n = idx >> 9, q = idx & 511;
    const float4* s4 = reinterpret_cast<const float4*>(state);
    float4 x = s4[idx];
    float x0 = state[(n<<11) + (q < 256 ? 0 : DIMH)];
    bf16 h0,l0,h1,l1,h2,l2,h3,l3;

    bfsplit(x.x,h0,l0); bfsplit(x.y,h1,l1); bfsplit(x.z,h2,l2); bfsplit(x.w,h3,l3);
    reinterpret_cast<__nv_bfloat162*>(g_sx_h)[idx*2+0] = __halves2bfloat162(h0,h1);
    reinterpret_cast<__nv_bfloat162*>(g_sx_h)[idx*2+1] = __halves2bfloat162(h2,h3);
    reinterpret_cast<__nv_bfloat162*>(g_sx_l)[idx*2+0] = __halves2bfloat162(l0,l1);
    reinterpret_cast<__nv_bfloat162*>(g_sx_l)[idx*2+1] = __halves2bfloat162(l2,l3);

    bfsplit(x.x-x0,h0,l0); bfsplit(x.y-x0,h1,l1); bfsplit(x.z-x0,h2,l2); bfsplit(x.w-x0,h3,l3);
    reinterpret_cast<__nv_bfloat162*>(g_st_h)[idx*2+0] = __halves2bfloat162(h0,h1);
    reinterpret_cast<__nv_bfloat162*>(g_st_h)[idx*2+1] = __halves2bfloat162(h2,h3);
    reinterpret_cast<__nv_bfloat162*>(g_st_l)[idx*2+0] = __halves2bfloat162(l0,l1);
    reinterpret_cast<__nv_bfloat162*>(g_st_l)[idx*2+1] = __halves2bfloat162(l2,l3);

    if (q < 256){
        float ux = 1.0f/(1.0f + expf(-10.0f*x.x));
        float uy = 1.0f/(1.0f + expf(-10.0f*x.y));
        float uz = 1.0f/(1.0f + expf(-10.0f*x.z));
        float uw = 1.0f/(1.0f + expf(-10.0f*x.w));
        bfsplit(ux,h0,l0); bfsplit(uy,h1,l1); bfsplit(uz,h2,l2); bfsplit(uw,h3,l3);
        int o = n*256 + q;
        reinterpret_cast<__nv_bfloat162*>(g_Hu_h)[o*2+0] = __halves2bfloat162(h0,h1);
        reinterpret_cast<__nv_bfloat162*>(g_Hu_h)[o*2+1] = __halves2bfloat162(h2,h3);
        reinterpret_cast<__nv_bfloat162*>(g_Hu_l)[o*2+0] = __halves2bfloat162(l0,l1);
        reinterpret_cast<__nv_bfloat162*>(g_Hu_l)[o*2+1] = __halves2bfloat162(l2,l3);
    }
}

// ---------------- softplus(U), biases, z0 constant ----------------
__global__ void prepIcnnK(const float* __restrict__ icU0, const float* __restrict__ icU1,
                          const float* __restrict__ icb0, const float* __restrict__ icb1,
                          const float* __restrict__ icb2){
    int tid = threadIdx.x;
    for (int i = tid; i < 64*64; i += blockDim.x) g_spU0[i] = softplusf(icU0[i]);
    if (tid < 64){
        g_spU1[tid]     = softplusf(icU1[tid]);
        g_cb01[tid]     = icb0[tid];
        g_cb01[64+tid]  = icb1[tid];
    }
    __syncthreads();
    __shared__ float z0a[64], z0b[64];
    if (tid < 64) z0a[tid] = srelu(icb0[tid]);
    __syncthreads();
    if (tid < 64){
        float s = icb1[tid];
        #pragma unroll 8
        for (int j=0;j<64;j++) s += g_spU0[tid*64+j]*z0a[j];
        z0b[tid] = srelu(s);
    }
    __syncthreads();
    if (tid == 0){
        float s = icb2[0];
        for (int j=0;j<64;j++) s += g_spU1[j]*z0b[j];
        g_z0[0] = srelu(s);
    }
}

// ---------------- z2 ----------------
__global__ void z2K(){
    __shared__ float sUT[64*64];
    __shared__ float z1s[4][64];
    int t = threadIdx.x;
    for (int i = t; i < 4096; i += 256){
        int j = i >> 6, k = i & 63;
        sUT[i] = g_spU0[k*64 + j];
    }
    int r = t >> 6, k = t & 63;
    int n = blockIdx.x*4 + r;
    z1s[r][k] = srelu(g_Z01[n*128 + k]);
    __syncthreads();
    float s = g_Z01[n*128 + 64 + k];
    #pragma unroll 8
    for (int j=0;j<64;j++) s += sUT[j*64 + k]*z1s[r][j];
    g_Z2[n*64 + k] = srelu(s);
}

// ---------------- final assembly ----------------
__global__ void finalK(const float* __restrict__ state, const float* __restrict__ icW2,
                       const float* __restrict__ icb2, float* __restrict__ out){
    int n = blockIdx.x;
    int tid = threadIdx.x;
    const float* srow = state + (size_t)n*DIN2;
    const float4* srow4 = reinterpret_cast<const float4*>(srow);
    const float4* icW24 = reinterpret_cast<const float4*>(icW2);
    const float4* CT4   = reinterpret_cast<const float4*>(g_CT + (size_t)n*DIN2);

    float x0u = srow[0], x0v = srow[DIMH];

    float dot = 0.0f, ss = 0.0f;
    #pragma unroll
    for (int it=0; it<2; it++){
        int q = tid + it*256;
        float4 x = srow4[q], w = icW24[q];
        dot += w.x*x.x + w.y*x.y + w.z*x.z + w.w*x.w;
        ss  += x.x*x.x + x.y*x.y + x.z*x.z + x.w*x.w;
    }
    #pragma unroll
    for (int o=16;o>0;o>>=1){
        dot += __shfl_down_sync(0xffffffffu, dot, o);
        ss  += __shfl_down_sync(0xffffffffu, ss,  o);
    }
    __shared__ float sd[8], sq[8];
    if ((tid & 31) == 0){ sd[tid>>5] = dot; sq[tid>>5] = ss; }
    __syncthreads();
    if (tid == 0){
        float D = 0.0f, S = 0.0f;
        #pragma unroll
        for (int w=0;w<8;w++){ D += sd[w]; S += sq[w]; }
        float z = icb2[0] + D;
        for (int k=0;k<64;k++) z = fmaf(g_spU1[k], g_Z2[n*64+k], z);
        float z3 = srelu(z);
        out[(size_t)n*2049 + 2048] = srelu(z3 - g_z0[0]) + 0.001f*S;
    }

    #pragma unroll
    for (int it=0; it<2; it++){
        int q = tid + it*256;
        int d = q*4;
        float4 x  = srow4[q];
        float4 ct = CT4[q];
        float x0 = (d < DIMH) ? x0u : x0v;
        float r[4];
        float xv[4] = {x.x, x.y, x.z, x.w};
        float cv[4] = {ct.x, ct.y, ct.z, ct.w};
        if (d < DIMH){
            const float4 v4 = srow4[q + 256];
            const float4 gg = reinterpret_cast<const float4*>(g_G1 + (size_t)n*DIMH)[q];
            float vv[4] = {v4.x, v4.y, v4.z, v4.w};
            float gv[4] = {gg.x, gg.y, gg.z, gg.w};
            #pragma unroll
            for (int e=0;e<4;e++){
                float ux = cv[e]*(xv[e]-x0);
                float ctrl = (ux < 10.0f && ux > -10.0f) ? ux : 0.0f;
                float uu = xv[e];
                r[e] = uu - uu*uu*uu*(1.0f/3.0f) - vv[e] + 1.0f + gv[e] + ctrl;
            }
        } else {
            const float4 u4 = srow4[q - 256];
            float uv[4] = {u4.x, u4.y, u4.z, u4.w};
            #pragma unroll
            for (int e=0;e<4;e++){
                float ux = cv[e]*(xv[e]-x0);
                float ctrl = (ux < 10.0f && ux > -10.0f) ? ux : 0.0f;
                r[e] = 0.2f*(uv[e] + 0.7f - 0.8f*xv[e]) + ctrl;
            }
        }
        float* o = out + (size_t)n*2049 + d;
        o[0]=r[0]; o[1]=r[1]; o[2]=r[2]; o[3]=r[3];
    }
}

// ======== 3xBF16 mma.sync GEMM (split-2 bf16 operands, fp32 accum) ========
#define CPASYNC(dst, src) asm volatile("cp.async.cg.shared.global [%0], [%1], 16;\n" :: "r"(dst), "l"(src))
#define CPCOMMIT()        asm volatile("cp.async.commit_group;\n" ::: "memory")
#define CPWAIT(n)         asm volatile("cp.async.wait_group %0;\n" :: "n"(n) : "memory")

__device__ __forceinline__ void ldsm4(uint32_t addr, uint32_t& r0, uint32_t& r1,
                                      uint32_t& r2, uint32_t& r3){
    asm volatile("ldmatrix.sync.aligned.m8n8.x4.shared.b16 {%0,%1,%2,%3}, [%4];"
                 : "=r"(r0), "=r"(r1), "=r"(r2), "=r"(r3) : "r"(addr));
}
__device__ __forceinline__ void mma_bf16(float* d, const uint32_t* a, uint32_t b0, uint32_t b1){
    asm volatile("mma.sync.aligned.m16n8k16.row.col.f32.bf16.bf16.f32 "
                 "{%0,%1,%2,%3}, {%4,%5,%6,%7}, {%8,%9}, {%0,%1,%2,%3};"
                 : "+f"(d[0]), "+f"(d[1]), "+f"(d[2]), "+f"(d[3])
                 : "r"(a[0]), "r"(a[1]), "r"(a[2]), "r"(a[3]), "r"(b0), "r"(b1));
}

// C[M,N] = (Ah+Al)@(Bh+Bl)^T via hh+lh+hl. BK=32. TANH: tanh epi.
// SOUT=1: write bf16 split (Ch,Cl). SOUT=0: write fp32 Cf.
template<int BM, int BN, int STAGES, int TANH, int SOUT>
__global__ __launch_bounds__(256, 2)
void mmaGemmBF(int M, int N, int K,
               const bf16* __restrict__ Ah, const bf16* __restrict__ Al,
               const bf16* __restrict__ Bh, const bf16* __restrict__ Bl,
               const float* __restrict__ bias,
               float* __restrict__ Cf, bf16* __restrict__ Ch, bf16* __restrict__ Cl){
    constexpr int ROWB = 80;                 // 32 bf16 (64B) + 16B pad
    constexpr int offAl = BM*ROWB;
    constexpr int offBh = 2*BM*ROWB;
    constexpr int offBl = offBh + BN*ROWB;
    constexpr int STG   = 2*(BM+BN)*ROWB;
    constexpr int WARPS_M = BM/32;
    constexpr int WARPS_N = 8/WARPS_M;
    constexpr int WN = BN/WARPS_N;
    constexpr int NP = WN/16;

    extern __shared__ __align__(16) char smem[];

    const int tid  = threadIdx.x;
    const int warp = tid >> 5, lane = tid & 31;
    const int wm = (warp % WARPS_M)*32;
    const int wn = (warp / WARPS_M)*WN;
    const int bm = blockIdx.y*BM, bn = blockIdx.x*BN;

    const int lr  = lane & 15;               // ldmatrix row within 16
    const int lcb = (lane >> 4)*16;          // 16B column half

    float acc[2][2*NP][4];
    #pragma unroll
    for (int i=0;i<2;i++)
        #pragma unroll
        for (int j=0;j<2*NP;j++)
            #pragma unroll
            for (int q=0;q<4;q++) acc[i][j][q] = 0.0f;

    uint32_t sBase = (uint32_t)__cvta_generic_to_shared(smem);

    auto loadTile = [&](int buf, int k0){
        uint32_t st = sBase + buf*STG;
        #pragma unroll
        for (int i=0;i<(BM*4)/256;i++){
            int L = tid + i*256;
            int r = L>>2, c = L&3;
            CPASYNC(st + r*ROWB + c*16,         Ah + (size_t)(bm+r)*K + k0 + c*8);
            CPASYNC(st + offAl + r*ROWB + c*16, Al + (size_t)(bm+r)*K + k0 + c*8);
        }
        #pragma unroll
        for (int i=0;i<(BN*4)/256;i++){
            int L = tid + i*256;
            int r = L>>2, c = L&3;
            CPASYNC(st + offBh + r*ROWB + c*16, Bh + (size_t)(bn+r)*K + k0 + c*8);
            CPASYNC(st + offBl + r*ROWB + c*16, Bl + (size_t)(bn+r)*K + k0 + c*8);
        }
        CPCOMMIT();
    };

    const int nk = K / 32;
    #pragma unroll
    for (int p=0; p<STAGES-1; p++){
        if (p < nk) loadTile(p, p*32); else CPCOMMIT();
    }

    for (int ck = 0; ck < nk; ck++){
        CPWAIT(STAGES-2);
        __syncthreads();

        int nxt = ck + STAGES - 1;
        if (nxt < nk) loadTile(nxt % STAGES, nxt*32); else CPCOMMIT();

        uint32_t st = sBase + (ck % STAGES)*STG;
        #pragma unroll
        for (int ks=0; ks<2; ks++){                      // two k16 steps
            uint32_t bh[NP][4], bl[NP][4];
            #pragma unroll
            for (int p=0; p<NP; p++){
                uint32_t boff = (uint32_t)((wn + p*16 + lr)*ROWB) + ks*32 + lcb;
                ldsm4(st + offBh + boff, bh[p][0], bh[p][1], bh[p][2], bh[p][3]);
                ldsm4(st + offBl + boff, bl[p][0], bl[p][1], bl[p][2], bl[p][3]);
            }
            #pragma unroll
            for (int mt=0; mt<2; mt++){
                uint32_t aoff = (uint32_t)((wm + mt*16 + lr)*ROWB) + ks*32 + lcb;
                uint32_t ah[4], al[4];
                ldsm4(st + aoff,        ah[0], ah[1], ah[2], ah[3]);
                ldsm4(st + offAl + aoff, al[0], al[1], al[2], al[3]);
                #pragma unroll
                for (int p=0; p<NP; p++){
                    // n-subtile 0: B regs {r0, r2}; subtile 1: {r1, r3}
                    mma_bf16(acc[mt][2*p+0], ah, bh[p][0], bh[p][2]);
                    mma_bf16(acc[mt][2*p+0], al, bh[p][0], bh[p][2]);
                    mma_bf16(acc[mt][2*p+0], ah, bl[p][0], bl[p][2]);
                    mma_bf16(acc[mt][2*p+1], ah, bh[p][1], bh[p][3]);
                    mma_bf16(acc[mt][2*p+1], al, bh[p][1], bh[p][3]);
                    mma_bf16(acc[mt][2*p+1], ah, bl[p][1], bl[p][3]);
                }
            }
        }
        __syncthreads();
    }

    const int tg = lane & 3, g = lane >> 2;
    #pragma unroll
    for (int mt=0; mt<2; mt++){
        #pragma unroll
        for (int nt=0; nt<2*NP; nt++){
            int p = nt >> 1, nsub = nt & 1;
            int row = bm + wm + mt*16 + g;
            int col = bn + wn + p*16 + nsub*8 + tg*2;
            float v0 = acc[mt][nt][0], v1 = acc[mt][nt][1];
            float v2 = acc[mt][nt][2], v3 = acc[mt][nt][3];
            if (bias){
                float b0v = bias[col], b1v = bias[col+1];
                v0 += b0v; v1 += b1v; v2 += b0v; v3 += b1v;
            }
            if (TANH){ v0 = tanhf(v0); v1 = tanhf(v1); v2 = tanhf(v2); v3 = tanhf(v3); }
            if (SOUT){
                bf16 h0,l0,h1,l1,h2,l2,h3,l3;
                bfsplit(v0,h0,l0); bfsplit(v1,h1,l1);
                bfsplit(v2,h2,l2); bfsplit(v3,h3,l3);
                *reinterpret_cast<__nv_bfloat162*>(Ch + (size_t)row*N + col)     = __halves2bfloat162(h0,h1);
                *reinterpret_cast<__nv_bfloat162*>(Ch + (size_t)(row+8)*N + col) = __halves2bfloat162(h2,h3);
                *reinterpret_cast<__nv_bfloat162*>(Cl + (size_t)row*N + col)     = __halves2bfloat162(l0,l1);
                *reinterpret_cast<__nv_bfloat162*>(Cl + (size_t)(row+8)*N + col) = __halves2bfloat162(l2,l3);
            } else {
                *reinterpret_cast<float2*>(Cf + (size_t)row*N + col)     = make_float2(v0, v1);
                *reinterpret_cast<float2*>(Cf + (size_t)(row+8)*N + col) = make_float2(v2, v3);
            }
        }
    }
}

// ---------------- host ----------------
extern "C" void kernel_launch(void* const* d_in, const int* in_sizes, int n_in,
                              void* d_out, int out_size){
    const float* state = (const float*)d_in[0];
    const float* t     = (const float*)d_in[1];
    const float* P     = (const float*)d_in[2];
    const float* W1    = (const float*)d_in[3];
    const float* b1    = (const float*)d_in[4];
    const float* W2    = (const float*)d_in[5];
    const float* b2    = (const float*)d_in[6];
    const float* W3    = (const float*)d_in[7];
    const float* b3    = (const float*)d_in[8];
    const float* icW0  = (const float*)d_in[9];
    const float* icb0  = (const float*)d_in[10];
    const float* icW1  = (const float*)d_in[11];
    const float* icb1  = (const float*)d_in[12];
    const float* icW2  = (const float*)d_in[13];
    const float* icb2  = (const float*)d_in[14];
    const float* icU0  = (const float*)d_in[15];
    const float* icU1  = (const float*)d_in[16];
    float* out = (float*)d_out;

    bf16 *Pt_h,*Pt_l,*PtSc_h,*PtSc_l,*Lm_h,*Lm_l,*Hu_h,*Hu_l,*st_h,*st_l,*sx_h,*sx_l;
    bf16 *W1_h,*W1_l,*W2_h,*W2_l,*W3_h,*W3_l,*icW_h,*icW_l,*H1_h,*H1_l,*H2_h,*H2_l;
    float *G1,*CT,*Z01,*cb01;
    cudaGetSymbolAddress((void**)&Pt_h,   g_Pt_h);   cudaGetSymbolAddress((void**)&Pt_l,   g_Pt_l);
    cudaGetSymbolAddress((void**)&PtSc_h, g_PtSc_h); cudaGetSymbolAddress((void**)&PtSc_l, g_PtSc_l);
    cudaGetSymbolAddress((void**)&Lm_h,   g_Lm_h);   cudaGetSymbolAddress((void**)&Lm_l,   g_Lm_l);
    cudaGetSymbolAddress((void**)&Hu_h,   g_Hu_h);   cudaGetSymbolAddress((void**)&Hu_l,   g_Hu_l);
    cudaGetSymbolAddress((void**)&st_h,   g_st_h);   cudaGetSymbolAddress((void**)&st_l,   g_st_l);
    cudaGetSymbolAddress((void**)&sx_h,   g_sx_h);   cudaGetSymbolAddress((void**)&sx_l,   g_sx_l);
    cudaGetSymbolAddress((void**)&W1_h,   g_W1_h);   cudaGetSymbolAddress((void**)&W1_l,   g_W1_l);
    cudaGetSymbolAddress((void**)&W2_h,   g_W2_h);   cudaGetSymbolAddress((void**)&W2_l,   g_W2_l);
    cudaGetSymbolAddress((void**)&W3_h,   g_W3_h);   cudaGetSymbolAddress((void**)&W3_l,   g_W3_l);
    cudaGetSymbolAddress((void**)&icW_h,  g_icW_h);  cudaGetSymbolAddress((void**)&icW_l,  g_icW_l);
    cudaGetSymbolAddress((void**)&H1_h,   g_H1_h);   cudaGetSymbolAddress((void**)&H1_l,   g_H1_l);
    cudaGetSymbolAddress((void**)&H2_h,   g_H2_h);   cudaGetSymbolAddress((void**)&H2_l,   g_H2_l);
    cudaGetSymbolAddress((void**)&G1,  g_G1);
    cudaGetSymbolAddress((void**)&CT,  g_CT);
    cudaGetSymbolAddress((void**)&Z01, g_Z01);
    cudaGetSymbolAddress((void**)&cb01,g_cb01);

    const int sm128 = 2*2*(128+128)*80;   // 81920  -> 2 CTAs/SM
    const int smLm  = 2*2*( 64+128)*80;   // 61440  -> 2 CTAs/SM
    const int smZ   = 4*2*( 64+ 64)*80;   // 81920  -> 2 CTAs/SM
    cudaFuncSetAttribute((const void*)mmaGemmBF<64,128,2,0,1>,  cudaFuncAttributeMaxDynamicSharedMemorySize, smLm);
    cudaFuncSetAttribute((const void*)mmaGemmBF<128,128,2,0,0>, cudaFuncAttributeMaxDynamicSharedMemorySize, sm128);
    cudaFuncSetAttribute((const void*)mmaGemmBF<128,128,2,1,1>, cudaFuncAttributeMaxDynamicSharedMemorySize, sm128);
    cudaFuncSetAttribute((const void*)mmaGemmBF<64,64,4,0,0>,   cudaFuncAttributeMaxDynamicSharedMemorySize, smZ);

    transposePK<<<dim3(32,32), dim3(32,8)>>>(P, t);
    catIcWK<<<(64*DIN2)/256, 256>>>(icW0, icW1);
    splitWK<<<(512*DIN2/4+255)/256, 256>>>(W1, W1_h, W1_l, 512*DIN2/4);
    splitWK<<<(512*512 /4+255)/256, 256>>>(W2, W2_h, W2_l, 512*512/4);
    splitWK<<<(DIN2*512/4+255)/256, 256>>>(W3, W3_h, W3_l, DIN2*512/4);
    prepIcnnK<<<1, 256>>>(icU0, icU1, icb0, icb1, icb2);
    huStK<<<(NROWS*512)/256, 256>>>(state);

    // Lm = PtSc @ Pt^T  (1024x1024x1024) -> bf16 split output
    mmaGemmBF<64,128,2,0,1><<<dim3(8,16), 256, smLm>>>(1024, 1024, 1024,
        PtSc_h, PtSc_l, Pt_h, Pt_l, nullptr, nullptr, Lm_h, Lm_l);
    // G1 = Hu @ Lm (symmetric)  (4096x1024x1024) -> fp32
    mmaGemmBF<128,128,2,0,0><<<dim3(8,32), 256, sm128>>>(NROWS, 1024, 1024,
        Hu_h, Hu_l, Lm_h, Lm_l, nullptr, G1, nullptr, nullptr);
    // H1 = tanh(st @ W1^T + b1) (4096x512x2048) -> bf16 split
    mmaGemmBF<128,128,2,1,1><<<dim3(4,32), 256, sm128>>>(NROWS, 512, 2048,
        st_h, st_l, W1_h, W1_l, b1, nullptr, H1_h, H1_l);
    // H2 = tanh(H1 @ W2^T + b2) (4096x512x512) -> bf16 split
    mmaGemmBF<128,128,2,1,1><<<dim3(4,32), 256, sm128>>>(NROWS, 512, 512,
        H1_h, H1_l, W2_h, W2_l, b2, nullptr, H2_h, H2_l);
    // CT = H2 @ W3^T + b3       (4096x2048x512) -> fp32
    mmaGemmBF<128,128,2,0,0><<<dim3(16,32), 256, sm128>>>(NROWS, 2048, 512,
        H2_h, H2_l, W3_h, W3_l, b3, CT, nullptr, nullptr);
    // Z01 = state @ icW^T + cb01 (4096x128x2048) -> fp32
    mmaGemmBF<64,64,4,0,0><<<dim3(2,64), 256, smZ>>>(NROWS, 128, 2048,
        sx_h, sx_l, icW_h, icW_l, cb01, Z01, nullptr, nullptr);

    z2K<<<NROWS/4, 256>>>();
    finalK<<<NROWS, 256>>>(state, icW2, icb2, out);
}

// round 13
// speedup vs baseline: 1.8056x; 1.0127x over previous
#include <cuda_runtime.h>
#include <cuda_bf16.h>
#include <math.h>
#include <stdint.h>

#define NROWS 4096
#define DIMH  1024
#define DIN2  2048

typedef __nv_bfloat16 bf16;

// ---------------- helpers ----------------
__device__ __forceinline__ float srelu(float x){
    float r = fmaxf(x, 0.0f);
    if (r < 0.1f){ float r2 = r*r; return (0.2f*r*r2 - r2*r2) * 500.0f; }
    return x - 0.05f;
}
__device__ __forceinline__ float softplusf(float x){
    return fmaxf(x, 0.0f) + log1pf(expf(-fabsf(x)));
}
__device__ __forceinline__ void bfsplit(float x, bf16& h, bf16& l){
    h = __float2bfloat16_rn(x);
    l = __float2bfloat16_rn(x - __bfloat162float(h));
}

// ---------------- scratch (device globals) ----------------
__device__ bf16  g_Pt_h  [DIMH*DIMH],  g_Pt_l  [DIMH*DIMH];
__device__ bf16  g_PtSc_h[DIMH*DIMH],  g_PtSc_l[DIMH*DIMH];
__device__ bf16  g_Lm_h  [DIMH*DIMH],  g_Lm_l  [DIMH*DIMH];
__device__ bf16  g_Hu_h  [NROWS*DIMH], g_Hu_l  [NROWS*DIMH];
__device__ bf16  g_st_h  [NROWS*DIN2], g_st_l  [NROWS*DIN2];
__device__ bf16  g_sx_h  [NROWS*DIN2], g_sx_l  [NROWS*DIN2];
__device__ bf16  g_W1_h  [512*DIN2],   g_W1_l  [512*DIN2];
__device__ bf16  g_W2_h  [512*512],    g_W2_l  [512*512];
__device__ bf16  g_W3_h  [DIN2*512],   g_W3_l  [DIN2*512];
__device__ bf16  g_icW_h [128*DIN2],   g_icW_l [128*DIN2];
__device__ bf16  g_H1_h  [NROWS*512],  g_H1_l  [NROWS*512];
__device__ bf16  g_H2_h  [NROWS*512],  g_H2_l  [NROWS*512];
__device__ float g_G1    [NROWS*DIMH];
__device__ float g_CT    [NROWS*DIN2];
__device__ float g_Z01   [NROWS*128];
__device__ float g_Z2    [NROWS*64];
__device__ float g_spU0  [64*64];
__device__ float g_spU1  [64];
__device__ float g_cb01  [128];
__device__ float g_z0    [1];

// ---------------- P transpose + eig scale + bf16 split ----------------
__global__ void transposePK(const float* __restrict__ P, const float* __restrict__ t){
    __shared__ float tile[32][33];
    int c0 = blockIdx.x*32, r0 = blockIdx.y*32;
    int x = threadIdx.x, y = threadIdx.y;
    float s = 2.0f * sinf(t[0]);
    #pragma unroll
    for (int i=0;i<32;i+=8)
        tile[y+i][x] = P[(size_t)(r0+y+i)*DIMH + c0 + x];
    __syncthreads();
    #pragma unroll
    for (int i=0;i<32;i+=8){
        int c = c0 + y + i;
        int r = r0 + x;
        float v = tile[x][y+i];
        float e = (r == 0) ? 0.0f : ((r <= 511) ? (1.0f + s) : (1.0f - s));
        float ev = e * v;
        size_t o = (size_t)c*DIMH + r;
        bf16 h, l;
        bfsplit(v,  h, l); g_Pt_h[o]   = h; g_Pt_l[o]   = l;
        bfsplit(ev, h, l); g_PtSc_h[o] = h; g_PtSc_l[o] = l;
    }
}

// ---------------- concat icW0/icW1 + split ----------------
__global__ void catIcWK(const float* __restrict__ w0, const float* __restrict__ w1){
    int i = blockIdx.x*256 + threadIdx.x;
    bf16 h, l;
    bfsplit(w0[i], h, l); g_icW_h[i] = h; g_icW_l[i] = l;
    bfsplit(w1[i], h, l); g_icW_h[64*DIN2+i] = h; g_icW_l[64*DIN2+i] = l;
}

// ---------------- generic weight split ----------------
__global__ void splitWK(const float* __restrict__ in, bf16* __restrict__ hi,
                        bf16* __restrict__ lo, int n4){
    int i = blockIdx.x*256 + threadIdx.x;
    if (i >= n4) return;
    float4 x = reinterpret_cast<const float4*>(in)[i];
    bf16 h0,l0,h1,l1,h2,l2,h3,l3;
    bfsplit(x.x,h0,l0); bfsplit(x.y,h1,l1); bfsplit(x.z,h2,l2); bfsplit(x.w,h3,l3);
    reinterpret_cast<__nv_bfloat162*>(hi)[i*2+0] = __halves2bfloat162(h0,h1);
    reinterpret_cast<__nv_bfloat162*>(hi)[i*2+1] = __halves2bfloat162(h2,h3);
    reinterpret_cast<__nv_bfloat162*>(lo)[i*2+0] = __halves2bfloat162(l0,l1);
    reinterpret_cast<__nv_bfloat162*>(lo)[i*2+1] = __halves2bfloat162(l2,l3);
}

// ---------------- Hu / st / state splits ----------------
__global__ void huStK(const float* __restrict__ state){
    int idx = blockIdx.x*blockDim.x + threadIdx.x;   // NROWS*512 float4s
    int n = idx >> 9, q = idx & 511;
    const float4* s4 = reinterpret_cast<const float4*>(state);
    float4 x = s4[idx];
    float x0 = state[(n<<11) + (q < 256 ? 0 : DIMH)];
    bf16 h0,l0,h1,l1,h2,l2,h3,l3;

    bfsplit(x.x,h0,l0); bfsplit(x.y,h1,l1); bfsplit(x.z,h2,l2); bfsplit(x.w,h3,l3);
    reinterpret_cast<__nv_bfloat162*>(g_sx_h)[idx*2+0] = __halves2bfloat162(h0,h1);
    reinterpret_cast<__nv_bfloat162*>(g_sx_h)[idx*2+1] = __halves2bfloat162(h2,h3);
    reinterpret_cast<__nv_bfloat162*>(g_sx_l)[idx*2+0] = __halves2bfloat162(l0,l1);
    reinterpret_cast<__nv_bfloat162*>(g_sx_l)[idx*2+1] = __halves2bfloat162(l2,l3);

    bfsplit(x.x-x0,h0,l0); bfsplit(x.y-x0,h1,l1); bfsplit(x.z-x0,h2,l2); bfsplit(x.w-x0,h3,l3);
    reinterpret_cast<__nv_bfloat162*>(g_st_h)[idx*2+0] = __halves2bfloat162(h0,h1);
    reinterpret_cast<__nv_bfloat162*>(g_st_h)[idx*2+1] = __halves2bfloat162(h2,h3);
    reinterpret_cast<__nv_bfloat162*>(g_st_l)[idx*2+0] = __halves2bfloat162(l0,l1);
    reinterpret_cast<__nv_bfloat162*>(g_st_l)[idx*2+1] = __halves2bfloat162(l2,l3);

    if (q < 256){
        float ux = 1.0f/(1.0f + expf(-10.0f*x.x));
        float uy = 1.0f/(1.0f + expf(-10.0f*x.y));
        float uz = 1.0f/(1.0f + expf(-10.0f*x.z));
        float uw = 1.0f/(1.0f + expf(-10.0f*x.w));
        bfsplit(ux,h0,l0); bfsplit(uy,h1,l1); bfsplit(uz,h2,l2); bfsplit(uw,h3,l3);
        int o = n*256 + q;
        reinterpret_cast<__nv_bfloat162*>(g_Hu_h)[o*2+0] = __halves2bfloat162(h0,h1);
        reinterpret_cast<__nv_bfloat162*>(g_Hu_h)[o*2+1] = __halves2bfloat162(h2,h3);
        reinterpret_cast<__nv_bfloat162*>(g_Hu_l)[o*2+0] = __halves2bfloat162(l0,l1);
        reinterpret_cast<__nv_bfloat162*>(g_Hu_l)[o*2+1] = __halves2bfloat162(l2,l3);
    }
}

// ---------------- softplus(U), biases, z0 constant ----------------
__global__ void prepIcnnK(const float* __restrict__ icU0, const float* __restrict__ icU1,
                          const float* __restrict__ icb0, const float* __restrict__ icb1,
                          const float* __restrict__ icb2){
    int tid = threadIdx.x;
    for (int i = tid; i < 64*64; i += blockDim.x) g_spU0[i] = softplusf(icU0[i]);
    if (tid < 64){
        g_spU1[tid]     = softplusf(icU1[tid]);
        g_cb01[tid]     = icb0[tid];
        g_cb01[64+tid]  = icb1[tid];
    }
    __syncthreads();
    __shared__ float z0a[64], z0b[64];
    if (tid < 64) z0a[tid] = srelu(icb0[tid]);
    __syncthreads();
    if (tid < 64){
        float s = icb1[tid];
        #pragma unroll 8
        for (int j=0;j<64;j++) s += g_spU0[tid*64+j]*z0a[j];
        z0b[tid] = srelu(s);
    }
    __syncthreads();
    if (tid == 0){
        float s = icb2[0];
        for (int j=0;j<64;j++) s += g_spU1[j]*z0b[j];
        g_z0[0] = srelu(s);
    }
}

// ---------------- z2 ----------------
__global__ void z2K(){
    __shared__ float sUT[64*64];
    __shared__ float z1s[4][64];
    int t = threadIdx.x;
    for (int i = t; i < 4096; i += 256){
        int j = i >> 6, k = i & 63;
        sUT[i] = g_spU0[k*64 + j];
    }
    int r = t >> 6, k = t & 63;
    int n = blockIdx.x*4 + r;
    z1s[r][k] = srelu(g_Z01[n*128 + k]);
    __syncthreads();
    float s = g_Z01[n*128 + 64 + k];
    #pragma unroll 8
    for (int j=0;j<64;j++) s += sUT[j*64 + k]*z1s[r][j];
    g_Z2[n*64 + k] = srelu(s);
}

// ---------------- final assembly ----------------
__global__ void finalK(const float* __restrict__ state, const float* __restrict__ icW2,
                       const float* __restrict__ icb2, float* __restrict__ out){
    int n = blockIdx.x;
    int tid = threadIdx.x;
    const float* srow = state + (size_t)n*DIN2;
    const float4* srow4 = reinterpret_cast<const float4*>(srow);
    const float4* icW24 = reinterpret_cast<const float4*>(icW2);
    const float4* CT4   = reinterpret_cast<const float4*>(g_CT + (size_t)n*DIN2);

    float x0u = srow[0], x0v = srow[DIMH];

    float dot = 0.0f, ss = 0.0f;
    #pragma unroll
    for (int it=0; it<2; it++){
        int q = tid + it*256;
        float4 x = srow4[q], w = icW24[q];
        dot += w.x*x.x + w.y*x.y + w.z*x.z + w.w*x.w;
        ss  += x.x*x.x + x.y*x.y + x.z*x.z + x.w*x.w;
    }
    #pragma unroll
    for (int o=16;o>0;o>>=1){
        dot += __shfl_down_sync(0xffffffffu, dot, o);
        ss  += __shfl_down_sync(0xffffffffu, ss,  o);
    }
    __shared__ float sd[8], sq[8];
    if ((tid & 31) == 0){ sd[tid>>5] = dot; sq[tid>>5] = ss; }
    __syncthreads();
    if (tid == 0){
        float D = 0.0f, S = 0.0f;
        #pragma unroll
        for (int w=0;w<8;w++){ D += sd[w]; S += sq[w]; }
        float z = icb2[0] + D;
        for (int k=0;k<64;k++) z = fmaf(g_spU1[k], g_Z2[n*64+k], z);
        float z3 = srelu(z);
        out[(size_t)n*2049 + 2048] = srelu(z3 - g_z0[0]) + 0.001f*S;
    }

    #pragma unroll
    for (int it=0; it<2; it++){
        int q = tid + it*256;
        int d = q*4;
        float4 x  = srow4[q];
        float4 ct = CT4[q];
        float x0 = (d < DIMH) ? x0u : x0v;
        float r[4];
        float xv[4] = {x.x, x.y, x.z, x.w};
        float cv[4] = {ct.x, ct.y, ct.z, ct.w};
        if (d < DIMH){
            const float4 v4 = srow4[q + 256];
            const float4 gg = reinterpret_cast<const float4*>(g_G1 + (size_t)n*DIMH)[q];
            float vv[4] = {v4.x, v4.y, v4.z, v4.w};
            float gv[4] = {gg.x, gg.y, gg.z, gg.w};
            #pragma unroll
            for (int e=0;e<4;e++){
                float ux = cv[e]*(xv[e]-x0);
                float ctrl = (ux < 10.0f && ux > -10.0f) ? ux : 0.0f;
                float uu = xv[e];
                r[e] = uu - uu*uu*uu*(1.0f/3.0f) - vv[e] + 1.0f + gv[e] + ctrl;
            }
        } else {
            const float4 u4 = srow4[q - 256];
            float uv[4] = {u4.x, u4.y, u4.z, u4.w};
            #pragma unroll
            for (int e=0;e<4;e++){
                float ux = cv[e]*(xv[e]-x0);
                float ctrl = (ux < 10.0f && ux > -10.0f) ? ux : 0.0f;
                r[e] = 0.2f*(uv[e] + 0.7f - 0.8f*xv[e]) + ctrl;
            }
        }
        float* o = out + (size_t)n*2049 + d;
        o[0]=r[0]; o[1]=r[1]; o[2]=r[2]; o[3]=r[3];
    }
}

// ======== 3xBF16 mma.sync GEMM (split-2 bf16 operands, fp32 accum) ========
#define CPASYNC(dst, src) asm volatile("cp.async.cg.shared.global [%0], [%1], 16;\n" :: "r"(dst), "l"(src))
#define CPCOMMIT()        asm volatile("cp.async.commit_group;\n" ::: "memory")
#define CPWAIT(n)         asm volatile("cp.async.wait_group %0;\n" :: "n"(n) : "memory")

__device__ __forceinline__ void ldsm4(uint32_t addr, uint32_t& r0, uint32_t& r1,
                                      uint32_t& r2, uint32_t& r3){
    asm volatile("ldmatrix.sync.aligned.m8n8.x4.shared.b16 {%0,%1,%2,%3}, [%4];"
                 : "=r"(r0), "=r"(r1), "=r"(r2), "=r"(r3) : "r"(addr));
}
__device__ __forceinline__ void mma_bf16(float* d, const uint32_t* a, uint32_t b0, uint32_t b1){
    asm volatile("mma.sync.aligned.m16n8k16.row.col.f32.bf16.bf16.f32 "
                 "{%0,%1,%2,%3}, {%4,%5,%6,%7}, {%8,%9}, {%0,%1,%2,%3};"
                 : "+f"(d[0]), "+f"(d[1]), "+f"(d[2]), "+f"(d[3])
                 : "r"(a[0]), "r"(a[1]), "r"(a[2]), "r"(a[3]), "r"(b0), "r"(b1));
}

// C[M,N] = (Ah+Al)@(Bh+Bl)^T via hh+lh+hl. BK=32. TANH: tanh epi.
// SOUT=1: write bf16 split (Ch,Cl). SOUT=0: write fp32 Cf.
// p-outer mainloop keeps live regs ~108 so (256,2) fits without spills.
template<int BM, int BN, int STAGES, int TANH, int SOUT>
__global__ __launch_bounds__(256, 2)
void mmaGemmBF(int M, int N, int K,
               const bf16* __restrict__ Ah, const bf16* __restrict__ Al,
               const bf16* __restrict__ Bh, const bf16* __restrict__ Bl,
               const float* __restrict__ bias,
               float* __restrict__ Cf, bf16* __restrict__ Ch, bf16* __restrict__ Cl){
    constexpr int ROWB = 80;                 // 32 bf16 (64B) + 16B pad
    constexpr int offAl = BM*ROWB;
    constexpr int offBh = 2*BM*ROWB;
    constexpr int offBl = offBh + BN*ROWB;
    constexpr int STG   = 2*(BM+BN)*ROWB;
    constexpr int WARPS_M = BM/32;
    constexpr int WARPS_N = 8/WARPS_M;
    constexpr int WN = BN/WARPS_N;
    constexpr int NP = WN/16;

    extern __shared__ __align__(16) char smem[];

    const int tid  = threadIdx.x;
    const int warp = tid >> 5, lane = tid & 31;
    const int wm = (warp % WARPS_M)*32;
    const int wn = (warp / WARPS_M)*WN;
    const int bm = blockIdx.y*BM, bn = blockIdx.x*BN;

    const int lr  = lane & 15;               // ldmatrix row within 16
    const int lcb = (lane >> 4)*16;          // 16B column half

    float acc[2][2*NP][4];
    #pragma unroll
    for (int i=0;i<2;i++)
        #pragma unroll
        for (int j=0;j<2*NP;j++)
            #pragma unroll
            for (int q=0;q<4;q++) acc[i][j][q] = 0.0f;

    uint32_t sBase = (uint32_t)__cvta_generic_to_shared(smem);

    auto loadTile = [&](int buf, int k0){
        uint32_t st = sBase + buf*STG;
        #pragma unroll
        for (int i=0;i<(BM*4)/256;i++){
            int L = tid + i*256;
            int r = L>>2, c = L&3;
            CPASYNC(st + r*ROWB + c*16,         Ah + (size_t)(bm+r)*K + k0 + c*8);
            CPASYNC(st + offAl + r*ROWB + c*16, Al + (size_t)(bm+r)*K + k0 + c*8);
        }
        #pragma unroll
        for (int i=0;i<(BN*4)/256;i++){
            int L = tid + i*256;
            int r = L>>2, c = L&3;
            CPASYNC(st + offBh + r*ROWB + c*16, Bh + (size_t)(bn+r)*K + k0 + c*8);
            CPASYNC(st + offBl + r*ROWB + c*16, Bl + (size_t)(bn+r)*K + k0 + c*8);
        }
        CPCOMMIT();
    };

    const int nk = K / 32;
    #pragma unroll
    for (int p=0; p<STAGES-1; p++){
        if (p < nk) loadTile(p, p*32); else CPCOMMIT();
    }

    for (int ck = 0; ck < nk; ck++){
        CPWAIT(STAGES-2);
        __syncthreads();

        int nxt = ck + STAGES - 1;
        if (nxt < nk) loadTile(nxt % STAGES, nxt*32); else CPCOMMIT();

        uint32_t st = sBase + (ck % STAGES)*STG;
        #pragma unroll
        for (int ks=0; ks<2; ks++){                      // two k16 steps
            // A fragments for both m-tiles (hi+lo): 16 regs live
            uint32_t ah[2][4], al[2][4];
            #pragma unroll
            for (int mt=0; mt<2; mt++){
                uint32_t aoff = (uint32_t)((wm + mt*16 + lr)*ROWB) + ks*32 + lcb;
                ldsm4(st + aoff,         ah[mt][0], ah[mt][1], ah[mt][2], ah[mt][3]);
                ldsm4(st + offAl + aoff, al[mt][0], al[mt][1], al[mt][2], al[mt][3]);
            }
            // p-outer: B fragments transient (8 regs)
            #pragma unroll
            for (int p=0; p<NP; p++){
                uint32_t boff = (uint32_t)((wn + p*16 + lr)*ROWB) + ks*32 + lcb;
                uint32_t bh[4], bl[4];
                ldsm4(st + offBh + boff, bh[0], bh[1], bh[2], bh[3]);
                ldsm4(st + offBl + boff, bl[0], bl[1], bl[2], bl[3]);
                #pragma unroll
                for (int mt=0; mt<2; mt++){
                    // n-subtile 0: B regs {r0, r2}; subtile 1: {r1, r3}
                    mma_bf16(acc[mt][2*p+0], ah[mt], bh[0], bh[2]);
                    mma_bf16(acc[mt][2*p+1], ah[mt], bh[1], bh[3]);
                    mma_bf16(acc[mt][2*p+0], al[mt], bh[0], bh[2]);
                    mma_bf16(acc[mt][2*p+1], al[mt], bh[1], bh[3]);
                    mma_bf16(acc[mt][2*p+0], ah[mt], bl[0], bl[2]);
                    mma_bf16(acc[mt][2*p+1], ah[mt], bl[1], bl[3]);
                }
            }
        }
        __syncthreads();
    }

    const int tg = lane & 3, g = lane >> 2;
    #pragma unroll
    for (int mt=0; mt<2; mt++){
        #pragma unroll
        for (int nt=0; nt<2*NP; nt++){
            int p = nt >> 1, nsub = nt & 1;
            int row = bm + wm + mt*16 + g;
            int col = bn + wn + p*16 + nsub*8 + tg*2;
            float v0 = acc[mt][nt][0], v1 = acc[mt][nt][1];
            float v2 = acc[mt][nt][2], v3 = acc[mt][nt][3];
            if (bias){
                float b0v = bias[col], b1v = bias[col+1];
                v0 += b0v; v1 += b1v; v2 += b0v; v3 += b1v;
            }
            if (TANH){ v0 = tanhf(v0); v1 = tanhf(v1); v2 = tanhf(v2); v3 = tanhf(v3); }
            if (SOUT){
                bf16 h0,l0,h1,l1,h2,l2,h3,l3;
                bfsplit(v0,h0,l0); bfsplit(v1,h1,l1);
                bfsplit(v2,h2,l2); bfsplit(v3,h3,l3);
                *reinterpret_cast<__nv_bfloat162*>(Ch + (size_t)row*N + col)     = __halves2bfloat162(h0,h1);
                *reinterpret_cast<__nv_bfloat162*>(Ch + (size_t)(row+8)*N + col) = __halves2bfloat162(h2,h3);
                *reinterpret_cast<__nv_bfloat162*>(Cl + (size_t)row*N + col)     = __halves2bfloat162(l0,l1);
                *reinterpret_cast<__nv_bfloat162*>(Cl + (size_t)(row+8)*N + col) = __halves2bfloat162(l2,l3);
            } else {
                *reinterpret_cast<float2*>(Cf + (size_t)row*N + col)     = make_float2(v0, v1);
                *reinterpret_cast<float2*>(Cf + (size_t)(row+8)*N + col) = make_float2(v2, v3);
            }
        }
    }
}

// ---------------- host ----------------
extern "C" void kernel_launch(void* const* d_in, const int* in_sizes, int n_in,
                              void* d_out, int out_size){
    const float* state = (const float*)d_in[0];
    const float* t     = (const float*)d_in[1];
    const float* P     = (const float*)d_in[2];
    const float* W1    = (const float*)d_in[3];
    const float* b1    = (const float*)d_in[4];
    const float* W2    = (const float*)d_in[5];
    const float* b2    = (const float*)d_in[6];
    const float* W3    = (const float*)d_in[7];
    const float* b3    = (const float*)d_in[8];
    const float* icW0  = (const float*)d_in[9];
    const float* icb0  = (const float*)d_in[10];
    const float* icW1  = (const float*)d_in[11];
    const float* icb1  = (const float*)d_in[12];
    const float* icW2  = (const float*)d_in[13];
    const float* icb2  = (const float*)d_in[14];
    const float* icU0  = (const float*)d_in[15];
    const float* icU1  = (const float*)d_in[16];
    float* out = (float*)d_out;

    bf16 *Pt_h,*Pt_l,*PtSc_h,*PtSc_l,*Lm_h,*Lm_l,*Hu_h,*Hu_l,*st_h,*st_l,*sx_h,*sx_l;
    bf16 *W1_h,*W1_l,*W2_h,*W2_l,*W3_h,*W3_l,*icW_h,*icW_l,*H1_h,*H1_l,*H2_h,*H2_l;
    float *G1,*CT,*Z01,*cb01;
    cudaGetSymbolAddress((void**)&Pt_h,   g_Pt_h);   cudaGetSymbolAddress((void**)&Pt_l,   g_Pt_l);
    cudaGetSymbolAddress((void**)&PtSc_h, g_PtSc_h); cudaGetSymbolAddress((void**)&PtSc_l, g_PtSc_l);
    cudaGetSymbolAddress((void**)&Lm_h,   g_Lm_h);   cudaGetSymbolAddress((void**)&Lm_l,   g_Lm_l);
    cudaGetSymbolAddress((void**)&Hu_h,   g_Hu_h);   cudaGetSymbolAddress((void**)&Hu_l,   g_Hu_l);
    cudaGetSymbolAddress((void**)&st_h,   g_st_h);   cudaGetSymbolAddress((void**)&st_l,   g_st_l);
    cudaGetSymbolAddress((void**)&sx_h,   g_sx_h);   cudaGetSymbolAddress((void**)&sx_l,   g_sx_l);
    cudaGetSymbolAddress((void**)&W1_h,   g_W1_h);   cudaGetSymbolAddress((void**)&W1_l,   g_W1_l);
    cudaGetSymbolAddress((void**)&W2_h,   g_W2_h);   cudaGetSymbolAddress((void**)&W2_l,   g_W2_l);
    cudaGetSymbolAddress((void**)&W3_h,   g_W3_h);   cudaGetSymbolAddress((void**)&W3_l,   g_W3_l);
    cudaGetSymbolAddress((void**)&icW_h,  g_icW_h);  cudaGetSymbolAddress((void**)&icW_l,  g_icW_l);
    cudaGetSymbolAddress((void**)&H1_h,   g_H1_h);   cudaGetSymbolAddress((void**)&H1_l,   g_H1_l);
    cudaGetSymbolAddress((void**)&H2_h,   g_H2_h);   cudaGetSymbolAddress((void**)&H2_l,   g_H2_l);
    cudaGetSymbolAddress((void**)&G1,  g_G1);
    cudaGetSymbolAddress((void**)&CT,  g_CT);
    cudaGetSymbolAddress((void**)&Z01, g_Z01);
    cudaGetSymbolAddress((void**)&cb01,g_cb01);

    const int sm128 = 2*2*(128+128)*80;   // 81920  -> 2 CTAs/SM
    const int smLm  = 2*2*( 64+128)*80;   // 61440  -> 2 CTAs/SM
    const int smZ   = 4*2*( 64+ 64)*80;   // 81920  -> 2 CTAs/SM
    cudaFuncSetAttribute((const void*)mmaGemmBF<64,128,2,0,1>,  cudaFuncAttributeMaxDynamicSharedMemorySize, smLm);
    cudaFuncSetAttribute((const void*)mmaGemmBF<128,128,2,0,0>, cudaFuncAttributeMaxDynamicSharedMemorySize, sm128);
    cudaFuncSetAttribute((const void*)mmaGemmBF<128,128,2,1,1>, cudaFuncAttributeMaxDynamicSharedMemorySize, sm128);
    cudaFuncSetAttribute((const void*)mmaGemmBF<64,64,4,0,0>,   cudaFuncAttributeMaxDynamicSharedMemorySize, smZ);

    transposePK<<<dim3(32,32), dim3(32,8)>>>(P, t);
    catIcWK<<<(64*DIN2)/256, 256>>>(icW0, icW1);
    splitWK<<<(512*DIN2/4+255)/256, 256>>>(W1, W1_h, W1_l, 512*DIN2/4);
    splitWK<<<(512*512 /4+255)/256, 256>>>(W2, W2_h, W2_l, 512*512/4);
    splitWK<<<(DIN2*512/4+255)/256, 256>>>(W3, W3_h, W3_l, DIN2*512/4);
    prepIcnnK<<<1, 256>>>(icU0, icU1, icb0, icb1, icb2);
    huStK<<<(NROWS*512)/256, 256>>>(state);

    // Lm = PtSc @ Pt^T  (1024x1024x1024) -> bf16 split output
    mmaGemmBF<64,128,2,0,1><<<dim3(8,16), 256, smLm>>>(1024, 1024, 1024,
        PtSc_h, PtSc_l, Pt_h, Pt_l, nullptr, nullptr, Lm_h, Lm_l);
    // G1 = Hu @ Lm (symmetric)  (4096x1024x1024) -> fp32
    mmaGemmBF<128,128,2,0,0><<<dim3(8,32), 256, sm128>>>(NROWS, 1024, 1024,
        Hu_h, Hu_l, Lm_h, Lm_l, nullptr, G1, nullptr, nullptr);
    // H1 = tanh(st @ W1^T + b1) (4096x512x2048) -> bf16 split
    mmaGemmBF<128,128,2,1,1><<<dim3(4,32), 256, sm128>>>(NROWS, 512, 2048,
        st_h, st_l, W1_h, W1_l, b1, nullptr, H1_h, H1_l);
    // H2 = tanh(H1 @ W2^T + b2) (4096x512x512) -> bf16 split
    mmaGemmBF<128,128,2,1,1><<<dim3(4,32), 256, sm128>>>(NROWS, 512, 512,
        H1_h, H1_l, W2_h, W2_l, b2, nullptr, H2_h, H2_l);
    // CT = H2 @ W3^T + b3       (4096x2048x512) -> fp32
    mmaGemmBF<128,128,2,0,0><<<dim3(16,32), 256, sm128>>>(NROWS, 2048, 512,
        H2_h, H2_l, W3_h, W3_l, b3, CT, nullptr, nullptr);
    // Z01 = state @ icW^T + cb01 (4096x128x2048) -> fp32
    mmaGemmBF<64,64,4,0,0><<<dim3(2,64), 256, smZ>>>(NROWS, 128, 2048,
        sx_h, sx_l, icW_h, icW_l, cb01, Z01, nullptr, nullptr);

    z2K<<<NROWS/4, 256>>>();
    finalK<<<NROWS, 256>>>(state, icW2, icb2, out);
}

// round 15
// speedup vs baseline: 2.1717x; 1.2028x over previous
#include <cuda_runtime.h>
#include <cuda_bf16.h>
#include <math.h>
#include <stdint.h>

#define NROWS 4096
#define DIMH  1024
#define DIN2  2048

typedef __nv_bfloat16 bf16;

// ---------------- helpers ----------------
__device__ __forceinline__ float srelu(float x){
    float r = fmaxf(x, 0.0f);
    if (r < 0.1f){ float r2 = r*r; return (0.2f*r*r2 - r2*r2) * 500.0f; }
    return x - 0.05f;
}
__device__ __forceinline__ float softplusf(float x){
    return fmaxf(x, 0.0f) + log1pf(expf(-fabsf(x)));
}
__device__ __forceinline__ void bfsplit(float x, bf16& h, bf16& l){
    h = __float2bfloat16_rn(x);
    l = __float2bfloat16_rn(x - __bfloat162float(h));
}

// ---------------- scratch (device globals) ----------------
__device__ bf16  g_Pt_h  [DIMH*DIMH],  g_Pt_l  [DIMH*DIMH];
__device__ bf16  g_PtSc_h[DIMH*DIMH],  g_PtSc_l[DIMH*DIMH];
__device__ bf16  g_Lm_h  [DIMH*DIMH],  g_Lm_l  [DIMH*DIMH];
__device__ bf16  g_Hu_h  [NROWS*DIMH], g_Hu_l  [NROWS*DIMH];
__device__ bf16  g_st_h  [NROWS*DIN2], g_st_l  [NROWS*DIN2];
__device__ bf16  g_sx_h  [NROWS*DIN2], g_sx_l  [NROWS*DIN2];
__device__ bf16  g_W1_h  [512*DIN2],   g_W1_l  [512*DIN2];
__device__ bf16  g_W2_h  [512*512],    g_W2_l  [512*512];
__device__ bf16  g_W3_h  [DIN2*512],   g_W3_l  [DIN2*512];
__device__ bf16  g_icW_h [128*DIN2],   g_icW_l [128*DIN2];
__device__ bf16  g_H1_h  [NROWS*512],  g_H1_l  [NROWS*512];
__device__ bf16  g_H2_h  [NROWS*512],  g_H2_l  [NROWS*512];
__device__ float g_G1    [NROWS*DIMH];
__device__ float g_CT    [NROWS*DIN2];
__device__ float g_Z01   [NROWS*128];
__device__ float g_Z2    [NROWS*64];
__device__ float g_spU0  [64*64];
__device__ float g_spU1  [64];
__device__ float g_cb01  [128];
__device__ float g_z0    [1];

// ---------------- P transpose + eig scale + bf16 split ----------------
__global__ void transposePK(const float* __restrict__ P, const float* __restrict__ t){
    __shared__ float tile[32][33];
    int c0 = blockIdx.x*32, r0 = blockIdx.y*32;
    int x = threadIdx.x, y = threadIdx.y;
    float s = 2.0f * sinf(t[0]);
    #pragma unroll
    for (int i=0;i<32;i+=8)
        tile[y+i][x] = P[(size_t)(r0+y+i)*DIMH + c0 + x];
    __syncthreads();
    #pragma unroll
    for (int i=0;i<32;i+=8){
        int c = c0 + y + i;
        int r = r0 + x;
        float v = tile[x][y+i];
        float e = (r == 0) ? 0.0f : ((r <= 511) ? (1.0f + s) : (1.0f - s));
        float ev = e * v;
        size_t o = (size_t)c*DIMH + r;
        bf16 h, l;
        bfsplit(v,  h, l); g_Pt_h[o]   = h; g_Pt_l[o]   = l;
        bfsplit(ev, h, l); g_PtSc_h[o] = h; g_PtSc_l[o] = l;
    }
}

// ---------------- concat icW0/icW1 + split ----------------
__global__ void catIcWK(const float* __restrict__ w0, const float* __restrict__ w1){
    int i = blockIdx.x*256 + threadIdx.x;
    bf16 h, l;
    bfsplit(w0[i], h, l); g_icW_h[i] = h; g_icW_l[i] = l;
    bfsplit(w1[i], h, l); g_icW_h[64*DIN2+i] = h; g_icW_l[64*DIN2+i] = l;
}

// ---------------- generic weight split ----------------
__global__ void splitWK(const float* __restrict__ in, bf16* __restrict__ hi,
                        bf16* __restrict__ lo, int n4){
    int i = blockIdx.x*256 + threadIdx.x;
    if (i >= n4) return;
    float4 x = reinterpret_cast<const float4*>(in)[i];
    bf16 h0,l0,h1,l1,h2,l2,h3,l3;
    bfsplit(x.x,h0,l0); bfsplit(x.y,h1,l1); bfsplit(x.z,h2,l2); bfsplit(x.w,h3,l3);
    reinterpret_cast<__nv_bfloat162*>(hi)[i*2+0] = __halves2bfloat162(h0,h1);
    reinterpret_cast<__nv_bfloat162*>(hi)[i*2+1] = __halves2bfloat162(h2,h3);
    reinterpret_cast<__nv_bfloat162*>(lo)[i*2+0] = __halves2bfloat162(l0,l1);
    reinterpret_cast<__nv_bfloat162*>(lo)[i*2+1] = __halves2bfloat162(l2,l3);
}

// ---------------- Hu / st / state splits ----------------
__global__ void huStK(const float* __restrict__ state){
    int idx = blockIdx.x*blockDim.x + threadIdx.x;   // NROWS*512 float4s
    int n = idx >> 9, q = idx & 511;
    const float4* s4 = reinterpret_cast<const float4*>(state);
    float4 x = s4[idx];
    float x0 = state[(n<<11) + (q < 256 ? 0 : DIMH)];
    bf16 h0,l0,h1,l1,h2,l2,h3,l3;

    bfsplit(x.x,h0,l0); bfsplit(x.y,h1,l1); bfsplit(x.z,h2,l2); bfsplit(x.w,h3,l3);
    reinterpret_cast<__nv_bfloat162*>(g_sx_h)[idx*2+0] = __halves2bfloat162(h0,h1);
    reinterpret_cast<__nv_bfloat162*>(g_sx_h)[idx*2+1] = __halves2bfloat162(h2,h3);
    reinterpret_cast<__nv_bfloat162*>(g_sx_l)[idx*2+0] = __halves2bfloat162(l0,l1);
    reinterpret_cast<__nv_bfloat162*>(g_sx_l)[idx*2+1] = __halves2bfloat162(l2,l3);

    bfsplit(x.x-x0,h0,l0); bfsplit(x.y-x0,h1,l1); bfsplit(x.z-x0,h2,l2); bfsplit(x.w-x0,h3,l3);
    reinterpret_cast<__nv_bfloat162*>(g_st_h)[idx*2+0] = __halves2bfloat162(h0,h1);
    reinterpret_cast<__nv_bfloat162*>(g_st_h)[idx*2+1] = __halves2bfloat162(h2,h3);
    reinterpret_cast<__nv_bfloat162*>(g_st_l)[idx*2+0] = __halves2bfloat162(l0,l1);
    reinterpret_cast<__nv_bfloat162*>(g_st_l)[idx*2+1] = __halves2bfloat162(l2,l3);

    if (q < 256){
        float ux = 1.0f/(1.0f + expf(-10.0f*x.x));
        float uy = 1.0f/(1.0f + expf(-10.0f*x.y));
        float uz = 1.0f/(1.0f + expf(-10.0f*x.z));
        float uw = 1.0f/(1.0f + expf(-10.0f*x.w));
        bfsplit(ux,h0,l0); bfsplit(uy,h1,l1); bfsplit(uz,h2,l2); bfsplit(uw,h3,l3);
        int o = n*256 + q;
        reinterpret_cast<__nv_bfloat162*>(g_Hu_h)[o*2+0] = __halves2bfloat162(h0,h1);
        reinterpret_cast<__nv_bfloat162*>(g_Hu_h)[o*2+1] = __halves2bfloat162(h2,h3);
        reinterpret_cast<__nv_bfloat162*>(g_Hu_l)[o*2+0] = __halves2bfloat162(l0,l1);
        reinterpret_cast<__nv_bfloat162*>(g_Hu_l)[o*2+1] = __halves2bfloat162(l2,l3);
    }
}

// ---------------- softplus(U), biases, z0 constant ----------------
__global__ void prepIcnnK(const float* __restrict__ icU0, const float* __restrict__ icU1,
                          const float* __restrict__ icb0, const float* __restrict__ icb1,
                          const float* __restrict__ icb2){
    int tid = threadIdx.x;
    for (int i = tid; i < 64*64; i += blockDim.x) g_spU0[i] = softplusf(icU0[i]);
    if (tid < 64){
        g_spU1[tid]     = softplusf(icU1[tid]);
        g_cb01[tid]     = icb0[tid];
        g_cb01[64+tid]  = icb1[tid];
    }
    __syncthreads();
    __shared__ float z0a[64], z0b[64];
    if (tid < 64) z0a[tid] = srelu(icb0[tid]);
    __syncthreads();
    if (tid < 64){
        float s = icb1[tid];
        #pragma unroll 8
        for (int j=0;j<64;j++) s += g_spU0[tid*64+j]*z0a[j];
        z0b[tid] = srelu(s);
    }
    __syncthreads();
    if (tid == 0){
        float s = icb2[0];
        for (int j=0;j<64;j++) s += g_spU1[j]*z0b[j];
        g_z0[0] = srelu(s);
    }
}

// ---------------- z2 ----------------
__global__ void z2K(){
    __shared__ float sUT[64*64];
    __shared__ float z1s[4][64];
    int t = threadIdx.x;
    for (int i = t; i < 4096; i += 256){
        int j = i >> 6, k = i & 63;
        sUT[i] = g_spU0[k*64 + j];
    }
    int r = t >> 6, k = t & 63;
    int n = blockIdx.x*4 + r;
    z1s[r][k] = srelu(g_Z01[n*128 + k]);
    __syncthreads();
    float s = g_Z01[n*128 + 64 + k];
    #pragma unroll 8
    for (int j=0;j<64;j++) s += sUT[j*64 + k]*z1s[r][j];
    g_Z2[n*64 + k] = srelu(s);
}

// ---------------- final assembly ----------------
__global__ void finalK(const float* __restrict__ state, const float* __restrict__ icW2,
                       const float* __restrict__ icb2, float* __restrict__ out){
    int n = blockIdx.x;
    int tid = threadIdx.x;
    const float* srow = state + (size_t)n*DIN2;
    const float4* srow4 = reinterpret_cast<const float4*>(srow);
    const float4* icW24 = reinterpret_cast<const float4*>(icW2);
    const float4* CT4   = reinterpret_cast<const float4*>(g_CT + (size_t)n*DIN2);

    float x0u = srow[0], x0v = srow[DIMH];

    float dot = 0.0f, ss = 0.0f;
    #pragma unroll
    for (int it=0; it<2; it++){
        int q = tid + it*256;
        float4 x = srow4[q], w = icW24[q];
        dot += w.x*x.x + w.y*x.y + w.z*x.z + w.w*x.w;
        ss  += x.x*x.x + x.y*x.y + x.z*x.z + x.w*x.w;
    }
    #pragma unroll
    for (int o=16;o>0;o>>=1){
        dot += __shfl_down_sync(0xffffffffu, dot, o);
        ss  += __shfl_down_sync(0xffffffffu, ss,  o);
    }
    __shared__ float sd[8], sq[8];
    if ((tid & 31) == 0){ sd[tid>>5] = dot; sq[tid>>5] = ss; }
    __syncthreads();
    if (tid == 0){
        float D = 0.0f, S = 0.0f;
        #pragma unroll
        for (int w=0;w<8;w++){ D += sd[w]; S += sq[w]; }
        float z = icb2[0] + D;
        for (int k=0;k<64;k++) z = fmaf(g_spU1[k], g_Z2[n*64+k], z);
        float z3 = srelu(z);
        out[(size_t)n*2049 + 2048] = srelu(z3 - g_z0[0]) + 0.001f*S;
    }

    #pragma unroll
    for (int it=0; it<2; it++){
        int q = tid + it*256;
        int d = q*4;
        float4 x  = srow4[q];
        float4 ct = CT4[q];
        float x0 = (d < DIMH) ? x0u : x0v;
        float r[4];
        float xv[4] = {x.x, x.y, x.z, x.w};
        float cv[4] = {ct.x, ct.y, ct.z, ct.w};
        if (d < DIMH){
            const float4 v4 = srow4[q + 256];
            const float4 gg = reinterpret_cast<const float4*>(g_G1 + (size_t)n*DIMH)[q];
            float vv[4] = {v4.x, v4.y, v4.z, v4.w};
            float gv[4] = {gg.x, gg.y, gg.z, gg.w};
            #pragma unroll
            for (int e=0;e<4;e++){
                float ux = cv[e]*(xv[e]-x0);
                float ctrl = (ux < 10.0f && ux > -10.0f) ? ux : 0.0f;
                float uu = xv[e];
                r[e] = uu - uu*uu*uu*(1.0f/3.0f) - vv[e] + 1.0f + gv[e] + ctrl;
            }
        } else {
            const float4 u4 = srow4[q - 256];
            float uv[4] = {u4.x, u4.y, u4.z, u4.w};
            #pragma unroll
            for (int e=0;e<4;e++){
                float ux = cv[e]*(xv[e]-x0);
                float ctrl = (ux < 10.0f && ux > -10.0f) ? ux : 0.0f;
                r[e] = 0.2f*(uv[e] + 0.7f - 0.8f*xv[e]) + ctrl;
            }
        }
        float* o = out + (size_t)n*2049 + d;
        o[0]=r[0]; o[1]=r[1]; o[2]=r[2]; o[3]=r[3];
    }
}

// ======== 3xBF16 mma.sync GEMM (split-2 bf16 operands, fp32 accum) ========
#define CPASYNC(dst, src) asm volatile("cp.async.cg.shared.global [%0], [%1], 16;\n" :: "r"(dst), "l"(src))
#define CPCOMMIT()        asm volatile("cp.async.commit_group;\n" ::: "memory")
#define CPWAIT(n)         asm volatile("cp.async.wait_group %0;\n" :: "n"(n) : "memory")

__device__ __forceinline__ void ldsm4(uint32_t addr, uint32_t& r0, uint32_t& r1,
                                      uint32_t& r2, uint32_t& r3){
    asm volatile("ldmatrix.sync.aligned.m8n8.x4.shared.b16 {%0,%1,%2,%3}, [%4];"
                 : "=r"(r0), "=r"(r1), "=r"(r2), "=r"(r3) : "r"(addr));
}
__device__ __forceinline__ void mma_bf16(float* d, const uint32_t* a, uint32_t b0, uint32_t b1){
    asm volatile("mma.sync.aligned.m16n8k16.row.col.f32.bf16.bf16.f32 "
                 "{%0,%1,%2,%3}, {%4,%5,%6,%7}, {%8,%9}, {%0,%1,%2,%3};"
                 : "+f"(d[0]), "+f"(d[1]), "+f"(d[2]), "+f"(d[3])
                 : "r"(a[0]), "r"(a[1]), "r"(a[2]), "r"(a[3]), "r"(b0), "r"(b1));
}

// C[M,N] = (Ah+Al)@(Bh+Bl)^T via hh+lh+hl. BK=32. TANH: tanh epi.
// SOUT=1: write bf16 split (Ch,Cl). SOUT=0: write fp32 Cf.
template<int BM, int BN, int STAGES, int TANH, int SOUT>
__global__ __launch_bounds__(256, 2)
void mmaGemmBF(int M, int N, int K,
               const bf16* __restrict__ Ah, const bf16* __restrict__ Al,
               const bf16* __restrict__ Bh, const bf16* __restrict__ Bl,
               const float* __restrict__ bias,
               float* __restrict__ Cf, bf16* __restrict__ Ch, bf16* __restrict__ Cl){
    constexpr int ROWB = 80;                 // 32 bf16 (64B) + 16B pad
    constexpr int offAl = BM*ROWB;
    constexpr int offBh = 2*BM*ROWB;
    constexpr int offBl = offBh + BN*ROWB;
    constexpr int STG   = 2*(BM+BN)*ROWB;
    constexpr int WARPS_M = BM/32;
    constexpr int WARPS_N = 8/WARPS_M;
    constexpr int WN = BN/WARPS_N;
    constexpr int NP = WN/16;

    extern __shared__ __align__(16) char smem[];

    const int tid  = threadIdx.x;
    const int warp = tid >> 5, lane = tid & 31;
    const int wm = (warp % WARPS_M)*32;
    const int wn = (warp / WARPS_M)*WN;
    const int bm = blockIdx.y*BM, bn = blockIdx.x*BN;

    const int lr  = lane & 15;               // ldmatrix row within 16
    const int lcb = (lane >> 4)*16;          // 16B column half

    float acc[2][2*NP][4];
    #pragma unroll
    for (int i=0;i<2;i++)
        #pragma unroll
        for (int j=0;j<2*NP;j++)
            #pragma unroll
            for (int q=0;q<4;q++) acc[i][j][q] = 0.0f;

    uint32_t sBase = (uint32_t)__cvta_generic_to_shared(smem);

    auto loadTile = [&](int buf, int k0){
        uint32_t st = sBase + buf*STG;
        #pragma unroll
        for (int i=0;i<(BM*4)/256;i++){
            int L = tid + i*256;
            int r = L>>2, c = L&3;
            CPASYNC(st + r*ROWB + c*16,         Ah + (size_t)(bm+r)*K + k0 + c*8);
            CPASYNC(st + offAl + r*ROWB + c*16, Al + (size_t)(bm+r)*K + k0 + c*8);
        }
        #pragma unroll
        for (int i=0;i<(BN*4)/256;i++){
            int L = tid + i*256;
            int r = L>>2, c = L&3;
            CPASYNC(st + offBh + r*ROWB + c*16, Bh + (size_t)(bn+r)*K + k0 + c*8);
            CPASYNC(st + offBl + r*ROWB + c*16, Bl + (size_t)(bn+r)*K + k0 + c*8);
        }
        CPCOMMIT();
    };

    const int nk = K / 32;
    #pragma unroll
    for (int p=0; p<STAGES-1; p++){
        if (p < nk) loadTile(p, p*32); else CPCOMMIT();
    }

    for (int ck = 0; ck < nk; ck++){
        CPWAIT(STAGES-2);
        __syncthreads();

        int nxt = ck + STAGES - 1;
        if (nxt < nk) loadTile(nxt % STAGES, nxt*32); else CPCOMMIT();

        uint32_t st = sBase + (ck % STAGES)*STG;
        #pragma unroll
        for (int ks=0; ks<2; ks++){                      // two k16 steps
            // A fragments for both m-tiles (hi+lo): 16 regs live
            uint32_t ah[2][4], al[2][4];
            #pragma unroll
            for (int mt=0; mt<2; mt++){
                uint32_t aoff = (uint32_t)((wm + mt*16 + lr)*ROWB) + ks*32 + lcb;
                ldsm4(st + aoff,         ah[mt][0], ah[mt][1], ah[mt][2], ah[mt][3]);
                ldsm4(st + offAl + aoff, al[mt][0], al[mt][1], al[mt][2], al[mt][3]);
            }
            // p-outer: B fragments transient (8 regs)
            #pragma unroll
            for (int p=0; p<NP; p++){
                uint32_t boff = (uint32_t)((wn + p*16 + lr)*ROWB) + ks*32 + lcb;
                uint32_t bh[4], bl[4];
                ldsm4(st + offBh + boff, bh[0], bh[1], bh[2], bh[3]);
                ldsm4(st + offBl + boff, bl[0], bl[1], bl[2], bl[3]);
                #pragma unroll
                for (int mt=0; mt<2; mt++){
                    // n-subtile 0: B regs {r0, r2}; subtile 1: {r1, r3}
                    mma_bf16(acc[mt][2*p+0], ah[mt], bh[0], bh[2]);
                    mma_bf16(acc[mt][2*p+1], ah[mt], bh[1], bh[3]);
                    mma_bf16(acc[mt][2*p+0], al[mt], bh[0], bh[2]);
                    mma_bf16(acc[mt][2*p+1], al[mt], bh[1], bh[3]);
                    mma_bf16(acc[mt][2*p+0], ah[mt], bl[0], bl[2]);
                    mma_bf16(acc[mt][2*p+1], ah[mt], bl[1], bl[3]);
                }
            }
        }
        __syncthreads();
    }

    const int tg = lane & 3, g = lane >> 2;
    #pragma unroll
    for (int mt=0; mt<2; mt++){
        #pragma unroll
        for (int nt=0; nt<2*NP; nt++){
            int p = nt >> 1, nsub = nt & 1;
            int row = bm + wm + mt*16 + g;
            int col = bn + wn + p*16 + nsub*8 + tg*2;
            float v0 = acc[mt][nt][0], v1 = acc[mt][nt][1];
            float v2 = acc[mt][nt][2], v3 = acc[mt][nt][3];
            if (bias){
                float b0v = bias[col], b1v = bias[col+1];
                v0 += b0v; v1 += b1v; v2 += b0v; v3 += b1v;
            }
            if (TANH){ v0 = tanhf(v0); v1 = tanhf(v1); v2 = tanhf(v2); v3 = tanhf(v3); }
            if (SOUT){
                bf16 h0,l0,h1,l1,h2,l2,h3,l3;
                bfsplit(v0,h0,l0); bfsplit(v1,h1,l1);
                bfsplit(v2,h2,l2); bfsplit(v3,h3,l3);
                *reinterpret_cast<__nv_bfloat162*>(Ch + (size_t)row*N + col)     = __halves2bfloat162(h0,h1);
                *reinterpret_cast<__nv_bfloat162*>(Ch + (size_t)(row+8)*N + col) = __halves2bfloat162(h2,h3);
                *reinterpret_cast<__nv_bfloat162*>(Cl + (size_t)row*N + col)     = __halves2bfloat162(l0,l1);
                *reinterpret_cast<__nv_bfloat162*>(Cl + (size_t)(row+8)*N + col) = __halves2bfloat162(l2,l3);
            } else {
                *reinterpret_cast<float2*>(Cf + (size_t)row*N + col)     = make_float2(v0, v1);
                *reinterpret_cast<float2*>(Cf + (size_t)(row+8)*N + col) = make_float2(v2, v3);
            }
        }
    }
}

// ---------------- host ----------------
extern "C" void kernel_launch(void* const* d_in, const int* in_sizes, int n_in,
                              void* d_out, int out_size){
    const float* state = (const float*)d_in[0];
    const float* t     = (const float*)d_in[1];
    const float* P     = (const float*)d_in[2];
    const float* W1    = (const float*)d_in[3];
    const float* b1    = (const float*)d_in[4];
    const float* W2    = (const float*)d_in[5];
    const float* b2    = (const float*)d_in[6];
    const float* W3    = (const float*)d_in[7];
    const float* b3    = (const float*)d_in[8];
    const float* icW0  = (const float*)d_in[9];
    const float* icb0  = (const float*)d_in[10];
    const float* icW1  = (const float*)d_in[11];
    const float* icb1  = (const float*)d_in[12];
    const float* icW2  = (const float*)d_in[13];
    const float* icb2  = (const float*)d_in[14];
    const float* icU0  = (const float*)d_in[15];
    const float* icU1  = (const float*)d_in[16];
    float* out = (float*)d_out;

    bf16 *Pt_h,*Pt_l,*PtSc_h,*PtSc_l,*Lm_h,*Lm_l,*Hu_h,*Hu_l,*st_h,*st_l,*sx_h,*sx_l;
    bf16 *W1_h,*W1_l,*W2_h,*W2_l,*W3_h,*W3_l,*icW_h,*icW_l,*H1_h,*H1_l,*H2_h,*H2_l;
    float *G1,*CT,*Z01,*cb01;
    cudaGetSymbolAddress((void**)&Pt_h,   g_Pt_h);   cudaGetSymbolAddress((void**)&Pt_l,   g_Pt_l);
    cudaGetSymbolAddress((void**)&PtSc_h, g_PtSc_h); cudaGetSymbolAddress((void**)&PtSc_l, g_PtSc_l);
    cudaGetSymbolAddress((void**)&Lm_h,   g_Lm_h);   cudaGetSymbolAddress((void**)&Lm_l,   g_Lm_l);
    cudaGetSymbolAddress((void**)&Hu_h,   g_Hu_h);   cudaGetSymbolAddress((void**)&Hu_l,   g_Hu_l);
    cudaGetSymbolAddress((void**)&st_h,   g_st_h);   cudaGetSymbolAddress((void**)&st_l,   g_st_l);
    cudaGetSymbolAddress((void**)&sx_h,   g_sx_h);   cudaGetSymbolAddress((void**)&sx_l,   g_sx_l);
    cudaGetSymbolAddress((void**)&W1_h,   g_W1_h);   cudaGetSymbolAddress((void**)&W1_l,   g_W1_l);
    cudaGetSymbolAddress((void**)&W2_h,   g_W2_h);   cudaGetSymbolAddress((void**)&W2_l,   g_W2_l);
    cudaGetSymbolAddress((void**)&W3_h,   g_W3_h);   cudaGetSymbolAddress((void**)&W3_l,   g_W3_l);
    cudaGetSymbolAddress((void**)&icW_h,  g_icW_h);  cudaGetSymbolAddress((void**)&icW_l,  g_icW_l);
    cudaGetSymbolAddress((void**)&H1_h,   g_H1_h);   cudaGetSymbolAddress((void**)&H1_l,   g_H1_l);
    cudaGetSymbolAddress((void**)&H2_h,   g_H2_h);   cudaGetSymbolAddress((void**)&H2_l,   g_H2_l);
    cudaGetSymbolAddress((void**)&G1,  g_G1);
    cudaGetSymbolAddress((void**)&CT,  g_CT);
    cudaGetSymbolAddress((void**)&Z01, g_Z01);
    cudaGetSymbolAddress((void**)&cb01,g_cb01);

    const int sm128 = 2*2*(128+128)*80;   // 81920  -> 2 CTAs/SM
    const int smLm  = 2*2*( 64+128)*80;   // 61440  -> 2 CTAs/SM
    const int smZ   = 4*2*( 64+ 64)*80;   // 81920  -> 2 CTAs/SM

    // One-time setup on FIRST call (correctness run, outside graph capture).
    // Statics are only *used* (never created) during the capture call.
    static cudaStream_t s1 = nullptr;
    static cudaEvent_t evFork = nullptr, evHu = nullptr, evJoin = nullptr;
    if (s1 == nullptr){
        cudaFuncSetAttribute((const void*)mmaGemmBF<64,128,2,0,1>,  cudaFuncAttributeMaxDynamicSharedMemorySize, smLm);
        cudaFuncSetAttribute((const void*)mmaGemmBF<128,128,2,0,0>, cudaFuncAttributeMaxDynamicSharedMemorySize, sm128);
        cudaFuncSetAttribute((const void*)mmaGemmBF<128,128,2,1,1>, cudaFuncAttributeMaxDynamicSharedMemorySize, sm128);
        cudaFuncSetAttribute((const void*)mmaGemmBF<64,64,4,0,0>,   cudaFuncAttributeMaxDynamicSharedMemorySize, smZ);
        cudaStreamCreateWithFlags(&s1, cudaStreamNonBlocking);
        cudaEventCreateWithFlags(&evFork, cudaEventDisableTiming);
        cudaEventCreateWithFlags(&evHu,   cudaEventDisableTiming);
        cudaEventCreateWithFlags(&evJoin, cudaEventDisableTiming);
    }

    // ---- dual-stream schedule (fork/join via events; capture-safe) ----
    cudaEventRecord(evFork, 0);
    cudaStreamWaitEvent(s1, evFork, 0);

    // ----- stream s1 chain -----
    transposePK<<<dim3(32,32), dim3(32,8), 0, s1>>>(P, t);
    catIcWK<<<(64*DIN2)/256, 256, 0, s1>>>(icW0, icW1);
    prepIcnnK<<<1, 256, 0, s1>>>(icU0, icU1, icb0, icb1, icb2);
    // Lm = PtSc @ Pt^T  (1024x1024x1024) -> bf16 split output
    mmaGemmBF<64,128,2,0,1><<<dim3(8,16), 256, smLm, s1>>>(1024, 1024, 1024,
        PtSc_h, PtSc_l, Pt_h, Pt_l, nullptr, nullptr, Lm_h, Lm_l);

    // ----- stream 0 chain -----
    splitWK<<<(512*DIN2/4+255)/256, 256>>>(W1, W1_h, W1_l, 512*DIN2/4);
    huStK<<<(NROWS*512)/256, 256>>>(state);
    cudaEventRecord(evHu, 0);
    // H1 = tanh(st @ W1^T + b1) (4096x512x2048) -> bf16 split
    mmaGemmBF<128,128,2,1,1><<<dim3(4,32), 256, sm128>>>(NROWS, 512, 2048,
        st_h, st_l, W1_h, W1_l, b1, nullptr, H1_h, H1_l);
    splitWK<<<(512*512 /4+255)/256, 256>>>(W2, W2_h, W2_l, 512*512/4);
    // H2 = tanh(H1 @ W2^T + b2) (4096x512x512) -> bf16 split
    mmaGemmBF<128,128,2,1,1><<<dim3(4,32), 256, sm128>>>(NROWS, 512, 512,
        H1_h, H1_l, W2_h, W2_l, b2, nullptr, H2_h, H2_l);
    splitWK<<<(DIN2*512/4+255)/256, 256>>>(W3, W3_h, W3_l, DIN2*512/4);
    // CT = H2 @ W3^T + b3       (4096x2048x512) -> fp32
    mmaGemmBF<128,128,2,0,0><<<dim3(16,32), 256, sm128>>>(NROWS, 2048, 512,
        H2_h, H2_l, W3_h, W3_l, b3, CT, nullptr, nullptr);

    // ----- stream s1: G1 needs Hu (evHu) + Lm -----
    cudaStreamWaitEvent(s1, evHu, 0);
    // G1 = Hu @ Lm (symmetric)  (4096x1024x1024) -> fp32
    mmaGemmBF<128,128,2,0,0><<<dim3(8,32), 256, sm128, s1>>>(NROWS, 1024, 1024,
        Hu_h, Hu_l, Lm_h, Lm_l, nullptr, G1, nullptr, nullptr);
    // Z01 = state @ icW^T + cb01 (4096x128x2048) -> fp32 (needs sx from huStK: covered by evHu)
    mmaGemmBF<64,64,4,0,0><<<dim3(2,64), 256, smZ, s1>>>(NROWS, 128, 2048,
        sx_h, sx_l, icW_h, icW_l, cb01, Z01, nullptr, nullptr);
    z2K<<<NROWS/4, 256, 0, s1>>>();
    cudaEventRecord(evJoin, s1);

    // ----- join + final on stream 0 -----
    cudaStreamWaitEvent(0, evJoin, 0);
    finalK<<<NROWS, 256>>>(state, icW2, icb2, out);
}

// round 16
// speedup vs baseline: 2.3595x; 1.0865x over previous
#include <cuda_runtime.h>
#include <cuda_bf16.h>
#include <math.h>
#include <stdint.h>

#define NROWS 4096
#define DIMH  1024
#define DIN2  2048

typedef __nv_bfloat16 bf16;

// ---------------- helpers ----------------
__device__ __forceinline__ float srelu(float x){
    float r = fmaxf(x, 0.0f);
    if (r < 0.1f){ float r2 = r*r; return (0.2f*r*r2 - r2*r2) * 500.0f; }
    return x - 0.05f;
}
__device__ __forceinline__ float softplusf(float x){
    return fmaxf(x, 0.0f) + log1pf(expf(-fabsf(x)));
}
__device__ __forceinline__ void bfsplit(float x, bf16& h, bf16& l){
    h = __float2bfloat16_rn(x);
    l = __float2bfloat16_rn(x - __bfloat162float(h));
}

// ---------------- scratch (device globals) ----------------
__device__ bf16  g_Pt_h  [DIMH*DIMH],  g_Pt_l  [DIMH*DIMH];
__device__ bf16  g_PtSc_h[DIMH*DIMH],  g_PtSc_l[DIMH*DIMH];
__device__ bf16  g_Lm_h  [DIMH*DIMH],  g_Lm_l  [DIMH*DIMH];
__device__ bf16  g_Hu_h  [NROWS*DIMH], g_Hu_l  [NROWS*DIMH];
__device__ bf16  g_st_h  [NROWS*DIN2], g_st_l  [NROWS*DIN2];
__device__ bf16  g_sx_h  [NROWS*DIN2], g_sx_l  [NROWS*DIN2];
__device__ bf16  g_W1_h  [512*DIN2],   g_W1_l  [512*DIN2];
__device__ bf16  g_W2_h  [512*512],    g_W2_l  [512*512];
__device__ bf16  g_W3_h  [DIN2*512],   g_W3_l  [DIN2*512];
__device__ bf16  g_icW_h [128*DIN2],   g_icW_l [128*DIN2];
__device__ bf16  g_H1_h  [NROWS*512],  g_H1_l  [NROWS*512];
__device__ bf16  g_H2_h  [NROWS*512],  g_H2_l  [NROWS*512];
__device__ float g_G1    [NROWS*DIMH];
__device__ float g_CT    [NROWS*DIN2];
__device__ float g_Z01   [NROWS*128];
__device__ float g_Z2    [NROWS*64];
__device__ float g_spU0  [64*64];
__device__ float g_spU1  [64];
__device__ float g_cb01  [128];
__device__ float g_z0    [1];

// ---------------- P transpose + eig scale + bf16 split ----------------
__global__ void transposePK(const float* __restrict__ P, const float* __restrict__ t){
    __shared__ float tile[32][33];
    int c0 = blockIdx.x*32, r0 = blockIdx.y*32;
    int x = threadIdx.x, y = threadIdx.y;
    float s = 2.0f * sinf(t[0]);
    #pragma unroll
    for (int i=0;i<32;i+=8)
        tile[y+i][x] = P[(size_t)(r0+y+i)*DIMH + c0 + x];
    __syncthreads();
    #pragma unroll
    for (int i=0;i<32;i+=8){
        int c = c0 + y + i;
        int r = r0 + x;
        float v = tile[x][y+i];
        float e = (r == 0) ? 0.0f : ((r <= 511) ? (1.0f + s) : (1.0f - s));
        float ev = e * v;
        size_t o = (size_t)c*DIMH + r;
        bf16 h, l;
        bfsplit(v,  h, l); g_Pt_h[o]   = h; g_Pt_l[o]   = l;
        bfsplit(ev, h, l); g_PtSc_h[o] = h; g_PtSc_l[o] = l;
    }
}

// ---------------- concat icW0/icW1 + split ----------------
__global__ void catIcWK(const float* __restrict__ w0, const float* __restrict__ w1){
    int i = blockIdx.x*256 + threadIdx.x;
    bf16 h, l;
    bfsplit(w0[i], h, l); g_icW_h[i] = h; g_icW_l[i] = l;
    bfsplit(w1[i], h, l); g_icW_h[64*DIN2+i] = h; g_icW_l[64*DIN2+i] = l;
}

// ---------------- generic weight split ----------------
__global__ void splitWK(const float* __restrict__ in, bf16* __restrict__ hi,
                        bf16* __restrict__ lo, int n4){
    int i = blockIdx.x*256 + threadIdx.x;
    if (i >= n4) return;
    float4 x = reinterpret_cast<const float4*>(in)[i];
    bf16 h0,l0,h1,l1,h2,l2,h3,l3;
    bfsplit(x.x,h0,l0); bfsplit(x.y,h1,l1); bfsplit(x.z,h2,l2); bfsplit(x.w,h3,l3);
    reinterpret_cast<__nv_bfloat162*>(hi)[i*2+0] = __halves2bfloat162(h0,h1);
    reinterpret_cast<__nv_bfloat162*>(hi)[i*2+1] = __halves2bfloat162(h2,h3);
    reinterpret_cast<__nv_bfloat162*>(lo)[i*2+0] = __halves2bfloat162(l0,l1);
    reinterpret_cast<__nv_bfloat162*>(lo)[i*2+1] = __halves2bfloat162(l2,l3);
}

// ---------------- Hu / st / state splits ----------------
__global__ void huStK(const float* __restrict__ state){
    int idx = blockIdx.x*blockDim.x + threadIdx.x;   // NROWS*512 float4s
    int n = idx >> 9, q = idx & 511;
    const float4* s4 = reinterpret_cast<const float4*>(state);
    float4 x = s4[idx];
    float x0 = state[(n<<11) + (q < 256 ? 0 : DIMH)];
    bf16 h0,l0,h1,l1,h2,l2,h3,l3;

    bfsplit(x.x,h0,l0); bfsplit(x.y,h1,l1); bfsplit(x.z,h2,l2); bfsplit(x.w,h3,l3);
    reinterpret_cast<__nv_bfloat162*>(g_sx_h)[idx*2+0] = __halves2bfloat162(h0,h1);
    reinterpret_cast<__nv_bfloat162*>(g_sx_h)[idx*2+1] = __halves2bfloat162(h2,h3);
    reinterpret_cast<__nv_bfloat162*>(g_sx_l)[idx*2+0] = __halves2bfloat162(l0,l1);
    reinterpret_cast<__nv_bfloat162*>(g_sx_l)[idx*2+1] = __halves2bfloat162(l2,l3);

    bfsplit(x.x-x0,h0,l0); bfsplit(x.y-x0,h1,l1); bfsplit(x.z-x0,h2,l2); bfsplit(x.w-x0,h3,l3);
    reinterpret_cast<__nv_bfloat162*>(g_st_h)[idx*2+0] = __halves2bfloat162(h0,h1);
    reinterpret_cast<__nv_bfloat162*>(g_st_h)[idx*2+1] = __halves2bfloat162(h2,h3);
    reinterpret_cast<__nv_bfloat162*>(g_st_l)[idx*2+0] = __halves2bfloat162(l0,l1);
    reinterpret_cast<__nv_bfloat162*>(g_st_l)[idx*2+1] = __halves2bfloat162(l2,l3);

    if (q < 256){
        float ux = 1.0f/(1.0f + expf(-10.0f*x.x));
        float uy = 1.0f/(1.0f + expf(-10.0f*x.y));
        float uz = 1.0f/(1.0f + expf(-10.0f*x.z));
        float uw = 1.0f/(1.0f + expf(-10.0f*x.w));
        bfsplit(ux,h0,l0); bfsplit(uy,h1,l1); bfsplit(uz,h2,l2); bfsplit(uw,h3,l3);
        int o = n*256 + q;
        reinterpret_cast<__nv_bfloat162*>(g_Hu_h)[o*2+0] = __halves2bfloat162(h0,h1);
        reinterpret_cast<__nv_bfloat162*>(g_Hu_h)[o*2+1] = __halves2bfloat162(h2,h3);
        reinterpret_cast<__nv_bfloat162*>(g_Hu_l)[o*2+0] = __halves2bfloat162(l0,l1);
        reinterpret_cast<__nv_bfloat162*>(g_Hu_l)[o*2+1] = __halves2bfloat162(l2,l3);
    }
}

// ---------------- softplus(U), biases, z0 constant ----------------
__global__ void prepIcnnK(const float* __restrict__ icU0, const float* __restrict__ icU1,
                          const float* __restrict__ icb0, const float* __restrict__ icb1,
                          const float* __restrict__ icb2){
    int tid = threadIdx.x;
    for (int i = tid; i < 64*64; i += blockDim.x) g_spU0[i] = softplusf(icU0[i]);
    if (tid < 64){
        g_spU1[tid]     = softplusf(icU1[tid]);
        g_cb01[tid]     = icb0[tid];
        g_cb01[64+tid]  = icb1[tid];
    }
    __syncthreads();
    __shared__ float z0a[64], z0b[64];
    if (tid < 64) z0a[tid] = srelu(icb0[tid]);
    __syncthreads();
    if (tid < 64){
        float s = icb1[tid];
        #pragma unroll 8
        for (int j=0;j<64;j++) s += g_spU0[tid*64+j]*z0a[j];
        z0b[tid] = srelu(s);
    }
    __syncthreads();
    if (tid == 0){
        float s = icb2[0];
        for (int j=0;j<64;j++) s += g_spU1[j]*z0b[j];
        g_z0[0] = srelu(s);
    }
}

// ---------------- z2 ----------------
__global__ void z2K(){
    __shared__ float sUT[64*64];
    __shared__ float z1s[4][64];
    int t = threadIdx.x;
    for (int i = t; i < 4096; i += 256){
        int j = i >> 6, k = i & 63;
        sUT[i] = g_spU0[k*64 + j];
    }
    int r = t >> 6, k = t & 63;
    int n = blockIdx.x*4 + r;
    z1s[r][k] = srelu(g_Z01[n*128 + k]);
    __syncthreads();
    float s = g_Z01[n*128 + 64 + k];
    #pragma unroll 8
    for (int j=0;j<64;j++) s += sUT[j*64 + k]*z1s[r][j];
    g_Z2[n*64 + k] = srelu(s);
}

// ---------------- final assembly ----------------
__global__ void finalK(const float* __restrict__ state, const float* __restrict__ icW2,
                       const float* __restrict__ icb2, float* __restrict__ out){
    int n = blockIdx.x;
    int tid = threadIdx.x;
    const float* srow = state + (size_t)n*DIN2;
    const float4* srow4 = reinterpret_cast<const float4*>(srow);
    const float4* icW24 = reinterpret_cast<const float4*>(icW2);
    const float4* CT4   = reinterpret_cast<const float4*>(g_CT + (size_t)n*DIN2);

    float x0u = srow[0], x0v = srow[DIMH];

    float dot = 0.0f, ss = 0.0f;
    #pragma unroll
    for (int it=0; it<2; it++){
        int q = tid + it*256;
        float4 x = srow4[q], w = icW24[q];
        dot += w.x*x.x + w.y*x.y + w.z*x.z + w.w*x.w;
        ss  += x.x*x.x + x.y*x.y + x.z*x.z + x.w*x.w;
    }
    #pragma unroll
    for (int o=16;o>0;o>>=1){
        dot += __shfl_down_sync(0xffffffffu, dot, o);
        ss  += __shfl_down_sync(0xffffffffu, ss,  o);
    }
    __shared__ float sd[8], sq[8];
    if ((tid & 31) == 0){ sd[tid>>5] = dot; sq[tid>>5] = ss; }
    __syncthreads();
    if (tid == 0){
        float D = 0.0f, S = 0.0f;
        #pragma unroll
        for (int w=0;w<8;w++){ D += sd[w]; S += sq[w]; }
        float z = icb2[0] + D;
        for (int k=0;k<64;k++) z = fmaf(g_spU1[k], g_Z2[n*64+k], z);
        float z3 = srelu(z);
        out[(size_t)n*2049 + 2048] = srelu(z3 - g_z0[0]) + 0.001f*S;
    }

    #pragma unroll
    for (int it=0; it<2; it++){
        int q = tid + it*256;
        int d = q*4;
        float4 x  = srow4[q];
        float4 ct = CT4[q];
        float x0 = (d < DIMH) ? x0u : x0v;
        float r[4];
        float xv[4] = {x.x, x.y, x.z, x.w};
        float cv[4] = {ct.x, ct.y, ct.z, ct.w};
        if (d < DIMH){
            const float4 v4 = srow4[q + 256];
            const float4 gg = reinterpret_cast<const float4*>(g_G1 + (size_t)n*DIMH)[q];
            float vv[4] = {v4.x, v4.y, v4.z, v4.w};
            float gv[4] = {gg.x, gg.y, gg.z, gg.w};
            #pragma unroll
            for (int e=0;e<4;e++){
                float ux = cv[e]*(xv[e]-x0);
                float ctrl = (ux < 10.0f && ux > -10.0f) ? ux : 0.0f;
                float uu = xv[e];
                r[e] = uu - uu*uu*uu*(1.0f/3.0f) - vv[e] + 1.0f + gv[e] + ctrl;
            }
        } else {
            const float4 u4 = srow4[q - 256];
            float uv[4] = {u4.x, u4.y, u4.z, u4.w};
            #pragma unroll
            for (int e=0;e<4;e++){
                float ux = cv[e]*(xv[e]-x0);
                float ctrl = (ux < 10.0f && ux > -10.0f) ? ux : 0.0f;
                r[e] = 0.2f*(uv[e] + 0.7f - 0.8f*xv[e]) + ctrl;
            }
        }
        float* o = out + (size_t)n*2049 + d;
        o[0]=r[0]; o[1]=r[1]; o[2]=r[2]; o[3]=r[3];
    }
}

// ======== 3xBF16 mma.sync GEMM (split-2 bf16, XOR-swizzled smem, fp32 accum) ========
#define CPASYNC(dst, src) asm volatile("cp.async.cg.shared.global [%0], [%1], 16;\n" :: "r"(dst), "l"(src))
#define CPCOMMIT()        asm volatile("cp.async.commit_group;\n" ::: "memory")
#define CPWAIT(n)         asm volatile("cp.async.wait_group %0;\n" :: "n"(n) : "memory")

__device__ __forceinline__ void ldsm4(uint32_t addr, uint32_t& r0, uint32_t& r1,
                                      uint32_t& r2, uint32_t& r3){
    asm volatile("ldmatrix.sync.aligned.m8n8.x4.shared.b16 {%0,%1,%2,%3}, [%4];"
                 : "=r"(r0), "=r"(r1), "=r"(r2), "=r"(r3) : "r"(addr));
}
__device__ __forceinline__ void mma_bf16(float* d, const uint32_t* a, uint32_t b0, uint32_t b1){
    asm volatile("mma.sync.aligned.m16n8k16.row.col.f32.bf16.bf16.f32 "
                 "{%0,%1,%2,%3}, {%4,%5,%6,%7}, {%8,%9}, {%0,%1,%2,%3};"
                 : "+f"(d[0]), "+f"(d[1]), "+f"(d[2]), "+f"(d[3])
                 : "r"(a[0]), "r"(a[1]), "r"(a[2]), "r"(a[3]), "r"(b0), "r"(b1));
}

// row = tile row, chunk = 16B chunk index (0..3) within 64B row.
// swizzled byte offset within tile: row*64 + (chunk ^ ((row>>1)&3))*16
__device__ __forceinline__ uint32_t swz(int row, int chunk){
    return (uint32_t)(row*64 + ((chunk ^ ((row>>1)&3))*16));
}

// C[M,N] = (Ah+Al)@(Bh+Bl)^T via hh+lh+hl. BK=32. TANH: tanh epi.
// SOUT=1: write bf16 split (Ch,Cl). SOUT=0: write fp32 Cf.
template<int BM, int BN, int STAGES, int TANH, int SOUT>
__global__ __launch_bounds__(256, 2)
void mmaGemmBF(int M, int N, int K,
               const bf16* __restrict__ Ah, const bf16* __restrict__ Al,
               const bf16* __restrict__ Bh, const bf16* __restrict__ Bl,
               const float* __restrict__ bias,
               float* __restrict__ Cf, bf16* __restrict__ Ch, bf16* __restrict__ Cl){
    constexpr int ROWB = 64;                 // 32 bf16, XOR-swizzled (no padding)
    constexpr int offAl = BM*ROWB;
    constexpr int offBh = 2*BM*ROWB;
    constexpr int offBl = offBh + BN*ROWB;
    constexpr int STG   = 2*(BM+BN)*ROWB;
    constexpr int WARPS_M = BM/32;
    constexpr int WARPS_N = 8/WARPS_M;
    constexpr int WN = BN/WARPS_N;
    constexpr int NP = WN/16;

    extern __shared__ __align__(16) char smem[];

    const int tid  = threadIdx.x;
    const int warp = tid >> 5, lane = tid & 31;
    const int wm = (warp % WARPS_M)*32;
    const int wn = (warp / WARPS_M)*WN;
    const int bm = blockIdx.y*BM, bn = blockIdx.x*BN;

    const int lr  = lane & 15;               // ldmatrix row within 16
    const int lch = lane >> 4;               // 16B chunk half (0/1) within k16 step

    float acc[2][2*NP][4];
    #pragma unroll
    for (int i=0;i<2;i++)
        #pragma unroll
        for (int j=0;j<2*NP;j++)
            #pragma unroll
            for (int q=0;q<4;q++) acc[i][j][q] = 0.0f;

    uint32_t sBase = (uint32_t)__cvta_generic_to_shared(smem);

    auto loadTile = [&](int buf, int k0){
        uint32_t st = sBase + buf*STG;
        #pragma unroll
        for (int i=0;i<(BM*4)/256;i++){
            int L = tid + i*256;
            int r = L>>2, c = L&3;
            uint32_t o = swz(r, c);
            CPASYNC(st + o,         Ah + (size_t)(bm+r)*K + k0 + c*8);
            CPASYNC(st + offAl + o, Al + (size_t)(bm+r)*K + k0 + c*8);
        }
        #pragma unroll
        for (int i=0;i<(BN*4)/256;i++){
            int L = tid + i*256;
            int r = L>>2, c = L&3;
            uint32_t o = swz(r, c);
            CPASYNC(st + offBh + o, Bh + (size_t)(bn+r)*K + k0 + c*8);
            CPASYNC(st + offBl + o, Bl + (size_t)(bn+r)*K + k0 + c*8);
        }
        CPCOMMIT();
    };

    const int nk = K / 32;
    #pragma unroll
    for (int p=0; p<STAGES-1; p++){
        if (p < nk) loadTile(p, p*32); else CPCOMMIT();
    }

    for (int ck = 0; ck < nk; ck++){
        CPWAIT(STAGES-2);
        __syncthreads();

        int nxt = ck + STAGES - 1;
        if (nxt < nk) loadTile(nxt % STAGES, nxt*32); else CPCOMMIT();

        uint32_t st = sBase + (ck % STAGES)*STG;
        #pragma unroll
        for (int ks=0; ks<2; ks++){                      // two k16 steps
            const int chunk = ks*2 + lch;                // 16B chunk index for this lane
            // A fragments for both m-tiles (hi+lo): 16 regs live
            uint32_t ah[2][4], al[2][4];
            #pragma unroll
            for (int mt=0; mt<2; mt++){
                uint32_t aoff = swz(wm + mt*16 + lr, chunk);
                ldsm4(st + aoff,         ah[mt][0], ah[mt][1], ah[mt][2], ah[mt][3]);
                ldsm4(st + offAl + aoff, al[mt][0], al[mt][1], al[mt][2], al[mt][3]);
            }
            // p-outer: B fragments transient (8 regs)
            #pragma unroll
            for (int p=0; p<NP; p++){
                uint32_t boff = swz(wn + p*16 + lr, chunk);
                uint32_t bh[4], bl[4];
                ldsm4(st + offBh + boff, bh[0], bh[1], bh[2], bh[3]);
                ldsm4(st + offBl + boff, bl[0], bl[1], bl[2], bl[3]);
                #pragma unroll
                for (int mt=0; mt<2; mt++){
                    // n-subtile 0: B regs {r0, r2}; subtile 1: {r1, r3}
                    mma_bf16(acc[mt][2*p+0], ah[mt], bh[0], bh[2]);
                    mma_bf16(acc[mt][2*p+1], ah[mt], bh[1], bh[3]);
                    mma_bf16(acc[mt][2*p+0], al[mt], bh[0], bh[2]);
                    mma_bf16(acc[mt][2*p+1], al[mt], bh[1], bh[3]);
                    mma_bf16(acc[mt][2*p+0], ah[mt], bl[0], bl[2]);
                    mma_bf16(acc[mt][2*p+1], ah[mt], bl[1], bl[3]);
                }
            }
        }
        __syncthreads();
    }

    const int tg = lane & 3, g = lane >> 2;
    #pragma unroll
    for (int mt=0; mt<2; mt++){
        #pragma unroll
        for (int nt=0; nt<2*NP; nt++){
            int p = nt >> 1, nsub = nt & 1;
            int row = bm + wm + mt*16 + g;
            int col = bn + wn + p*16 + nsub*8 + tg*2;
            float v0 = acc[mt][nt][0], v1 = acc[mt][nt][1];
            float v2 = acc[mt][nt][2], v3 = acc[mt][nt][3];
            if (bias){
                float b0v = bias[col], b1v = bias[col+1];
                v0 += b0v; v1 += b1v; v2 += b0v; v3 += b1v;
            }
            if (TANH){ v0 = tanhf(v0); v1 = tanhf(v1); v2 = tanhf(v2); v3 = tanhf(v3); }
            if (SOUT){
                bf16 h0,l0,h1,l1,h2,l2,h3,l3;
                bfsplit(v0,h0,l0); bfsplit(v1,h1,l1);
                bfsplit(v2,h2,l2); bfsplit(v3,h3,l3);
                *reinterpret_cast<__nv_bfloat162*>(Ch + (size_t)row*N + col)     = __halves2bfloat162(h0,h1);
                *reinterpret_cast<__nv_bfloat162*>(Ch + (size_t)(row+8)*N + col) = __halves2bfloat162(h2,h3);
                *reinterpret_cast<__nv_bfloat162*>(Cl + (size_t)row*N + col)     = __halves2bfloat162(l0,l1);
                *reinterpret_cast<__nv_bfloat162*>(Cl + (size_t)(row+8)*N + col) = __halves2bfloat162(l2,l3);
            } else {
                *reinterpret_cast<float2*>(Cf + (size_t)row*N + col)     = make_float2(v0, v1);
                *reinterpret_cast<float2*>(Cf + (size_t)(row+8)*N + col) = make_float2(v2, v3);
            }
        }
    }
}

// ---------------- host ----------------
extern "C" void kernel_launch(void* const* d_in, const int* in_sizes, int n_in,
                              void* d_out, int out_size){
    const float* state = (const float*)d_in[0];
    const float* t     = (const float*)d_in[1];
    const float* P     = (const float*)d_in[2];
    const float* W1    = (const float*)d_in[3];
    const float* b1    = (const float*)d_in[4];
    const float* W2    = (const float*)d_in[5];
    const float* b2    = (const float*)d_in[6];
    const float* W3    = (const float*)d_in[7];
    const float* b3    = (const float*)d_in[8];
    const float* icW0  = (const float*)d_in[9];
    const float* icb0  = (const float*)d_in[10];
    const float* icW1  = (const float*)d_in[11];
    const float* icb1  = (const float*)d_in[12];
    const float* icW2  = (const float*)d_in[13];
    const float* icb2  = (const float*)d_in[14];
    const float* icU0  = (const float*)d_in[15];
    const float* icU1  = (const float*)d_in[16];
    float* out = (float*)d_out;

    bf16 *Pt_h,*Pt_l,*PtSc_h,*PtSc_l,*Lm_h,*Lm_l,*Hu_h,*Hu_l,*st_h,*st_l,*sx_h,*sx_l;
    bf16 *W1_h,*W1_l,*W2_h,*W2_l,*W3_h,*W3_l,*icW_h,*icW_l,*H1_h,*H1_l,*H2_h,*H2_l;
    float *G1,*CT,*Z01,*cb01;
    cudaGetSymbolAddress((void**)&Pt_h,   g_Pt_h);   cudaGetSymbolAddress((void**)&Pt_l,   g_Pt_l);
    cudaGetSymbolAddress((void**)&PtSc_h, g_PtSc_h); cudaGetSymbolAddress((void**)&PtSc_l, g_PtSc_l);
    cudaGetSymbolAddress((void**)&Lm_h,   g_Lm_h);   cudaGetSymbolAddress((void**)&Lm_l,   g_Lm_l);
    cudaGetSymbolAddress((void**)&Hu_h,   g_Hu_h);   cudaGetSymbolAddress((void**)&Hu_l,   g_Hu_l);
    cudaGetSymbolAddress((void**)&st_h,   g_st_h);   cudaGetSymbolAddress((void**)&st_l,   g_st_l);
    cudaGetSymbolAddress((void**)&sx_h,   g_sx_h);   cudaGetSymbolAddress((void**)&sx_l,   g_sx_l);
    cudaGetSymbolAddress((void**)&W1_h,   g_W1_h);   cudaGetSymbolAddress((void**)&W1_l,   g_W1_l);
    cudaGetSymbolAddress((void**)&W2_h,   g_W2_h);   cudaGetSymbolAddress((void**)&W2_l,   g_W2_l);
    cudaGetSymbolAddress((void**)&W3_h,   g_W3_h);   cudaGetSymbolAddress((void**)&W3_l,   g_W3_l);
    cudaGetSymbolAddress((void**)&icW_h,  g_icW_h);  cudaGetSymbolAddress((void**)&icW_l,  g_icW_l);
    cudaGetSymbolAddress((void**)&H1_h,   g_H1_h);   cudaGetSymbolAddress((void**)&H1_l,   g_H1_l);
    cudaGetSymbolAddress((void**)&H2_h,   g_H2_h);   cudaGetSymbolAddress((void**)&H2_l,   g_H2_l);
    cudaGetSymbolAddress((void**)&G1,  g_G1);
    cudaGetSymbolAddress((void**)&CT,  g_CT);
    cudaGetSymbolAddress((void**)&Z01, g_Z01);
    cudaGetSymbolAddress((void**)&cb01,g_cb01);

    const int sm128 = 3*2*(128+128)*64;   // 98304  -> 2 CTAs/SM
    const int smLm  = 3*2*( 64+128)*64;   // 73728  -> 2 CTAs/SM
    const int smZ   = 4*2*( 64+ 64)*64;   // 65536  -> 2 CTAs/SM

    // One-time setup on FIRST call (correctness run, outside graph capture).
    static cudaStream_t s1 = nullptr;
    static cudaEvent_t evFork = nullptr, evHu = nullptr, evJoin = nullptr;
    if (s1 == nullptr){
        cudaFuncSetAttribute((const void*)mmaGemmBF<64,128,3,0,1>,  cudaFuncAttributeMaxDynamicSharedMemorySize, smLm);
        cudaFuncSetAttribute((const void*)mmaGemmBF<128,128,3,0,0>, cudaFuncAttributeMaxDynamicSharedMemorySize, sm128);
        cudaFuncSetAttribute((const void*)mmaGemmBF<128,128,3,1,1>, cudaFuncAttributeMaxDynamicSharedMemorySize, sm128);
        cudaFuncSetAttribute((const void*)mmaGemmBF<64,64,4,0,0>,   cudaFuncAttributeMaxDynamicSharedMemorySize, smZ);
        cudaStreamCreateWithFlags(&s1, cudaStreamNonBlocking);
        cudaEventCreateWithFlags(&evFork, cudaEventDisableTiming);
        cudaEventCreateWithFlags(&evHu,   cudaEventDisableTiming);
        cudaEventCreateWithFlags(&evJoin, cudaEventDisableTiming);
    }

    // ---- dual-stream schedule (fork/join via events; capture-safe) ----
    cudaEventRecord(evFork, 0);
    cudaStreamWaitEvent(s1, evFork, 0);

    // ----- stream s1 chain -----
    transposePK<<<dim3(32,32), dim3(32,8), 0, s1>>>(P, t);
    catIcWK<<<(64*DIN2)/256, 256, 0, s1>>>(icW0, icW1);
    prepIcnnK<<<1, 256, 0, s1>>>(icU0, icU1, icb0, icb1, icb2);
    // Lm = PtSc @ Pt^T  (1024x1024x1024) -> bf16 split output
    mmaGemmBF<64,128,3,0,1><<<dim3(8,16), 256, smLm, s1>>>(1024, 1024, 1024,
        PtSc_h, PtSc_l, Pt_h, Pt_l, nullptr, nullptr, Lm_h, Lm_l);

    // ----- stream 0 chain -----
    splitWK<<<(512*DIN2/4+255)/256, 256>>>(W1, W1_h, W1_l, 512*DIN2/4);
    huStK<<<(NROWS*512)/256, 256>>>(state);
    cudaEventRecord(evHu, 0);
    // H1 = tanh(st @ W1^T + b1) (4096x512x2048) -> bf16 split
    mmaGemmBF<128,128,3,1,1><<<dim3(4,32), 256, sm128>>>(NROWS, 512, 2048,
        st_h, st_l, W1_h, W1_l, b1, nullptr, H1_h, H1_l);
    splitWK<<<(512*512 /4+255)/256, 256>>>(W2, W2_h, W2_l, 512*512/4);
    // H2 = tanh(H1 @ W2^T + b2) (4096x512x512) -> bf16 split
    mmaGemmBF<128,128,3,1,1><<<dim3(4,32), 256, sm128>>>(NROWS, 512, 512,
        H1_h, H1_l, W2_h, W2_l, b2, nullptr, H2_h, H2_l);
    splitWK<<<(DIN2*512/4+255)/256, 256>>>(W3, W3_h, W3_l, DIN2*512/4);
    // CT = H2 @ W3^T + b3       (4096x2048x512) -> fp32
    mmaGemmBF<128,128,3,0,0><<<dim3(16,32), 256, sm128>>>(NROWS, 2048, 512,
        H2_h, H2_l, W3_h, W3_l, b3, CT, nullptr, nullptr);

    // ----- stream s1: G1 needs Hu (evHu) + Lm -----
    cudaStreamWaitEvent(s1, evHu, 0);
    // G1 = Hu @ Lm (symmetric)  (4096x1024x1024) -> fp32
    mmaGemmBF<128,128,3,0,0><<<dim3(8,32), 256, sm128, s1>>>(NROWS, 1024, 1024,
        Hu_h, Hu_l, Lm_h, Lm_l, nullptr, G1, nullptr, nullptr);
    // Z01 = state @ icW^T + cb01 (4096x128x2048) -> fp32
    mmaGemmBF<64,64,4,0,0><<<dim3(2,64), 256, smZ, s1>>>(NROWS, 128, 2048,
        sx_h, sx_l, icW_h, icW_l, cb01, Z01, nullptr, nullptr);
    z2K<<<NROWS/4, 256, 0, s1>>>();
    cudaEventRecord(evJoin, s1);

    // ----- join + final on stream 0 -----
    cudaStreamWaitEvent(0, evJoin, 0);
    finalK<<<NROWS, 256>>>(state, icW2, icb2, out);
}

// round 17
// speedup vs baseline: 2.3721x; 1.0053x over previous
#include <cuda_runtime.h>
#include <cuda_bf16.h>
#include <math.h>
#include <stdint.h>

#define NROWS 4096
#define DIMH  1024
#define DIN2  2048

typedef __nv_bfloat16 bf16;

// ---------------- helpers ----------------
__device__ __forceinline__ float srelu(float x){
    float r = fmaxf(x, 0.0f);
    if (r < 0.1f){ float r2 = r*r; return (0.2f*r*r2 - r2*r2) * 500.0f; }
    return x - 0.05f;
}
__device__ __forceinline__ float softplusf(float x){
    return fmaxf(x, 0.0f) + log1pf(expf(-fabsf(x)));
}
__device__ __forceinline__ void bfsplit(float x, bf16& h, bf16& l){
    h = __float2bfloat16_rn(x);
    l = __float2bfloat16_rn(x - __bfloat162float(h));
}

// ---------------- scratch (device globals) ----------------
__device__ bf16  g_Pt_h  [DIMH*DIMH],  g_Pt_l  [DIMH*DIMH];
__device__ bf16  g_PtSc_h[DIMH*DIMH],  g_PtSc_l[DIMH*DIMH];
__device__ bf16  g_Lm_h  [DIMH*DIMH],  g_Lm_l  [DIMH*DIMH];
__device__ bf16  g_Hu_h  [NROWS*DIMH], g_Hu_l  [NROWS*DIMH];
__device__ bf16  g_st_h  [NROWS*DIN2], g_st_l  [NROWS*DIN2];
__device__ bf16  g_sx_h  [NROWS*DIN2], g_sx_l  [NROWS*DIN2];
__device__ bf16  g_W1_h  [512*DIN2],   g_W1_l  [512*DIN2];
__device__ bf16  g_W2_h  [512*512],    g_W2_l  [512*512];
__device__ bf16  g_W3_h  [DIN2*512],   g_W3_l  [DIN2*512];
__device__ bf16  g_icW_h [128*DIN2],   g_icW_l [128*DIN2];
__device__ bf16  g_H1_h  [NROWS*512],  g_H1_l  [NROWS*512];
__device__ bf16  g_H2_h  [NROWS*512],  g_H2_l  [NROWS*512];
__device__ float g_G1    [NROWS*DIMH];
__device__ float g_CT    [NROWS*DIN2];
__device__ float g_Z01   [NROWS*128];
__device__ float g_Z2    [NROWS*64];
__device__ float g_spU0  [64*64];
__device__ float g_spU1  [64];
__device__ float g_cb01  [128];
__device__ float g_z0    [1];

// ---------------- P transpose + eig scale + bf16 split ----------------
__global__ void transposePK(const float* __restrict__ P, const float* __restrict__ t){
    __shared__ float tile[32][33];
    int c0 = blockIdx.x*32, r0 = blockIdx.y*32;
    int x = threadIdx.x, y = threadIdx.y;
    float s = 2.0f * sinf(t[0]);
    #pragma unroll
    for (int i=0;i<32;i+=8)
        tile[y+i][x] = P[(size_t)(r0+y+i)*DIMH + c0 + x];
    __syncthreads();
    #pragma unroll
    for (int i=0;i<32;i+=8){
        int c = c0 + y + i;
        int r = r0 + x;
        float v = tile[x][y+i];
        float e = (r == 0) ? 0.0f : ((r <= 511) ? (1.0f + s) : (1.0f - s));
        float ev = e * v;
        size_t o = (size_t)c*DIMH + r;
        bf16 h, l;
        bfsplit(v,  h, l); g_Pt_h[o]   = h; g_Pt_l[o]   = l;
        bfsplit(ev, h, l); g_PtSc_h[o] = h; g_PtSc_l[o] = l;
    }
}

// ---------------- concat icW0/icW1 + split ----------------
__global__ void catIcWK(const float* __restrict__ w0, const float* __restrict__ w1){
    int i = blockIdx.x*256 + threadIdx.x;
    bf16 h, l;
    bfsplit(w0[i], h, l); g_icW_h[i] = h; g_icW_l[i] = l;
    bfsplit(w1[i], h, l); g_icW_h[64*DIN2+i] = h; g_icW_l[64*DIN2+i] = l;
}

// ---------------- generic weight split ----------------
__global__ void splitWK(const float* __restrict__ in, bf16* __restrict__ hi,
                        bf16* __restrict__ lo, int n4){
    int i = blockIdx.x*256 + threadIdx.x;
    if (i >= n4) return;
    float4 x = reinterpret_cast<const float4*>(in)[i];
    bf16 h0,l0,h1,l1,h2,l2,h3,l3;
    bfsplit(x.x,h0,l0); bfsplit(x.y,h1,l1); bfsplit(x.z,h2,l2); bfsplit(x.w,h3,l3);
    reinterpret_cast<__nv_bfloat162*>(hi)[i*2+0] = __halves2bfloat162(h0,h1);
    reinterpret_cast<__nv_bfloat162*>(hi)[i*2+1] = __halves2bfloat162(h2,h3);
    reinterpret_cast<__nv_bfloat162*>(lo)[i*2+0] = __halves2bfloat162(l0,l1);
    reinterpret_cast<__nv_bfloat162*>(lo)[i*2+1] = __halves2bfloat162(l2,l3);
}

// ---------------- Hu / st / state splits ----------------
__global__ void huStK(const float* __restrict__ state){
    int idx = blockIdx.x*blockDim.x + threadIdx.x;   // NROWS*512 float4s
    int n = idx >> 9, q = idx & 511;
    const float4* s4 = reinterpret_cast<const float4*>(state);
    float4 x = s4[idx];
    float x0 = state[(n<<11) + (q < 256 ? 0 : DIMH)];
    bf16 h0,l0,h1,l1,h2,l2,h3,l3;

    bfsplit(x.x,h0,l0); bfsplit(x.y,h1,l1); bfsplit(x.z,h2,l2); bfsplit(x.w,h3,l3);
    reinterpret_cast<__nv_bfloat162*>(g_sx_h)[idx*2+0] = __halves2bfloat162(h0,h1);
    reinterpret_cast<__nv_bfloat162*>(g_sx_h)[idx*2+1] = __halves2bfloat162(h2,h3);
    reinterpret_cast<__nv_bfloat162*>(g_sx_l)[idx*2+0] = __halves2bfloat162(l0,l1);
    reinterpret_cast<__nv_bfloat162*>(g_sx_l)[idx*2+1] = __halves2bfloat162(l2,l3);

    bfsplit(x.x-x0,h0,l0); bfsplit(x.y-x0,h1,l1); bfsplit(x.z-x0,h2,l2); bfsplit(x.w-x0,h3,l3);
    reinterpret_cast<__nv_bfloat162*>(g_st_h)[idx*2+0] = __halves2bfloat162(h0,h1);
    reinterpret_cast<__nv_bfloat162*>(g_st_h)[idx*2+1] = __halves2bfloat162(h2,h3);
    reinterpret_cast<__nv_bfloat162*>(g_st_l)[idx*2+0] = __halves2bfloat162(l0,l1);
    reinterpret_cast<__nv_bfloat162*>(g_st_l)[idx*2+1] = __halves2bfloat162(l2,l3);

    if (q < 256){
        float ux = 1.0f/(1.0f + expf(-10.0f*x.x));
        float uy = 1.0f/(1.0f + expf(-10.0f*x.y));
        float uz = 1.0f/(1.0f + expf(-10.0f*x.z));
        float uw = 1.0f/(1.0f + expf(-10.0f*x.w));
        bfsplit(ux,h0,l0); bfsplit(uy,h1,l1); bfsplit(uz,h2,l2); bfsplit(uw,h3,l3);
        int o = n*256 + q;
        reinterpret_cast<__nv_bfloat162*>(g_Hu_h)[o*2+0] = __halves2bfloat162(h0,h1);
        reinterpret_cast<__nv_bfloat162*>(g_Hu_h)[o*2+1] = __halves2bfloat162(h2,h3);
        reinterpret_cast<__nv_bfloat162*>(g_Hu_l)[o*2+0] = __halves2bfloat162(l0,l1);
        reinterpret_cast<__nv_bfloat162*>(g_Hu_l)[o*2+1] = __halves2bfloat162(l2,l3);
    }
}

// ---------------- softplus(U), biases, z0 constant ----------------
__global__ void prepIcnnK(const float* __restrict__ icU0, const float* __restrict__ icU1,
                          const float* __restrict__ icb0, const float* __restrict__ icb1,
                          const float* __restrict__ icb2){
    int tid = threadIdx.x;
    for (int i = tid; i < 64*64; i += blockDim.x) g_spU0[i] = softplusf(icU0[i]);
    if (tid < 64){
        g_spU1[tid]     = softplusf(icU1[tid]);
        g_cb01[tid]     = icb0[tid];
        g_cb01[64+tid]  = icb1[tid];
    }
    __syncthreads();
    __shared__ float z0a[64], z0b[64];
    if (tid < 64) z0a[tid] = srelu(icb0[tid]);
    __syncthreads();
    if (tid < 64){
        float s = icb1[tid];
        #pragma unroll 8
        for (int j=0;j<64;j++) s += g_spU0[tid*64+j]*z0a[j];
        z0b[tid] = srelu(s);
    }
    __syncthreads();
    if (tid == 0){
        float s = icb2[0];
        for (int j=0;j<64;j++) s += g_spU1[j]*z0b[j];
        g_z0[0] = srelu(s);
    }
}

// ---------------- z2 ----------------
__global__ void z2K(){
    __shared__ float sUT[64*64];
    __shared__ float z1s[4][64];
    int t = threadIdx.x;
    for (int i = t; i < 4096; i += 256){
        int j = i >> 6, k = i & 63;
        sUT[i] = g_spU0[k*64 + j];
    }
    int r = t >> 6, k = t & 63;
    int n = blockIdx.x*4 + r;
    z1s[r][k] = srelu(g_Z01[n*128 + k]);
    __syncthreads();
    float s = g_Z01[n*128 + 64 + k];
    #pragma unroll 8
    for (int j=0;j<64;j++) s += sUT[j*64 + k]*z1s[r][j];
    g_Z2[n*64 + k] = srelu(s);
}

// ---------------- final assembly ----------------
__global__ void finalK(const float* __restrict__ state, const float* __restrict__ icW2,
                       const float* __restrict__ icb2, float* __restrict__ out){
    int n = blockIdx.x;
    int tid = threadIdx.x;
    const float* srow = state + (size_t)n*DIN2;
    const float4* srow4 = reinterpret_cast<const float4*>(srow);
    const float4* icW24 = reinterpret_cast<const float4*>(icW2);
    const float4* CT4   = reinterpret_cast<const float4*>(g_CT + (size_t)n*DIN2);

    float x0u = srow[0], x0v = srow[DIMH];

    float dot = 0.0f, ss = 0.0f;
    #pragma unroll
    for (int it=0; it<2; it++){
        int q = tid + it*256;
        float4 x = srow4[q], w = icW24[q];
        dot += w.x*x.x + w.y*x.y + w.z*x.z + w.w*x.w;
        ss  += x.x*x.x + x.y*x.y + x.z*x.z + x.w*x.w;
    }
    #pragma unroll
    for (int o=16;o>0;o>>=1){
        dot += __shfl_down_sync(0xffffffffu, dot, o);
        ss  += __shfl_down_sync(0xffffffffu, ss,  o);
    }
    __shared__ float sd[8], sq[8];
    if ((tid & 31) == 0){ sd[tid>>5] = dot; sq[tid>>5] = ss; }
    __syncthreads();
    if (tid == 0){
        float D = 0.0f, S = 0.0f;
        #pragma unroll
        for (int w=0;w<8;w++){ D += sd[w]; S += sq[w]; }
        float z = icb2[0] + D;
        for (int k=0;k<64;k++) z = fmaf(g_spU1[k], g_Z2[n*64+k], z);
        float z3 = srelu(z);
        out[(size_t)n*2049 + 2048] = srelu(z3 - g_z0[0]) + 0.001f*S;
    }

    #pragma unroll
    for (int it=0; it<2; it++){
        int q = tid + it*256;
        int d = q*4;
        float4 x  = srow4[q];
        float4 ct = CT4[q];
        float x0 = (d < DIMH) ? x0u : x0v;
        float r[4];
        float xv[4] = {x.x, x.y, x.z, x.w};
        float cv[4] = {ct.x, ct.y, ct.z, ct.w};
        if (d < DIMH){
            const float4 v4 = srow4[q + 256];
            const float4 gg = reinterpret_cast<const float4*>(g_G1 + (size_t)n*DIMH)[q];
            float vv[4] = {v4.x, v4.y, v4.z, v4.w};
            float gv[4] = {gg.x, gg.y, gg.z, gg.w};
            #pragma unroll
            for (int e=0;e<4;e++){
                float ux = cv[e]*(xv[e]-x0);
                float ctrl = (ux < 10.0f && ux > -10.0f) ? ux : 0.0f;
                float uu = xv[e];
                r[e] = uu - uu*uu*uu*(1.0f/3.0f) - vv[e] + 1.0f + gv[e] + ctrl;
            }
        } else {
            const float4 u4 = srow4[q - 256];
            float uv[4] = {u4.x, u4.y, u4.z, u4.w};
            #pragma unroll
            for (int e=0;e<4;e++){
                float ux = cv[e]*(xv[e]-x0);
                float ctrl = (ux < 10.0f && ux > -10.0f) ? ux : 0.0f;
                r[e] = 0.2f*(uv[e] + 0.7f - 0.8f*xv[e]) + ctrl;
            }
        }
        float* o = out + (size_t)n*2049 + d;
        o[0]=r[0]; o[1]=r[1]; o[2]=r[2]; o[3]=r[3];
    }
}

// ======== 3xBF16 mma.sync GEMM (split-2 bf16, XOR-swizzled smem, fp32 accum) ========
#define CPASYNC(dst, src) asm volatile("cp.async.cg.shared.global [%0], [%1], 16;\n" :: "r"(dst), "l"(src))
#define CPCOMMIT()        asm volatile("cp.async.commit_group;\n" ::: "memory")
#define CPWAIT(n)         asm volatile("cp.async.wait_group %0;\n" :: "n"(n) : "memory")

__device__ __forceinline__ void ldsm4(uint32_t addr, uint32_t& r0, uint32_t& r1,
                                      uint32_t& r2, uint32_t& r3){
    asm volatile("ldmatrix.sync.aligned.m8n8.x4.shared.b16 {%0,%1,%2,%3}, [%4];"
                 : "=r"(r0), "=r"(r1), "=r"(r2), "=r"(r3) : "r"(addr));
}
__device__ __forceinline__ void mma_bf16(float* d, const uint32_t* a, uint32_t b0, uint32_t b1){
    asm volatile("mma.sync.aligned.m16n8k16.row.col.f32.bf16.bf16.f32 "
                 "{%0,%1,%2,%3}, {%4,%5,%6,%7}, {%8,%9}, {%0,%1,%2,%3};"
                 : "+f"(d[0]), "+f"(d[1]), "+f"(d[2]), "+f"(d[3])
                 : "r"(a[0]), "r"(a[1]), "r"(a[2]), "r"(a[3]), "r"(b0), "r"(b1));
}

// row = tile row, chunk = 16B chunk index (0..3) within 64B row.
// swizzled byte offset within tile: row*64 + (chunk ^ ((row>>1)&3))*16
__device__ __forceinline__ uint32_t swz(int row, int chunk){
    return (uint32_t)(row*64 + ((chunk ^ ((row>>1)&3))*16));
}

// C[M,N] = (Ah+Al)@(Bh+Bl)^T via hh+lh+hl. BK=32. TANH: tanh epi.
// SOUT=1: write bf16 split (Ch,Cl). SOUT=0: write fp32 Cf.
template<int BM, int BN, int STAGES, int TANH, int SOUT>
__global__ __launch_bounds__(256, 2)
void mmaGemmBF(int M, int N, int K,
               const bf16* __restrict__ Ah, const bf16* __restrict__ Al,
               const bf16* __restrict__ Bh, const bf16* __restrict__ Bl,
               const float* __restrict__ bias,
               float* __restrict__ Cf, bf16* __restrict__ Ch, bf16* __restrict__ Cl){
    constexpr int ROWB = 64;                 // 32 bf16, XOR-swizzled (no padding)
    constexpr int offAl = BM*ROWB;
    constexpr int offBh = 2*BM*ROWB;
    constexpr int offBl = offBh + BN*ROWB;
    constexpr int STG   = 2*(BM+BN)*ROWB;
    constexpr int WARPS_M = BM/32;
    constexpr int WARPS_N = 8/WARPS_M;
    constexpr int WN = BN/WARPS_N;
    constexpr int NP = WN/16;

    extern __shared__ __align__(16) char smem[];

    const int tid  = threadIdx.x;
    const int warp = tid >> 5, lane = tid & 31;
    const int wm = (warp % WARPS_M)*32;
    const int wn = (warp / WARPS_M)*WN;
    const int bm = blockIdx.y*BM, bn = blockIdx.x*BN;

    const int lr  = lane & 15;               // ldmatrix row within 16
    const int lch = lane >> 4;               // 16B chunk half (0/1) within k16 step

    float acc[2][2*NP][4];
    #pragma unroll
    for (int i=0;i<2;i++)
        #pragma unroll
        for (int j=0;j<2*NP;j++)
            #pragma unroll
            for (int q=0;q<4;q++) acc[i][j][q] = 0.0f;

    uint32_t sBase = (uint32_t)__cvta_generic_to_shared(smem);

    auto loadTile = [&](int buf, int k0){
        uint32_t st = sBase + buf*STG;
        #pragma unroll
        for (int i=0;i<(BM*4)/256;i++){
            int L = tid + i*256;
            int r = L>>2, c = L&3;
            uint32_t o = swz(r, c);
            CPASYNC(st + o,         Ah + (size_t)(bm+r)*K + k0 + c*8);
            CPASYNC(st + offAl + o, Al + (size_t)(bm+r)*K + k0 + c*8);
        }
        #pragma unroll
        for (int i=0;i<(BN*4)/256;i++){
            int L = tid + i*256;
            int r = L>>2, c = L&3;
            uint32_t o = swz(r, c);
            CPASYNC(st + offBh + o, Bh + (size_t)(bn+r)*K + k0 + c*8);
            CPASYNC(st + offBl + o, Bl + (size_t)(bn+r)*K + k0 + c*8);
        }
        CPCOMMIT();
    };

    const int nk = K / 32;
    #pragma unroll
    for (int p=0; p<STAGES-1; p++){
        if (p < nk) loadTile(p, p*32); else CPCOMMIT();
    }

    for (int ck = 0; ck < nk; ck++){
        CPWAIT(STAGES-2);
        __syncthreads();

        int nxt = ck + STAGES - 1;
        if (nxt < nk) loadTile(nxt % STAGES, nxt*32); else CPCOMMIT();

        uint32_t st = sBase + (ck % STAGES)*STG;
        #pragma unroll
        for (int ks=0; ks<2; ks++){                      // two k16 steps
            const int chunk = ks*2 + lch;                // 16B chunk index for this lane
            // A fragments for both m-tiles (hi+lo): 16 regs live
            uint32_t ah[2][4], al[2][4];
            #pragma unroll
            for (int mt=0; mt<2; mt++){
                uint32_t aoff = swz(wm + mt*16 + lr, chunk);
                ldsm4(st + aoff,         ah[mt][0], ah[mt][1], ah[mt][2], ah[mt][3]);
                ldsm4(st + offAl + aoff, al[mt][0], al[mt][1], al[mt][2], al[mt][3]);
            }
            // p-outer: B fragments transient (8 regs)
            #pragma unroll
            for (int p=0; p<NP; p++){
                uint32_t boff = swz(wn + p*16 + lr, chunk);
                uint32_t bh[4], bl[4];
                ldsm4(st + offBh + boff, bh[0], bh[1], bh[2], bh[3]);
                ldsm4(st + offBl + boff, bl[0], bl[1], bl[2], bl[3]);
                #pragma unroll
                for (int mt=0; mt<2; mt++){
                    // n-subtile 0: B regs {r0, r2}; subtile 1: {r1, r3}
                    mma_bf16(acc[mt][2*p+0], ah[mt], bh[0], bh[2]);
                    mma_bf16(acc[mt][2*p+1], ah[mt], bh[1], bh[3]);
                    mma_bf16(acc[mt][2*p+0], al[mt], bh[0], bh[2]);
                    mma_bf16(acc[mt][2*p+1], al[mt], bh[1], bh[3]);
                    mma_bf16(acc[mt][2*p+0], ah[mt], bl[0], bl[2]);
                    mma_bf16(acc[mt][2*p+1], ah[mt], bl[1], bl[3]);
                }
            }
        }
        __syncthreads();
    }

    const int tg = lane & 3, g = lane >> 2;
    #pragma unroll
    for (int mt=0; mt<2; mt++){
        #pragma unroll
        for (int nt=0; nt<2*NP; nt++){
            int p = nt >> 1, nsub = nt & 1;
            int row = bm + wm + mt*16 + g;
            int col = bn + wn + p*16 + nsub*8 + tg*2;
            float v0 = acc[mt][nt][0], v1 = acc[mt][nt][1];
            float v2 = acc[mt][nt][2], v3 = acc[mt][nt][3];
            if (bias){
                float b0v = bias[col], b1v = bias[col+1];
                v0 += b0v; v1 += b1v; v2 += b0v; v3 += b1v;
            }
            if (TANH){ v0 = tanhf(v0); v1 = tanhf(v1); v2 = tanhf(v2); v3 = tanhf(v3); }
            if (SOUT){
                bf16 h0,l0,h1,l1,h2,l2,h3,l3;
                bfsplit(v0,h0,l0); bfsplit(v1,h1,l1);
                bfsplit(v2,h2,l2); bfsplit(v3,h3,l3);
                *reinterpret_cast<__nv_bfloat162*>(Ch + (size_t)row*N + col)     = __halves2bfloat162(h0,h1);
                *reinterpret_cast<__nv_bfloat162*>(Ch + (size_t)(row+8)*N + col) = __halves2bfloat162(h2,h3);
                *reinterpret_cast<__nv_bfloat162*>(Cl + (size_t)row*N + col)     = __halves2bfloat162(l0,l1);
                *reinterpret_cast<__nv_bfloat162*>(Cl + (size_t)(row+8)*N + col) = __halves2bfloat162(l2,l3);
            } else {
                *reinterpret_cast<float2*>(Cf + (size_t)row*N + col)     = make_float2(v0, v1);
                *reinterpret_cast<float2*>(Cf + (size_t)(row+8)*N + col) = make_float2(v2, v3);
            }
        }
    }
}

// ---------------- host ----------------
extern "C" void kernel_launch(void* const* d_in, const int* in_sizes, int n_in,
                              void* d_out, int out_size){
    const float* state = (const float*)d_in[0];
    const float* t     = (const float*)d_in[1];
    const float* P     = (const float*)d_in[2];
    const float* W1    = (const float*)d_in[3];
    const float* b1    = (const float*)d_in[4];
    const float* W2    = (const float*)d_in[5];
    const float* b2    = (const float*)d_in[6];
    const float* W3    = (const float*)d_in[7];
    const float* b3    = (const float*)d_in[8];
    const float* icW0  = (const float*)d_in[9];
    const float* icb0  = (const float*)d_in[10];
    const float* icW1  = (const float*)d_in[11];
    const float* icb1  = (const float*)d_in[12];
    const float* icW2  = (const float*)d_in[13];
    const float* icb2  = (const float*)d_in[14];
    const float* icU0  = (const float*)d_in[15];
    const float* icU1  = (const float*)d_in[16];
    float* out = (float*)d_out;

    bf16 *Pt_h,*Pt_l,*PtSc_h,*PtSc_l,*Lm_h,*Lm_l,*Hu_h,*Hu_l,*st_h,*st_l,*sx_h,*sx_l;
    bf16 *W1_h,*W1_l,*W2_h,*W2_l,*W3_h,*W3_l,*icW_h,*icW_l,*H1_h,*H1_l,*H2_h,*H2_l;
    float *G1,*CT,*Z01,*cb01;
    cudaGetSymbolAddress((void**)&Pt_h,   g_Pt_h);   cudaGetSymbolAddress((void**)&Pt_l,   g_Pt_l);
    cudaGetSymbolAddress((void**)&PtSc_h, g_PtSc_h); cudaGetSymbolAddress((void**)&PtSc_l, g_PtSc_l);
    cudaGetSymbolAddress((void**)&Lm_h,   g_Lm_h);   cudaGetSymbolAddress((void**)&Lm_l,   g_Lm_l);
    cudaGetSymbolAddress((void**)&Hu_h,   g_Hu_h);   cudaGetSymbolAddress((void**)&Hu_l,   g_Hu_l);
    cudaGetSymbolAddress((void**)&st_h,   g_st_h);   cudaGetSymbolAddress((void**)&st_l,   g_st_l);
    cudaGetSymbolAddress((void**)&sx_h,   g_sx_h);   cudaGetSymbolAddress((void**)&sx_l,   g_sx_l);
    cudaGetSymbolAddress((void**)&W1_h,   g_W1_h);   cudaGetSymbolAddress((void**)&W1_l,   g_W1_l);
    cudaGetSymbolAddress((void**)&W2_h,   g_W2_h);   cudaGetSymbolAddress((void**)&W2_l,   g_W2_l);
    cudaGetSymbolAddress((void**)&W3_h,   g_W3_h);   cudaGetSymbolAddress((void**)&W3_l,   g_W3_l);
    cudaGetSymbolAddress((void**)&icW_h,  g_icW_h);  cudaGetSymbolAddress((void**)&icW_l,  g_icW_l);
    cudaGetSymbolAddress((void**)&H1_h,   g_H1_h);   cudaGetSymbolAddress((void**)&H1_l,   g_H1_l);
    cudaGetSymbolAddress((void**)&H2_h,   g_H2_h);   cudaGetSymbolAddress((void**)&H2_l,   g_H2_l);
    cudaGetSymbolAddress((void**)&G1,  g_G1);
    cudaGetSymbolAddress((void**)&CT,  g_CT);
    cudaGetSymbolAddress((void**)&Z01, g_Z01);
    cudaGetSymbolAddress((void**)&cb01,g_cb01);

    const int sm128 = 3*2*(128+128)*64;   // 98304  -> 2 CTAs/SM
    const int sm64n = 3*2*(128+ 64)*64;   // 73728  -> 2 CTAs/SM
    const int smLm  = 3*2*( 64+128)*64;   // 73728  -> 2 CTAs/SM
    const int smZ   = 4*2*( 64+ 64)*64;   // 65536  -> 2 CTAs/SM

    // One-time setup on FIRST call (correctness run, outside graph capture).
    static cudaStream_t s1 = nullptr;
    static cudaEvent_t evFork = nullptr, evHu = nullptr, evJoin = nullptr;
    if (s1 == nullptr){
        cudaFuncSetAttribute((const void*)mmaGemmBF<64,128,3,0,1>,  cudaFuncAttributeMaxDynamicSharedMemorySize, smLm);
        cudaFuncSetAttribute((const void*)mmaGemmBF<128,128,3,0,0>, cudaFuncAttributeMaxDynamicSharedMemorySize, sm128);
        cudaFuncSetAttribute((const void*)mmaGemmBF<128,64,3,1,1>,  cudaFuncAttributeMaxDynamicSharedMemorySize, sm64n);
        cudaFuncSetAttribute((const void*)mmaGemmBF<64,64,4,0,0>,   cudaFuncAttributeMaxDynamicSharedMemorySize, smZ);
        cudaStreamCreateWithFlags(&s1, cudaStreamNonBlocking);
        cudaEventCreateWithFlags(&evFork, cudaEventDisableTiming);
        cudaEventCreateWithFlags(&evHu,   cudaEventDisableTiming);
        cudaEventCreateWithFlags(&evJoin, cudaEventDisableTiming);
    }

    // ---- dual-stream schedule (fork/join via events; capture-safe) ----
    cudaEventRecord(evFork, 0);
    cudaStreamWaitEvent(s1, evFork, 0);

    // ----- stream s1 chain -----
    transposePK<<<dim3(32,32), dim3(32,8), 0, s1>>>(P, t);
    catIcWK<<<(64*DIN2)/256, 256, 0, s1>>>(icW0, icW1);
    prepIcnnK<<<1, 256, 0, s1>>>(icU0, icU1, icb0, icb1, icb2);
    // Lm = PtSc @ Pt^T  (1024x1024x1024) -> bf16 split output
    mmaGemmBF<64,128,3,0,1><<<dim3(8,16), 256, smLm, s1>>>(1024, 1024, 1024,
        PtSc_h, PtSc_l, Pt_h, Pt_l, nullptr, nullptr, Lm_h, Lm_l);

    // ----- stream 0 chain -----
    splitWK<<<(512*DIN2/4+255)/256, 256>>>(W1, W1_h, W1_l, 512*DIN2/4);
    huStK<<<(NROWS*512)/256, 256>>>(state);
    cudaEventRecord(evHu, 0);
    // H1 = tanh(st @ W1^T + b1) (4096x512x2048) -> bf16 split, 256 CTAs
    mmaGemmBF<128,64,3,1,1><<<dim3(8,32), 256, sm64n>>>(NROWS, 512, 2048,
        st_h, st_l, W1_h, W1_l, b1, nullptr, H1_h, H1_l);
    splitWK<<<(512*512 /4+255)/256, 256>>>(W2, W2_h, W2_l, 512*512/4);
    // H2 = tanh(H1 @ W2^T + b2) (4096x512x512) -> bf16 split, 256 CTAs
    mmaGemmBF<128,64,3,1,1><<<dim3(8,32), 256, sm64n>>>(NROWS, 512, 512,
        H1_h, H1_l, W2_h, W2_l, b2, nullptr, H2_h, H2_l);
    splitWK<<<(DIN2*512/4+255)/256, 256>>>(W3, W3_h, W3_l, DIN2*512/4);
    // CT = H2 @ W3^T + b3       (4096x2048x512) -> fp32
    mmaGemmBF<128,128,3,0,0><<<dim3(16,32), 256, sm128>>>(NROWS, 2048, 512,
        H2_h, H2_l, W3_h, W3_l, b3, CT, nullptr, nullptr);

    // ----- stream s1: G1 needs Hu (evHu) + Lm -----
    cudaStreamWaitEvent(s1, evHu, 0);
    // G1 = Hu @ Lm (symmetric)  (4096x1024x1024) -> fp32
    mmaGemmBF<128,128,3,0,0><<<dim3(8,32), 256, sm128, s1>>>(NROWS, 1024, 1024,
        Hu_h, Hu_l, Lm_h, Lm_l, nullptr, G1, nullptr, nullptr);
    // Z01 = state @ icW^T + cb01 (4096x128x2048) -> fp32
    mmaGemmBF<64,64,4,0,0><<<dim3(2,64), 256, smZ, s1>>>(NROWS, 128, 2048,
        sx_h, sx_l, icW_h, icW_l, cb01, Z01, nullptr, nullptr);
    z2K<<<NROWS/4, 256, 0, s1>>>();
    cudaEventRecord(evJoin, s1);

    // ----- join + final on stream 0 -----
    cudaStreamWaitEvent(0, evJoin, 0);
    finalK<<<NROWS, 256>>>(state, icW2, icb2, out);
}